// round 1
// baseline (speedup 1.0000x reference)
#include <cuda_runtime.h>
#include <math.h>

#define BATCH 4096
#define SDIM  512
#define ADIM  64
#define HDIM  2048
#define KDIM  577          // 512 + 64 + 1
#define KPAD  584          // 73 * 8, 16B-aligned rows (584*4 % 16 == 0)
#define FOURH 8192

// ---- scratch (static device globals; no allocation at runtime) ----
__device__ float g_xp[BATCH * KPAD];       // packed, zero-padded input  (~9.6 MB)
__device__ float g_vb[FOURH];              // bh + h @ Wh
__device__ float g_vbp[8 * FOURH];         // k-split partials for vb
__device__ float g_hn[BATCH * HDIM];       // h_new (~33.5 MB)

// ---------------------------------------------------------------------------
// 1) pack x = concat(s, a_prev, r_prev), zero-pad K to KPAD
// ---------------------------------------------------------------------------
__global__ void pack_kernel(const float* __restrict__ s,
                            const float* __restrict__ a,
                            const float* __restrict__ r) {
    int idx = blockIdx.x * blockDim.x + threadIdx.x;
    if (idx >= BATCH * KPAD) return;
    int b = idx / KPAD;
    int k = idx - b * KPAD;
    float v = 0.0f;
    if (k < SDIM)                v = s[b * SDIM + k];
    else if (k < SDIM + ADIM)    v = a[b * ADIM + (k - SDIM)];
    else if (k == SDIM + ADIM)   v = r[b];
    g_xp[idx] = v;
}

// ---------------------------------------------------------------------------
// 2) vb partials: vbp[kc][j] = sum_{k in chunk kc} h[k] * Wh[k][j]
//    grid (8192/256, 8), block 256. Coalesced over j.
// ---------------------------------------------------------------------------
__global__ void vb_partial(const float* __restrict__ h,
                           const float* __restrict__ Wh) {
    int j  = blockIdx.x * 256 + threadIdx.x;
    int k0 = blockIdx.y * 256;
    float acc = 0.0f;
#pragma unroll 8
    for (int k = 0; k < 256; k++) {
        acc += h[k0 + k] * Wh[(size_t)(k0 + k) * FOURH + j];
    }
    g_vbp[blockIdx.y * FOURH + j] = acc;
}

// 3) vb reduce: vb[j] = bh[j] + sum_kc vbp[kc][j]
__global__ void vb_reduce(const float* __restrict__ bh) {
    int j = blockIdx.x * 256 + threadIdx.x;
    float acc = bh[j];
#pragma unroll
    for (int kc = 0; kc < 8; kc++) acc += g_vbp[kc * FOURH + j];
    g_vb[j] = acc;
}

// ---------------------------------------------------------------------------
// 4) fused GEMM + LSTM gates:
//    For block tile (64 batch rows) x (64 hidden cols), compute all 4 gate
//    columns (j, j+2048, j+4096, j+6144) of z = x @ Wx + vb, then gate math,
//    write h_new. Per-thread: 4 rows x 4 cols x 4 gates = 64 accumulators.
// ---------------------------------------------------------------------------
#define BM 64
#define BN 64
#define BK 8

__global__ __launch_bounds__(256) void lstm_gemm(const float* __restrict__ Wx,
                                                 const float* __restrict__ cvec) {
    __shared__ float xs[BK][BM];          // k-major
    __shared__ float ws[BK][4 * BN];      // [k][gate*64 + jj]

    int tid = threadIdx.x;
    int tx = tid & 15;        // 0..15 -> cols
    int ty = tid >> 4;        // 0..15 -> rows
    int row0 = blockIdx.y * BM;
    int j0   = blockIdx.x * BN;

    float acc[4][4][4];       // [gate][r][c]
#pragma unroll
    for (int g = 0; g < 4; g++)
#pragma unroll
        for (int r2 = 0; r2 < 4; r2++)
#pragma unroll
            for (int c2 = 0; c2 < 4; c2++) acc[g][r2][c2] = 0.0f;

    for (int k0 = 0; k0 < KPAD; k0 += BK) {
        // load x tile: 64 rows x 8 k = 128 float4, threads 0..127
        if (tid < 128) {
            int rr  = tid >> 1;
            int kk4 = (tid & 1) * 4;
            float4 v = *(const float4*)&g_xp[(size_t)(row0 + rr) * KPAD + k0 + kk4];
            xs[kk4 + 0][rr] = v.x;
            xs[kk4 + 1][rr] = v.y;
            xs[kk4 + 2][rr] = v.z;
            xs[kk4 + 3][rr] = v.w;
        }
        // load W tile: 8 k x 256 cols = 512 float4, 2 per thread
#pragma unroll
        for (int i = 0; i < 2; i++) {
            int slot = tid + i * 256;        // 0..511
            int kk   = slot >> 6;
            int rem  = slot & 63;
            int g    = rem >> 4;
            int jj4  = (rem & 15) * 4;
            int k    = k0 + kk;
            float4 v = make_float4(0.f, 0.f, 0.f, 0.f);
            if (k < KDIM)
                v = *(const float4*)&Wx[(size_t)k * FOURH + g * HDIM + j0 + jj4];
            *(float4*)&ws[kk][g * BN + jj4] = v;
        }
        __syncthreads();

#pragma unroll
        for (int kk = 0; kk < BK; kk++) {
            float4 a4 = *(float4*)&xs[kk][ty * 4];
            float av[4] = {a4.x, a4.y, a4.z, a4.w};
#pragma unroll
            for (int g = 0; g < 4; g++) {
                float4 w4 = *(float4*)&ws[kk][g * BN + tx * 4];
                float wv[4] = {w4.x, w4.y, w4.z, w4.w};
#pragma unroll
                for (int r2 = 0; r2 < 4; r2++)
#pragma unroll
                    for (int c2 = 0; c2 < 4; c2++)
                        acc[g][r2][c2] += av[r2] * wv[c2];
            }
        }
        __syncthreads();
    }

    // epilogue: gate math -> h_new
#pragma unroll
    for (int c2 = 0; c2 < 4; c2++) {
        int j = j0 + tx * 4 + c2;
        float vbi = g_vb[0 * HDIM + j];
        float vbf = g_vb[1 * HDIM + j];
        float vbg = g_vb[2 * HDIM + j];
        float vbo = g_vb[3 * HDIM + j];
        float cj  = cvec[j];
#pragma unroll
        for (int r2 = 0; r2 < 4; r2++) {
            int row = row0 + ty * 4 + r2;
            float zi = acc[0][r2][c2] + vbi;
            float zf = acc[1][r2][c2] + vbf;
            float zg = acc[2][r2][c2] + vbg;
            float zo = acc[3][r2][c2] + vbo;
            float ig = 1.0f / (1.0f + expf(-zi));
            float fg = 1.0f / (1.0f + expf(-zf));
            float og = 1.0f / (1.0f + expf(-zo));
            float cn = fg * cj + ig * tanhf(zg);
            g_hn[(size_t)row * HDIM + j] = og * tanhf(cn);
        }
    }
}

// ---------------------------------------------------------------------------
// 5) heads: logits = h_new @ Wa + ba -> softmax; v = h_new @ Wv + bv
//    Block handles 32 batch rows. 256 threads: thread (r = tid/8, ag = tid%8)
//    owns actions [ag*8, ag*8+8) of row r. Value dot computed redundantly
//    per row-group; lane ag==0 writes it.
// ---------------------------------------------------------------------------
__global__ __launch_bounds__(256) void heads_kernel(const float* __restrict__ Wa,
                                                    const float* __restrict__ ba,
                                                    const float* __restrict__ Wv,
                                                    const float* __restrict__ bv,
                                                    float* __restrict__ out) {
    __shared__ float hs[32][64];
    __shared__ float was[64][64];
    __shared__ float wvs[64];

    int tid  = threadIdx.x;
    int r    = tid >> 3;   // 0..31
    int ag   = tid & 7;    // 0..7
    int row0 = blockIdx.x * 32;

    float acc[8];
#pragma unroll
    for (int a = 0; a < 8; a++) acc[a] = 0.0f;
    float vacc = 0.0f;

    for (int k0 = 0; k0 < HDIM; k0 += 64) {
        // h tile: 32x64 = 512 float4, 2 per thread
#pragma unroll
        for (int i = 0; i < 2; i++) {
            int slot = tid + i * 256;
            int rr   = slot >> 4;
            int kk4  = (slot & 15) * 4;
            *(float4*)&hs[rr][kk4] =
                *(const float4*)&g_hn[(size_t)(row0 + rr) * HDIM + k0 + kk4];
        }
        // Wa tile: 64x64 = 1024 float4, 4 per thread
#pragma unroll
        for (int i = 0; i < 4; i++) {
            int slot = tid + i * 256;
            int kk   = slot >> 4;
            int a4   = (slot & 15) * 4;
            *(float4*)&was[kk][a4] = *(const float4*)&Wa[(size_t)(k0 + kk) * 64 + a4];
        }
        if (tid < 64) wvs[tid] = Wv[k0 + tid];
        __syncthreads();

#pragma unroll 8
        for (int kk = 0; kk < 64; kk++) {
            float h = hs[r][kk];
            vacc += h * wvs[kk];
#pragma unroll
            for (int a = 0; a < 8; a++)
                acc[a] += h * was[kk][ag * 8 + a];
        }
        __syncthreads();
    }

    // softmax across the 8 threads holding this row (8 logits each)
    float l[8];
    float m = -INFINITY;
#pragma unroll
    for (int a = 0; a < 8; a++) {
        l[a] = acc[a] + ba[ag * 8 + a];
        m = fmaxf(m, l[a]);
    }
#pragma unroll
    for (int off = 4; off > 0; off >>= 1)
        m = fmaxf(m, __shfl_xor_sync(0xFFFFFFFFu, m, off, 8));

    float sum = 0.0f;
#pragma unroll
    for (int a = 0; a < 8; a++) {
        l[a] = expf(l[a] - m);
        sum += l[a];
    }
#pragma unroll
    for (int off = 4; off > 0; off >>= 1)
        sum += __shfl_xor_sync(0xFFFFFFFFu, sum, off, 8);

    float inv = 1.0f / sum;
    int row = row0 + r;
#pragma unroll
    for (int a = 0; a < 8; a++)
        out[(size_t)row * 64 + ag * 8 + a] = l[a] * inv;
    if (ag == 0)
        out[(size_t)BATCH * 64 + row] = vacc + bv[0];
}

// ---------------------------------------------------------------------------
extern "C" void kernel_launch(void* const* d_in, const int* in_sizes, int n_in,
                              void* d_out, int out_size) {
    const float* s      = (const float*)d_in[0];
    const float* a_prev = (const float*)d_in[1];
    const float* r_prev = (const float*)d_in[2];
    const float* h      = (const float*)d_in[3];
    const float* c      = (const float*)d_in[4];
    const float* Wx     = (const float*)d_in[5];
    const float* Wh     = (const float*)d_in[6];
    const float* bh     = (const float*)d_in[7];
    const float* Wa     = (const float*)d_in[8];
    const float* ba     = (const float*)d_in[9];
    const float* Wv     = (const float*)d_in[10];
    const float* bv     = (const float*)d_in[11];
    float* out = (float*)d_out;

    pack_kernel<<<(BATCH * KPAD + 255) / 256, 256>>>(s, a_prev, r_prev);
    vb_partial<<<dim3(FOURH / 256, 8), 256>>>(h, Wh);
    vb_reduce<<<FOURH / 256, 256>>>(bh);
    lstm_gemm<<<dim3(HDIM / BN, BATCH / BM), 256>>>(Wx, c);
    heads_kernel<<<BATCH / 32, 256>>>(Wa, ba, Wv, bv, out);
}

// round 3
// speedup vs baseline: 1.7692x; 1.7692x over previous
#include <cuda_runtime.h>
#include <cuda_bf16.h>
#include <math.h>
#include <cstdint>

#define BATCH 4096
#define SDIM  512
#define ADIM  64
#define HDIM  2048
#define KDIM  577
#define KP    640            // padded K: 10 chunks of 64
#define FOURH 8192

// ---------------- scratch (static device globals) ----------------
__device__ __nv_bfloat16 g_x_hi[BATCH * KP];
__device__ __nv_bfloat16 g_x_lo[BATCH * KP];
__device__ __nv_bfloat16 g_w_hi[FOURH * KP];   // gate-interleaved rows n' = j*4 + g
__device__ __nv_bfloat16 g_w_lo[FOURH * KP];
__device__ float g_vb[FOURH];
__device__ float g_vbp[8 * FOURH];
__device__ float g_hn[BATCH * HDIM];

__device__ __forceinline__ uint32_t smem_u32(const void* p) {
    uint32_t a;
    asm("{ .reg .u64 t; cvta.to.shared.u64 t, %1; cvt.u32.u64 %0, t; }" : "=r"(a) : "l"(p));
    return a;
}
#define SWZ128(off) ((off) ^ (((off) >> 3) & 0x70))

__device__ __forceinline__ void ldmx4(uint32_t* r, uint32_t addr) {
    asm volatile("ldmatrix.sync.aligned.m8n8.x4.shared.b16 {%0,%1,%2,%3}, [%4];"
                 : "=r"(r[0]), "=r"(r[1]), "=r"(r[2]), "=r"(r[3]) : "r"(addr));
}
__device__ __forceinline__ void ldmx2(uint32_t* r, uint32_t addr) {
    asm volatile("ldmatrix.sync.aligned.m8n8.x2.shared.b16 {%0,%1}, [%2];"
                 : "=r"(r[0]), "=r"(r[1]) : "r"(addr));
}
__device__ __forceinline__ void mma16816(float* c, const uint32_t* a, const uint32_t* b) {
    asm volatile(
        "mma.sync.aligned.m16n8k16.row.col.f32.bf16.bf16.f32 "
        "{%0,%1,%2,%3}, {%4,%5,%6,%7}, {%8,%9}, {%0,%1,%2,%3};"
        : "+f"(c[0]), "+f"(c[1]), "+f"(c[2]), "+f"(c[3])
        : "r"(a[0]), "r"(a[1]), "r"(a[2]), "r"(a[3]), "r"(b[0]), "r"(b[1]));
}

// ---------------------------------------------------------------------------
// 1) convX: pack [s|a|r] -> bf16 hi/lo planes [BATCH x KP]
// ---------------------------------------------------------------------------
__global__ void convX(const float* __restrict__ s, const float* __restrict__ a,
                      const float* __restrict__ r) {
    int idx = blockIdx.x * 256 + threadIdx.x;
    if (idx >= BATCH * KP) return;
    int b = idx / KP;
    int k = idx - b * KP;
    float v = 0.0f;
    if (k < SDIM)                v = s[b * SDIM + k];
    else if (k < SDIM + ADIM)    v = a[b * ADIM + (k - SDIM)];
    else if (k == SDIM + ADIM)   v = r[b];
    __nv_bfloat16 hi = __float2bfloat16(v);
    g_x_hi[idx] = hi;
    g_x_lo[idx] = __float2bfloat16(v - __bfloat162float(hi));
}

// ---------------------------------------------------------------------------
// 2) convW: Wx [KDIM x 8192] -> K-major bf16 hi/lo, gate-interleaved rows
//    n' = (n & 2047)*4 + (n >> 11)
// ---------------------------------------------------------------------------
__global__ void convW(const float* __restrict__ Wx) {
    __shared__ float t[64][33];
    int n0 = blockIdx.x * 32;
    int k0 = blockIdx.y * 64;
    int tx = threadIdx.x, ty = threadIdx.y;       // (32, 8)
#pragma unroll
    for (int i = 0; i < 8; i++) {
        int kl = ty * 8 + i;
        int k  = k0 + kl;
        t[kl][tx] = (k < KDIM) ? Wx[(size_t)k * FOURH + n0 + tx] : 0.0f;
    }
    __syncthreads();
    int tid = ty * 32 + tx;
    int nl  = tid >> 3;
    int ch  = tid & 7;
    int n   = n0 + nl;
    size_t np = (size_t)(n & 2047) * 4 + (n >> 11);
    uint4 vh, vl;
    __nv_bfloat16* ph = (__nv_bfloat16*)&vh;
    __nv_bfloat16* pl = (__nv_bfloat16*)&vl;
#pragma unroll
    for (int u = 0; u < 8; u++) {
        float v = t[ch * 8 + u][nl];
        __nv_bfloat16 hi = __float2bfloat16(v);
        ph[u] = hi;
        pl[u] = __float2bfloat16(v - __bfloat162float(hi));
    }
    *(uint4*)&g_w_hi[np * KP + k0 + ch * 8] = vh;
    *(uint4*)&g_w_lo[np * KP + k0 + ch * 8] = vl;
}

// ---------------------------------------------------------------------------
// 3+4) vb = bh + h @ Wh (fp32 exact)
// ---------------------------------------------------------------------------
__global__ void vb_partial(const float* __restrict__ h, const float* __restrict__ Wh) {
    int j  = blockIdx.x * 256 + threadIdx.x;
    int k0 = blockIdx.y * 256;
    float acc = 0.0f;
#pragma unroll 8
    for (int k = 0; k < 256; k++)
        acc += h[k0 + k] * Wh[(size_t)(k0 + k) * FOURH + j];
    g_vbp[blockIdx.y * FOURH + j] = acc;
}
__global__ void vb_reduce(const float* __restrict__ bh) {
    int j = blockIdx.x * 256 + threadIdx.x;
    float acc = bh[j];
#pragma unroll
    for (int kc = 0; kc < 8; kc++) acc += g_vbp[kc * FOURH + j];
    g_vb[j] = acc;
}

// ---------------------------------------------------------------------------
// 5) HMMA GEMM + LSTM gate epilogue.
//    CTA: 128 rows x 128 cols (= 32 hidden units x 4 gates interleaved).
//    8 warps, each 64x32. bf16 hi/lo 3-term split, fp32 accum.
// ---------------------------------------------------------------------------
#define SA_HI 0
#define SA_LO 16384
#define SB_HI 32768
#define SB_LO 49152
#define SMEM_SZ 65536

__global__ __launch_bounds__(256, 2) void lstm_mma(const float* __restrict__ cvec) {
    extern __shared__ char smem[];
    uint32_t sb = smem_u32(smem);
    int tid  = threadIdx.x;
    int lane = tid & 31, w = tid >> 5;
    int wm = w & 1, wn = w >> 1;          // 2 x 4 warp grid
    int row0 = blockIdx.y * 128;
    int j0   = blockIdx.x * 32;

    int lr = lane & 7, ls = lane >> 3;
    uint32_t a_row = wm * 64 + lr + (ls & 1) * 8;   // + mt*16
    uint32_t a_chs = (uint32_t)(ls >> 1);           // + kb
    uint32_t b_row = wn * 32 + lr;                  // + nt*8
    uint32_t b_chs = (uint32_t)(ls & 1);            // + kb

    float acc[4][4][4];
#pragma unroll
    for (int mt = 0; mt < 4; mt++)
#pragma unroll
        for (int nt = 0; nt < 4; nt++)
#pragma unroll
            for (int i = 0; i < 4; i++) acc[mt][nt][i] = 0.0f;

    for (int t = 0; t < KP / 64; t++) {
        int kg = t * 64;
        // global -> smem: 4 planes of [128 rows x 64 bf16], SW128 swizzle
#pragma unroll
        for (int i = 0; i < 4; i++) {
            int slot = tid + i * 256;
            int r  = slot >> 3;
            int ch = slot & 7;
            uint32_t sw = SWZ128((uint32_t)(r * 128 + ch * 16));
            size_t xa = (size_t)(row0 + r) * KP + kg + ch * 8;
            *(uint4*)(smem + SA_HI + sw) = *(const uint4*)(g_x_hi + xa);
            *(uint4*)(smem + SA_LO + sw) = *(const uint4*)(g_x_lo + xa);
            size_t wa = (size_t)(j0 * 4 + r) * KP + kg + ch * 8;
            *(uint4*)(smem + SB_HI + sw) = *(const uint4*)(g_w_hi + wa);
            *(uint4*)(smem + SB_LO + sw) = *(const uint4*)(g_w_lo + wa);
        }
        __syncthreads();

#pragma unroll
        for (int kb = 0; kb < 8; kb += 2) {          // 4 k16 steps
            uint32_t bhi[4][2], blo[4][2];
#pragma unroll
            for (int nt = 0; nt < 4; nt++) {
                uint32_t off = SWZ128((b_row + nt * 8) * 128 + (kb + b_chs) * 16);
                ldmx2(bhi[nt], sb + SB_HI + off);
                ldmx2(blo[nt], sb + SB_LO + off);
            }
#pragma unroll
            for (int mt = 0; mt < 4; mt++) {
                uint32_t ahi[4], alo[4];
                uint32_t off = SWZ128((a_row + mt * 16) * 128 + (kb + a_chs) * 16);
                ldmx4(ahi, sb + SA_HI + off);
                ldmx4(alo, sb + SA_LO + off);
#pragma unroll
                for (int nt = 0; nt < 4; nt++) {
                    mma16816(acc[mt][nt], ahi, bhi[nt]);
                    mma16816(acc[mt][nt], ahi, blo[nt]);
                    mma16816(acc[mt][nt], alo, bhi[nt]);
                }
            }
        }
        __syncthreads();
    }

    // ---- epilogue: gate math; cols interleaved c = jj*4 + g ----
    int q = lane & 3;
    int gp = q & 1;            // 0: this lane holds (zi,zf); 1: (zg,zo)
    int jsel = q >> 1;
    float* hsm = (float*)smem; // [128][33] overlay (planes dead now)

#pragma unroll
    for (int nt = 0; nt < 4; nt++) {
        int j = j0 + wn * 8 + nt * 2 + jsel;
        float vbi = __ldg(&g_vb[j]);
        float vbf = __ldg(&g_vb[HDIM + j]);
        float vbg = __ldg(&g_vb[2 * HDIM + j]);
        float vbo = __ldg(&g_vb[3 * HDIM + j]);
        float cj  = __ldg(&cvec[j]);
#pragma unroll
        for (int mt = 0; mt < 4; mt++) {
            float v0 = acc[mt][nt][0], v1 = acc[mt][nt][1];
            float v2 = acc[mt][nt][2], v3 = acc[mt][nt][3];
            float p0 = __shfl_xor_sync(0xFFFFFFFFu, v0, 1);
            float p1 = __shfl_xor_sync(0xFFFFFFFFu, v1, 1);
            float p2 = __shfl_xor_sync(0xFFFFFFFFu, v2, 1);
            float p3 = __shfl_xor_sync(0xFFFFFFFFu, v3, 1);
            float zi0 = gp ? p0 : v0, zf0 = gp ? p1 : v1;
            float zg0 = gp ? v0 : p0, zo0 = gp ? v1 : p1;
            float zi1 = gp ? p2 : v2, zf1 = gp ? p3 : v3;
            float zg1 = gp ? v2 : p2, zo1 = gp ? v3 : p3;

            zi0 += vbi; zf0 += vbf; zg0 += vbg; zo0 += vbo;
            zi1 += vbi; zf1 += vbf; zg1 += vbg; zo1 += vbo;

            float i0 = 1.0f / (1.0f + __expf(-zi0));
            float f0 = 1.0f / (1.0f + __expf(-zf0));
            float o0 = 1.0f / (1.0f + __expf(-zo0));
            float c0 = f0 * cj + i0 * tanhf(zg0);
            float h0 = o0 * tanhf(c0);
            float i1 = 1.0f / (1.0f + __expf(-zi1));
            float f1 = 1.0f / (1.0f + __expf(-zf1));
            float o1 = 1.0f / (1.0f + __expf(-zo1));
            float c1 = f1 * cj + i1 * tanhf(zg1);
            float h1 = o1 * tanhf(c1);

            if (gp == 0) {
                int rw = wm * 64 + mt * 16 + (lane >> 2);
                int jl = wn * 8 + nt * 2 + jsel;
                hsm[rw * 33 + jl]       = h0;
                hsm[(rw + 8) * 33 + jl] = h1;
            }
        }
    }
    __syncthreads();

    // coalesced write of the CTA's [128 x 32] h tile
#pragma unroll
    for (int i = 0; i < 16; i++) {
        int idx = tid + i * 256;
        int rw = idx >> 5, cl = idx & 31;
        g_hn[(size_t)(row0 + rw) * HDIM + j0 + cl] = hsm[rw * 33 + cl];
    }
}

// ---------------------------------------------------------------------------
// 6) heads: softmax(h @ Wa + ba), v = h @ Wv + bv
// ---------------------------------------------------------------------------
__global__ __launch_bounds__(256) void heads_kernel(const float* __restrict__ Wa,
                                                    const float* __restrict__ ba,
                                                    const float* __restrict__ Wv,
                                                    const float* __restrict__ bv,
                                                    float* __restrict__ out) {
    __shared__ float hs[32][64];
    __shared__ float was[64][64];
    __shared__ float wvs[64];

    int tid  = threadIdx.x;
    int r    = tid >> 3;
    int ag   = tid & 7;
    int row0 = blockIdx.x * 32;

    float acc[8];
#pragma unroll
    for (int a = 0; a < 8; a++) acc[a] = 0.0f;
    float vacc = 0.0f;

    for (int k0 = 0; k0 < HDIM; k0 += 64) {
#pragma unroll
        for (int i = 0; i < 2; i++) {
            int slot = tid + i * 256;
            int rr = slot >> 4, kk4 = (slot & 15) * 4;
            *(float4*)&hs[rr][kk4] =
                *(const float4*)&g_hn[(size_t)(row0 + rr) * HDIM + k0 + kk4];
        }
#pragma unroll
        for (int i = 0; i < 4; i++) {
            int slot = tid + i * 256;
            int kk = slot >> 4, a4 = (slot & 15) * 4;
            *(float4*)&was[kk][a4] = *(const float4*)&Wa[(size_t)(k0 + kk) * 64 + a4];
        }
        if (tid < 64) wvs[tid] = Wv[k0 + tid];
        __syncthreads();

#pragma unroll 8
        for (int kk = 0; kk < 64; kk++) {
            float h = hs[r][kk];
            vacc += h * wvs[kk];
#pragma unroll
            for (int a = 0; a < 8; a++)
                acc[a] += h * was[kk][ag * 8 + a];
        }
        __syncthreads();
    }

    float l[8];
    float m = -INFINITY;
#pragma unroll
    for (int a = 0; a < 8; a++) {
        l[a] = acc[a] + ba[ag * 8 + a];
        m = fmaxf(m, l[a]);
    }
#pragma unroll
    for (int off = 4; off > 0; off >>= 1)
        m = fmaxf(m, __shfl_xor_sync(0xFFFFFFFFu, m, off, 8));

    float sum = 0.0f;
#pragma unroll
    for (int a = 0; a < 8; a++) {
        l[a] = expf(l[a] - m);
        sum += l[a];
    }
#pragma unroll
    for (int off = 4; off > 0; off >>= 1)
        sum += __shfl_xor_sync(0xFFFFFFFFu, sum, off, 8);

    float inv = 1.0f / sum;
    int row = row0 + r;
#pragma unroll
    for (int a = 0; a < 8; a++)
        out[(size_t)row * 64 + ag * 8 + a] = l[a] * inv;
    if (ag == 0)
        out[(size_t)BATCH * 64 + row] = vacc + bv[0];
}

// ---------------------------------------------------------------------------
extern "C" void kernel_launch(void* const* d_in, const int* in_sizes, int n_in,
                              void* d_out, int out_size) {
    const float* s      = (const float*)d_in[0];
    const float* a_prev = (const float*)d_in[1];
    const float* r_prev = (const float*)d_in[2];
    const float* h      = (const float*)d_in[3];
    const float* c      = (const float*)d_in[4];
    const float* Wx     = (const float*)d_in[5];
    const float* Wh     = (const float*)d_in[6];
    const float* bh     = (const float*)d_in[7];
    const float* Wa     = (const float*)d_in[8];
    const float* ba     = (const float*)d_in[9];
    const float* Wv     = (const float*)d_in[10];
    const float* bv     = (const float*)d_in[11];
    float* out = (float*)d_out;

    static bool attr_set = false;
    if (!attr_set) {
        cudaFuncSetAttribute(lstm_mma, cudaFuncAttributeMaxDynamicSharedMemorySize, SMEM_SZ);
        attr_set = true;
    }

    convX<<<(BATCH * KP + 255) / 256, 256>>>(s, a_prev, r_prev);
    convW<<<dim3(FOURH / 32, KP / 64), dim3(32, 8)>>>(Wx);
    vb_partial<<<dim3(FOURH / 256, 8), 256>>>(h, Wh);
    vb_reduce<<<FOURH / 256, 256>>>(bh);
    lstm_mma<<<dim3(HDIM / 32, BATCH / 128), 256, SMEM_SZ>>>(c);
    heads_kernel<<<BATCH / 32, 256>>>(Wa, ba, Wv, bv, out);
}

// round 4
// speedup vs baseline: 1.9384x; 1.0956x over previous
#include <cuda_runtime.h>
#include <cuda_bf16.h>
#include <math.h>
#include <cstdint>

#define BATCH 4096
#define SDIM  512
#define ADIM  64
#define HDIM  2048
#define KDIM  577
#define KP    640            // padded K: 10 chunks of 64
#define NCH   10
#define FOURH 8192

// ---------------- scratch (static device globals) ----------------
__device__ __nv_bfloat16 g_x_hi[BATCH * KP];
__device__ __nv_bfloat16 g_x_lo[BATCH * KP];
__device__ __nv_bfloat16 g_w_hi[FOURH * KP];   // gate-interleaved rows n' = j*4 + g
__device__ __nv_bfloat16 g_w_lo[FOURH * KP];
__device__ float g_vb[FOURH];
__device__ float g_vbp[8 * FOURH];
__device__ float g_hn[BATCH * HDIM];

__device__ __forceinline__ uint32_t smem_u32(const void* p) {
    uint32_t a;
    asm("{ .reg .u64 t; cvta.to.shared.u64 t, %1; cvt.u32.u64 %0, t; }" : "=r"(a) : "l"(p));
    return a;
}
#define SWZ128(off) ((off) ^ (((off) >> 3) & 0x70))

__device__ __forceinline__ void cpa16(uint32_t smem, const void* g) {
    asm volatile("cp.async.cg.shared.global [%0], [%1], 16;" :: "r"(smem), "l"(g));
}
#define CPA_COMMIT()  asm volatile("cp.async.commit_group;" ::: "memory")
#define CPA_WAIT(n)   asm volatile("cp.async.wait_group %0;" :: "n"(n) : "memory")

__device__ __forceinline__ void ldmx4(uint32_t* r, uint32_t addr) {
    asm volatile("ldmatrix.sync.aligned.m8n8.x4.shared.b16 {%0,%1,%2,%3}, [%4];"
                 : "=r"(r[0]), "=r"(r[1]), "=r"(r[2]), "=r"(r[3]) : "r"(addr));
}
__device__ __forceinline__ void ldmx2(uint32_t* r, uint32_t addr) {
    asm volatile("ldmatrix.sync.aligned.m8n8.x2.shared.b16 {%0,%1}, [%2];"
                 : "=r"(r[0]), "=r"(r[1]) : "r"(addr));
}
__device__ __forceinline__ void mma16816(float* c, const uint32_t* a, const uint32_t* b) {
    asm volatile(
        "mma.sync.aligned.m16n8k16.row.col.f32.bf16.bf16.f32 "
        "{%0,%1,%2,%3}, {%4,%5,%6,%7}, {%8,%9}, {%0,%1,%2,%3};"
        : "+f"(c[0]), "+f"(c[1]), "+f"(c[2]), "+f"(c[3])
        : "r"(a[0]), "r"(a[1]), "r"(a[2]), "r"(a[3]), "r"(b[0]), "r"(b[1]));
}

// ---------------------------------------------------------------------------
// 1) convX: pack [s|a|r] -> bf16 hi/lo planes [BATCH x KP]
// ---------------------------------------------------------------------------
__global__ void convX(const float* __restrict__ s, const float* __restrict__ a,
                      const float* __restrict__ r) {
    int idx = blockIdx.x * 256 + threadIdx.x;
    if (idx >= BATCH * KP) return;
    int b = idx / KP;
    int k = idx - b * KP;
    float v = 0.0f;
    if (k < SDIM)                v = s[b * SDIM + k];
    else if (k < SDIM + ADIM)    v = a[b * ADIM + (k - SDIM)];
    else if (k == SDIM + ADIM)   v = r[b];
    __nv_bfloat16 hi = __float2bfloat16(v);
    g_x_hi[idx] = hi;
    g_x_lo[idx] = __float2bfloat16(v - __bfloat162float(hi));
}

// ---------------------------------------------------------------------------
// 2) convW: Wx [KDIM x 8192] -> K-major bf16 hi/lo, gate-interleaved rows
// ---------------------------------------------------------------------------
__global__ void convW(const float* __restrict__ Wx) {
    __shared__ float t[64][33];
    int n0 = blockIdx.x * 32;
    int k0 = blockIdx.y * 64;
    int tx = threadIdx.x, ty = threadIdx.y;       // (32, 8)
#pragma unroll
    for (int i = 0; i < 8; i++) {
        int kl = ty * 8 + i;
        int k  = k0 + kl;
        t[kl][tx] = (k < KDIM) ? Wx[(size_t)k * FOURH + n0 + tx] : 0.0f;
    }
    __syncthreads();
    int tid = ty * 32 + tx;
    int nl  = tid >> 3;
    int ch  = tid & 7;
    int n   = n0 + nl;
    size_t np = (size_t)(n & 2047) * 4 + (n >> 11);
    uint4 vh, vl;
    __nv_bfloat16* ph = (__nv_bfloat16*)&vh;
    __nv_bfloat16* pl = (__nv_bfloat16*)&vl;
#pragma unroll
    for (int u = 0; u < 8; u++) {
        float v = t[ch * 8 + u][nl];
        __nv_bfloat16 hi = __float2bfloat16(v);
        ph[u] = hi;
        pl[u] = __float2bfloat16(v - __bfloat162float(hi));
    }
    *(uint4*)&g_w_hi[np * KP + k0 + ch * 8] = vh;
    *(uint4*)&g_w_lo[np * KP + k0 + ch * 8] = vl;
}

// ---------------------------------------------------------------------------
// 3+4) vb = bh + h @ Wh (fp32 exact)
// ---------------------------------------------------------------------------
__global__ void vb_partial(const float* __restrict__ h, const float* __restrict__ Wh) {
    int j  = blockIdx.x * 256 + threadIdx.x;
    int k0 = blockIdx.y * 256;
    float acc = 0.0f;
#pragma unroll 8
    for (int k = 0; k < 256; k++)
        acc += h[k0 + k] * Wh[(size_t)(k0 + k) * FOURH + j];
    g_vbp[blockIdx.y * FOURH + j] = acc;
}
__global__ void vb_reduce(const float* __restrict__ bh) {
    int j = blockIdx.x * 256 + threadIdx.x;
    float acc = bh[j];
#pragma unroll
    for (int kc = 0; kc < 8; kc++) acc += g_vbp[kc * FOURH + j];
    g_vb[j] = acc;
}

// ---------------------------------------------------------------------------
// 5) HMMA GEMM + LSTM gate epilogue, cp.async double-buffered.
//    CTA: 256 rows x 128 cols (32 hidden x 4 gates interleaved), 512 threads,
//    16 warps in 4m x 4n grid, each warp 64x32. bf16 hi/lo 3-term split.
// ---------------------------------------------------------------------------
#define ST_AHI 0
#define ST_ALO 32768
#define ST_BHI 65536
#define ST_BLO 81920
#define ST_STRIDE 98304
#define SMEM_SZ (2 * ST_STRIDE)

__device__ __forceinline__ void load_stage(uint32_t sb, int stage, int kg,
                                           int row0, int j0, int tid) {
    uint32_t base = sb + stage * ST_STRIDE;
    // A planes: 256 rows x 64 bf16 = 2048 x 16B each
#pragma unroll
    for (int i = 0; i < 4; i++) {
        int slot = tid + i * 512;
        int r = slot >> 3, ch = slot & 7;
        uint32_t sw = SWZ128((uint32_t)(r * 128 + ch * 16));
        size_t xa = (size_t)(row0 + r) * KP + kg + ch * 8;
        cpa16(base + ST_AHI + sw, g_x_hi + xa);
        cpa16(base + ST_ALO + sw, g_x_lo + xa);
    }
    // B planes: 128 rows x 64 bf16 = 1024 x 16B each
#pragma unroll
    for (int i = 0; i < 2; i++) {
        int slot = tid + i * 512;
        int r = slot >> 3, ch = slot & 7;
        uint32_t sw = SWZ128((uint32_t)(r * 128 + ch * 16));
        size_t wa = (size_t)(j0 * 4 + r) * KP + kg + ch * 8;
        cpa16(base + ST_BHI + sw, g_w_hi + wa);
        cpa16(base + ST_BLO + sw, g_w_lo + wa);
    }
}

__global__ __launch_bounds__(512, 1) void lstm_mma(const float* __restrict__ cvec) {
    extern __shared__ char smem[];
    uint32_t sb = smem_u32(smem);
    int tid  = threadIdx.x;
    int lane = tid & 31, w = tid >> 5;
    int wm = w & 3, wn = w >> 2;          // 4 x 4 warp grid
    int row0 = blockIdx.y * 256;
    int j0   = blockIdx.x * 32;

    int lr = lane & 7, ls = lane >> 3;
    uint32_t a_row = wm * 64 + lr + (ls & 1) * 8;   // + mt*16
    uint32_t a_chs = (uint32_t)(ls >> 1);           // + kb
    uint32_t b_row = wn * 32 + lr;                  // + nt*8
    uint32_t b_chs = (uint32_t)(ls & 1);            // + kb

    float acc[4][4][4];
#pragma unroll
    for (int mt = 0; mt < 4; mt++)
#pragma unroll
        for (int nt = 0; nt < 4; nt++)
#pragma unroll
            for (int i = 0; i < 4; i++) acc[mt][nt][i] = 0.0f;

    // prefetch chunk 0
    load_stage(sb, 0, 0, row0, j0, tid);
    CPA_COMMIT();

    for (int t = 0; t < NCH; t++) {
        int cur = t & 1;
        if (t + 1 < NCH) {
            load_stage(sb, cur ^ 1, (t + 1) * 64, row0, j0, tid);
            CPA_COMMIT();
            CPA_WAIT(1);
        } else {
            CPA_WAIT(0);
        }
        __syncthreads();

        uint32_t sa = sb + cur * ST_STRIDE;
#pragma unroll
        for (int kb = 0; kb < 8; kb += 2) {          // 4 k16 steps
            uint32_t bhi[4][2], blo[4][2];
#pragma unroll
            for (int nt = 0; nt < 4; nt++) {
                uint32_t off = SWZ128((b_row + nt * 8) * 128 + (kb + b_chs) * 16);
                ldmx2(bhi[nt], sa + ST_BHI + off);
                ldmx2(blo[nt], sa + ST_BLO + off);
            }
#pragma unroll
            for (int mt = 0; mt < 4; mt++) {
                uint32_t ahi[4], alo[4];
                uint32_t off = SWZ128((a_row + mt * 16) * 128 + (kb + a_chs) * 16);
                ldmx4(ahi, sa + ST_AHI + off);
                ldmx4(alo, sa + ST_ALO + off);
#pragma unroll
                for (int nt = 0; nt < 4; nt++) {
                    mma16816(acc[mt][nt], ahi, bhi[nt]);
                    mma16816(acc[mt][nt], ahi, blo[nt]);
                    mma16816(acc[mt][nt], alo, bhi[nt]);
                }
            }
        }
        __syncthreads();
    }

    // ---- epilogue: gate math; cols interleaved c = jj*4 + g ----
    int q = lane & 3;
    int gp = q & 1;            // 0: this lane holds (zi,zf); 1: (zg,zo)
    int jsel = q >> 1;
    float* hsm = (float*)smem; // [256][33] overlay

#pragma unroll
    for (int nt = 0; nt < 4; nt++) {
        int j = j0 + wn * 8 + nt * 2 + jsel;
        float vbi = __ldg(&g_vb[j]);
        float vbf = __ldg(&g_vb[HDIM + j]);
        float vbg = __ldg(&g_vb[2 * HDIM + j]);
        float vbo = __ldg(&g_vb[3 * HDIM + j]);
        float cj  = __ldg(&cvec[j]);
#pragma unroll
        for (int mt = 0; mt < 4; mt++) {
            float v0 = acc[mt][nt][0], v1 = acc[mt][nt][1];
            float v2 = acc[mt][nt][2], v3 = acc[mt][nt][3];
            float p0 = __shfl_xor_sync(0xFFFFFFFFu, v0, 1);
            float p1 = __shfl_xor_sync(0xFFFFFFFFu, v1, 1);
            float p2 = __shfl_xor_sync(0xFFFFFFFFu, v2, 1);
            float p3 = __shfl_xor_sync(0xFFFFFFFFu, v3, 1);
            float zi0 = gp ? p0 : v0, zf0 = gp ? p1 : v1;
            float zg0 = gp ? v0 : p0, zo0 = gp ? v1 : p1;
            float zi1 = gp ? p2 : v2, zf1 = gp ? p3 : v3;
            float zg1 = gp ? v2 : p2, zo1 = gp ? v3 : p3;

            zi0 += vbi; zf0 += vbf; zg0 += vbg; zo0 += vbo;
            zi1 += vbi; zf1 += vbf; zg1 += vbg; zo1 += vbo;

            float i0 = 1.0f / (1.0f + __expf(-zi0));
            float f0 = 1.0f / (1.0f + __expf(-zf0));
            float o0 = 1.0f / (1.0f + __expf(-zo0));
            float c0 = f0 * cj + i0 * tanhf(zg0);
            float h0 = o0 * tanhf(c0);
            float i1 = 1.0f / (1.0f + __expf(-zi1));
            float f1 = 1.0f / (1.0f + __expf(-zf1));
            float o1 = 1.0f / (1.0f + __expf(-zo1));
            float c1 = f1 * cj + i1 * tanhf(zg1);
            float h1 = o1 * tanhf(c1);

            if (gp == 0) {
                int rw = wm * 64 + mt * 16 + (lane >> 2);
                int jl = wn * 8 + nt * 2 + jsel;
                hsm[rw * 33 + jl]       = h0;
                hsm[(rw + 8) * 33 + jl] = h1;
            }
        }
    }
    __syncthreads();

    // coalesced write of the CTA's [256 x 32] h tile
#pragma unroll
    for (int i = 0; i < 16; i++) {
        int idx = tid + i * 512;
        int rw = idx >> 5, cl = idx & 31;
        g_hn[(size_t)(row0 + rw) * HDIM + j0 + cl] = hsm[rw * 33 + cl];
    }
}

// ---------------------------------------------------------------------------
// 6) heads: softmax(h @ Wa + ba), v = h @ Wv + bv
// ---------------------------------------------------------------------------
__global__ __launch_bounds__(256) void heads_kernel(const float* __restrict__ Wa,
                                                    const float* __restrict__ ba,
                                                    const float* __restrict__ Wv,
                                                    const float* __restrict__ bv,
                                                    float* __restrict__ out) {
    __shared__ float hs[32][64];
    __shared__ float was[64][64];
    __shared__ float wvs[64];

    int tid  = threadIdx.x;
    int r    = tid >> 3;
    int ag   = tid & 7;
    int row0 = blockIdx.x * 32;

    float acc[8];
#pragma unroll
    for (int a = 0; a < 8; a++) acc[a] = 0.0f;
    float vacc = 0.0f;

    for (int k0 = 0; k0 < HDIM; k0 += 64) {
#pragma unroll
        for (int i = 0; i < 2; i++) {
            int slot = tid + i * 256;
            int rr = slot >> 4, kk4 = (slot & 15) * 4;
            *(float4*)&hs[rr][kk4] =
                *(const float4*)&g_hn[(size_t)(row0 + rr) * HDIM + k0 + kk4];
        }
#pragma unroll
        for (int i = 0; i < 4; i++) {
            int slot = tid + i * 256;
            int kk = slot >> 4, a4 = (slot & 15) * 4;
            *(float4*)&was[kk][a4] = *(const float4*)&Wa[(size_t)(k0 + kk) * 64 + a4];
        }
        if (tid < 64) wvs[tid] = Wv[k0 + tid];
        __syncthreads();

#pragma unroll 8
        for (int kk = 0; kk < 64; kk++) {
            float h = hs[r][kk];
            vacc += h * wvs[kk];
#pragma unroll
            for (int a = 0; a < 8; a++)
                acc[a] += h * was[kk][ag * 8 + a];
        }
        __syncthreads();
    }

    float l[8];
    float m = -INFINITY;
#pragma unroll
    for (int a = 0; a < 8; a++) {
        l[a] = acc[a] + ba[ag * 8 + a];
        m = fmaxf(m, l[a]);
    }
#pragma unroll
    for (int off = 4; off > 0; off >>= 1)
        m = fmaxf(m, __shfl_xor_sync(0xFFFFFFFFu, m, off, 8));

    float sum = 0.0f;
#pragma unroll
    for (int a = 0; a < 8; a++) {
        l[a] = expf(l[a] - m);
        sum += l[a];
    }
#pragma unroll
    for (int off = 4; off > 0; off >>= 1)
        sum += __shfl_xor_sync(0xFFFFFFFFu, sum, off, 8);

    float inv = 1.0f / sum;
    int row = row0 + r;
#pragma unroll
    for (int a = 0; a < 8; a++)
        out[(size_t)row * 64 + ag * 8 + a] = l[a] * inv;
    if (ag == 0)
        out[(size_t)BATCH * 64 + row] = vacc + bv[0];
}

// ---------------------------------------------------------------------------
extern "C" void kernel_launch(void* const* d_in, const int* in_sizes, int n_in,
                              void* d_out, int out_size) {
    const float* s      = (const float*)d_in[0];
    const float* a_prev = (const float*)d_in[1];
    const float* r_prev = (const float*)d_in[2];
    const float* h      = (const float*)d_in[3];
    const float* c      = (const float*)d_in[4];
    const float* Wx     = (const float*)d_in[5];
    const float* Wh     = (const float*)d_in[6];
    const float* bh     = (const float*)d_in[7];
    const float* Wa     = (const float*)d_in[8];
    const float* ba     = (const float*)d_in[9];
    const float* Wv     = (const float*)d_in[10];
    const float* bv     = (const float*)d_in[11];
    float* out = (float*)d_out;

    static bool attr_set = false;
    if (!attr_set) {
        cudaFuncSetAttribute(lstm_mma, cudaFuncAttributeMaxDynamicSharedMemorySize, SMEM_SZ);
        attr_set = true;
    }

    convX<<<(BATCH * KP + 255) / 256, 256>>>(s, a_prev, r_prev);
    convW<<<dim3(FOURH / 32, KP / 64), dim3(32, 8)>>>(Wx);
    vb_partial<<<dim3(FOURH / 256, 8), 256>>>(h, Wh);
    vb_reduce<<<FOURH / 256, 256>>>(bh);
    lstm_mma<<<dim3(HDIM / 32, BATCH / 256), 512, SMEM_SZ>>>(c);
    heads_kernel<<<BATCH / 32, 256>>>(Wa, ba, Wv, bv, out);
}

// round 5
// speedup vs baseline: 2.2640x; 1.1680x over previous
#include <cuda_runtime.h>
#include <cuda_fp16.h>
#include <math.h>
#include <cstdint>

#define BATCH 4096
#define SDIM  512
#define ADIM  64
#define HDIM  2048
#define KDIM  577
#define KP    640            // padded K: 10 chunks of 64
#define NCH   10
#define FOURH 8192

// ---------------- scratch (static device globals) ----------------
__device__ __half g_x_hi[BATCH * KP];
__device__ __half g_x_lo[BATCH * KP];
__device__ __half g_w[FOURH * KP];      // gate-interleaved rows n' = j*4 + g
__device__ float g_vb[FOURH];
__device__ float g_vbp[8 * FOURH];
__device__ float g_hn[BATCH * HDIM];

__device__ __forceinline__ uint32_t smem_u32(const void* p) {
    uint32_t a;
    asm("{ .reg .u64 t; cvta.to.shared.u64 t, %1; cvt.u32.u64 %0, t; }" : "=r"(a) : "l"(p));
    return a;
}
#define SWZ128(off) ((off) ^ (((off) >> 3) & 0x70))

__device__ __forceinline__ void cpa16(uint32_t smem, const void* g) {
    asm volatile("cp.async.cg.shared.global [%0], [%1], 16;" :: "r"(smem), "l"(g));
}
#define CPA_COMMIT()  asm volatile("cp.async.commit_group;" ::: "memory")
#define CPA_WAIT(n)   asm volatile("cp.async.wait_group %0;" :: "n"(n) : "memory")

__device__ __forceinline__ void ldmx4(uint32_t* r, uint32_t addr) {
    asm volatile("ldmatrix.sync.aligned.m8n8.x4.shared.b16 {%0,%1,%2,%3}, [%4];"
                 : "=r"(r[0]), "=r"(r[1]), "=r"(r[2]), "=r"(r[3]) : "r"(addr));
}
__device__ __forceinline__ void ldmx2(uint32_t* r, uint32_t addr) {
    asm volatile("ldmatrix.sync.aligned.m8n8.x2.shared.b16 {%0,%1}, [%2];"
                 : "=r"(r[0]), "=r"(r[1]) : "r"(addr));
}
__device__ __forceinline__ void mma16816(float* c, const uint32_t* a, const uint32_t* b) {
    asm volatile(
        "mma.sync.aligned.m16n8k16.row.col.f32.f16.f16.f32 "
        "{%0,%1,%2,%3}, {%4,%5,%6,%7}, {%8,%9}, {%0,%1,%2,%3};"
        : "+f"(c[0]), "+f"(c[1]), "+f"(c[2]), "+f"(c[3])
        : "r"(a[0]), "r"(a[1]), "r"(a[2]), "r"(a[3]), "r"(b[0]), "r"(b[1]));
}

// ---------------------------------------------------------------------------
// 1) convX: pack [s|a|r] -> fp16 hi/lo planes [BATCH x KP]
// ---------------------------------------------------------------------------
__global__ void convX(const float* __restrict__ s, const float* __restrict__ a,
                      const float* __restrict__ r) {
    int idx = blockIdx.x * 256 + threadIdx.x;
    if (idx >= BATCH * KP) return;
    int b = idx / KP;
    int k = idx - b * KP;
    float v = 0.0f;
    if (k < SDIM)                v = s[b * SDIM + k];
    else if (k < SDIM + ADIM)    v = a[b * ADIM + (k - SDIM)];
    else if (k == SDIM + ADIM)   v = r[b];
    __half hi = __float2half_rn(v);
    g_x_hi[idx] = hi;
    g_x_lo[idx] = __float2half_rn(v - __half2float(hi));
}

// ---------------------------------------------------------------------------
// 2) convW: Wx [KDIM x 8192] -> K-major fp16, gate-interleaved rows
//    n' = (n & 2047)*4 + (n >> 11)
// ---------------------------------------------------------------------------
__global__ void convW(const float* __restrict__ Wx) {
    __shared__ float t[64][33];
    int n0 = blockIdx.x * 32;
    int k0 = blockIdx.y * 64;
    int tx = threadIdx.x, ty = threadIdx.y;       // (32, 8)
#pragma unroll
    for (int i = 0; i < 8; i++) {
        int kl = ty * 8 + i;
        int k  = k0 + kl;
        t[kl][tx] = (k < KDIM) ? Wx[(size_t)k * FOURH + n0 + tx] : 0.0f;
    }
    __syncthreads();
    int tid = ty * 32 + tx;
    int nl  = tid >> 3;
    int ch  = tid & 7;
    int n   = n0 + nl;
    size_t np = (size_t)(n & 2047) * 4 + (n >> 11);
    uint4 vh;
    __half* ph = (__half*)&vh;
#pragma unroll
    for (int u = 0; u < 8; u++)
        ph[u] = __float2half_rn(t[ch * 8 + u][nl]);
    *(uint4*)&g_w[np * KP + k0 + ch * 8] = vh;
}

// ---------------------------------------------------------------------------
// 3+4) vb = bh + h @ Wh (fp32 exact)
// ---------------------------------------------------------------------------
__global__ void vb_partial(const float* __restrict__ h, const float* __restrict__ Wh) {
    int j  = blockIdx.x * 256 + threadIdx.x;
    int k0 = blockIdx.y * 256;
    float acc = 0.0f;
#pragma unroll 8
    for (int k = 0; k < 256; k++)
        acc += h[k0 + k] * Wh[(size_t)(k0 + k) * FOURH + j];
    g_vbp[blockIdx.y * FOURH + j] = acc;
}
__global__ void vb_reduce(const float* __restrict__ bh) {
    int j = blockIdx.x * 256 + threadIdx.x;
    float acc = bh[j];
#pragma unroll
    for (int kc = 0; kc < 8; kc++) acc += g_vbp[kc * FOURH + j];
    g_vb[j] = acc;
}

// ---------------------------------------------------------------------------
// 5) HMMA GEMM + LSTM gate epilogue, cp.async double-buffered.
//    CTA: 256 rows x 128 cols (32 hidden x 4 gates interleaved), 512 threads,
//    16 warps in 4m x 4n grid, each warp 64x32.
//    fp16 2-term split: z = xh*w + xl*w (error ~ x*wl ~ 2^-12 rel).
// ---------------------------------------------------------------------------
#define ST_AHI 0
#define ST_ALO 32768
#define ST_B   65536
#define ST_STRIDE 81920
#define SMEM_SZ (2 * ST_STRIDE)

__device__ __forceinline__ void load_stage(uint32_t sb, int stage, int kg,
                                           int row0, int j0, int tid) {
    uint32_t base = sb + stage * ST_STRIDE;
    // A planes: 256 rows x 64 halfs = 2048 x 16B each
#pragma unroll
    for (int i = 0; i < 4; i++) {
        int slot = tid + i * 512;
        int r = slot >> 3, ch = slot & 7;
        uint32_t sw = SWZ128((uint32_t)(r * 128 + ch * 16));
        size_t xa = (size_t)(row0 + r) * KP + kg + ch * 8;
        cpa16(base + ST_AHI + sw, g_x_hi + xa);
        cpa16(base + ST_ALO + sw, g_x_lo + xa);
    }
    // B plane: 128 rows x 64 halfs = 1024 x 16B
#pragma unroll
    for (int i = 0; i < 2; i++) {
        int slot = tid + i * 512;
        int r = slot >> 3, ch = slot & 7;
        uint32_t sw = SWZ128((uint32_t)(r * 128 + ch * 16));
        size_t wa = (size_t)(j0 * 4 + r) * KP + kg + ch * 8;
        cpa16(base + ST_B + sw, g_w + wa);
    }
}

__global__ __launch_bounds__(512, 1) void lstm_mma(const float* __restrict__ cvec) {
    extern __shared__ char smem[];
    uint32_t sb = smem_u32(smem);
    int tid  = threadIdx.x;
    int lane = tid & 31, w = tid >> 5;
    int wm = w & 3, wn = w >> 2;          // 4 x 4 warp grid
    int row0 = blockIdx.y * 256;
    int j0   = blockIdx.x * 32;

    int lr = lane & 7, ls = lane >> 3;
    uint32_t a_row = wm * 64 + lr + (ls & 1) * 8;   // + mt*16
    uint32_t a_chs = (uint32_t)(ls >> 1);           // + kb
    uint32_t b_row = wn * 32 + lr;                  // + nt*8
    uint32_t b_chs = (uint32_t)(ls & 1);            // + kb

    float acc[4][4][4];
#pragma unroll
    for (int mt = 0; mt < 4; mt++)
#pragma unroll
        for (int nt = 0; nt < 4; nt++)
#pragma unroll
            for (int i = 0; i < 4; i++) acc[mt][nt][i] = 0.0f;

    // prefetch chunk 0
    load_stage(sb, 0, 0, row0, j0, tid);
    CPA_COMMIT();

    for (int t = 0; t < NCH; t++) {
        int cur = t & 1;
        if (t + 1 < NCH) {
            load_stage(sb, cur ^ 1, (t + 1) * 64, row0, j0, tid);
            CPA_COMMIT();
            CPA_WAIT(1);
        } else {
            CPA_WAIT(0);
        }
        __syncthreads();

        uint32_t sa = sb + cur * ST_STRIDE;
#pragma unroll
        for (int kb = 0; kb < 8; kb += 2) {          // 4 k16 steps
            uint32_t bb[4][2];
#pragma unroll
            for (int nt = 0; nt < 4; nt++) {
                uint32_t off = SWZ128((b_row + nt * 8) * 128 + (kb + b_chs) * 16);
                ldmx2(bb[nt], sa + ST_B + off);
            }
#pragma unroll
            for (int mt = 0; mt < 4; mt++) {
                uint32_t ahi[4], alo[4];
                uint32_t off = SWZ128((a_row + mt * 16) * 128 + (kb + a_chs) * 16);
                ldmx4(ahi, sa + ST_AHI + off);
                ldmx4(alo, sa + ST_ALO + off);
#pragma unroll
                for (int nt = 0; nt < 4; nt++) {
                    mma16816(acc[mt][nt], ahi, bb[nt]);
                    mma16816(acc[mt][nt], alo, bb[nt]);
                }
            }
        }
        __syncthreads();
    }

    // ---- epilogue: gate math; cols interleaved c = jj*4 + g ----
    int q = lane & 3;
    int gp = q & 1;            // 0: this lane holds (zi,zf); 1: (zg,zo)
    int jsel = q >> 1;
    float* hsm = (float*)smem; // [256][33] overlay

#pragma unroll
    for (int nt = 0; nt < 4; nt++) {
        int j = j0 + wn * 8 + nt * 2 + jsel;
        float vbi = __ldg(&g_vb[j]);
        float vbf = __ldg(&g_vb[HDIM + j]);
        float vbg = __ldg(&g_vb[2 * HDIM + j]);
        float vbo = __ldg(&g_vb[3 * HDIM + j]);
        float cj  = __ldg(&cvec[j]);
#pragma unroll
        for (int mt = 0; mt < 4; mt++) {
            float v0 = acc[mt][nt][0], v1 = acc[mt][nt][1];
            float v2 = acc[mt][nt][2], v3 = acc[mt][nt][3];
            float p0 = __shfl_xor_sync(0xFFFFFFFFu, v0, 1);
            float p1 = __shfl_xor_sync(0xFFFFFFFFu, v1, 1);
            float p2 = __shfl_xor_sync(0xFFFFFFFFu, v2, 1);
            float p3 = __shfl_xor_sync(0xFFFFFFFFu, v3, 1);
            float zi0 = gp ? p0 : v0, zf0 = gp ? p1 : v1;
            float zg0 = gp ? v0 : p0, zo0 = gp ? v1 : p1;
            float zi1 = gp ? p2 : v2, zf1 = gp ? p3 : v3;
            float zg1 = gp ? v2 : p2, zo1 = gp ? v3 : p3;

            zi0 += vbi; zf0 += vbf; zg0 += vbg; zo0 += vbo;
            zi1 += vbi; zf1 += vbf; zg1 += vbg; zo1 += vbo;

            float i0 = 1.0f / (1.0f + __expf(-zi0));
            float f0 = 1.0f / (1.0f + __expf(-zf0));
            float o0 = 1.0f / (1.0f + __expf(-zo0));
            float c0 = f0 * cj + i0 * tanhf(zg0);
            float h0 = o0 * tanhf(c0);
            float i1 = 1.0f / (1.0f + __expf(-zi1));
            float f1 = 1.0f / (1.0f + __expf(-zf1));
            float o1 = 1.0f / (1.0f + __expf(-zo1));
            float c1 = f1 * cj + i1 * tanhf(zg1);
            float h1 = o1 * tanhf(c1);

            if (gp == 0) {
                int rw = wm * 64 + mt * 16 + (lane >> 2);
                int jl = wn * 8 + nt * 2 + jsel;
                hsm[rw * 33 + jl]       = h0;
                hsm[(rw + 8) * 33 + jl] = h1;
            }
        }
    }
    __syncthreads();

    // coalesced write of the CTA's [256 x 32] h tile
#pragma unroll
    for (int i = 0; i < 16; i++) {
        int idx = tid + i * 512;
        int rw = idx >> 5, cl = idx & 31;
        g_hn[(size_t)(row0 + rw) * HDIM + j0 + cl] = hsm[rw * 33 + cl];
    }
}

// ---------------------------------------------------------------------------
// 6) heads: softmax(h @ Wa + ba), v = h @ Wv + bv
// ---------------------------------------------------------------------------
__global__ __launch_bounds__(256) void heads_kernel(const float* __restrict__ Wa,
                                                    const float* __restrict__ ba,
                                                    const float* __restrict__ Wv,
                                                    const float* __restrict__ bv,
                                                    float* __restrict__ out) {
    __shared__ float hs[32][64];
    __shared__ float was[64][64];
    __shared__ float wvs[64];

    int tid  = threadIdx.x;
    int r    = tid >> 3;
    int ag   = tid & 7;
    int row0 = blockIdx.x * 32;

    float acc[8];
#pragma unroll
    for (int a = 0; a < 8; a++) acc[a] = 0.0f;
    float vacc = 0.0f;

    for (int k0 = 0; k0 < HDIM; k0 += 64) {
#pragma unroll
        for (int i = 0; i < 2; i++) {
            int slot = tid + i * 256;
            int rr = slot >> 4, kk4 = (slot & 15) * 4;
            *(float4*)&hs[rr][kk4] =
                *(const float4*)&g_hn[(size_t)(row0 + rr) * HDIM + k0 + kk4];
        }
#pragma unroll
        for (int i = 0; i < 4; i++) {
            int slot = tid + i * 256;
            int kk = slot >> 4, a4 = (slot & 15) * 4;
            *(float4*)&was[kk][a4] = *(const float4*)&Wa[(size_t)(k0 + kk) * 64 + a4];
        }
        if (tid < 64) wvs[tid] = Wv[k0 + tid];
        __syncthreads();

#pragma unroll 8
        for (int kk = 0; kk < 64; kk++) {
            float h = hs[r][kk];
            vacc += h * wvs[kk];
#pragma unroll
            for (int a = 0; a < 8; a++)
                acc[a] += h * was[kk][ag * 8 + a];
        }
        __syncthreads();
    }

    float l[8];
    float m = -INFINITY;
#pragma unroll
    for (int a = 0; a < 8; a++) {
        l[a] = acc[a] + ba[ag * 8 + a];
        m = fmaxf(m, l[a]);
    }
#pragma unroll
    for (int off = 4; off > 0; off >>= 1)
        m = fmaxf(m, __shfl_xor_sync(0xFFFFFFFFu, m, off, 8));

    float sum = 0.0f;
#pragma unroll
    for (int a = 0; a < 8; a++) {
        l[a] = expf(l[a] - m);
        sum += l[a];
    }
#pragma unroll
    for (int off = 4; off > 0; off >>= 1)
        sum += __shfl_xor_sync(0xFFFFFFFFu, sum, off, 8);

    float inv = 1.0f / sum;
    int row = row0 + r;
#pragma unroll
    for (int a = 0; a < 8; a++)
        out[(size_t)row * 64 + ag * 8 + a] = l[a] * inv;
    if (ag == 0)
        out[(size_t)BATCH * 64 + row] = vacc + bv[0];
}

// ---------------------------------------------------------------------------
extern "C" void kernel_launch(void* const* d_in, const int* in_sizes, int n_in,
                              void* d_out, int out_size) {
    const float* s      = (const float*)d_in[0];
    const float* a_prev = (const float*)d_in[1];
    const float* r_prev = (const float*)d_in[2];
    const float* h      = (const float*)d_in[3];
    const float* c      = (const float*)d_in[4];
    const float* Wx     = (const float*)d_in[5];
    const float* Wh     = (const float*)d_in[6];
    const float* bh     = (const float*)d_in[7];
    const float* Wa     = (const float*)d_in[8];
    const float* ba     = (const float*)d_in[9];
    const float* Wv     = (const float*)d_in[10];
    const float* bv     = (const float*)d_in[11];
    float* out = (float*)d_out;

    static bool attr_set = false;
    if (!attr_set) {
        cudaFuncSetAttribute(lstm_mma, cudaFuncAttributeMaxDynamicSharedMemorySize, SMEM_SZ);
        attr_set = true;
    }

    convX<<<(BATCH * KP + 255) / 256, 256>>>(s, a_prev, r_prev);
    convW<<<dim3(FOURH / 32, KP / 64), dim3(32, 8)>>>(Wx);
    vb_partial<<<dim3(FOURH / 256, 8), 256>>>(h, Wh);
    vb_reduce<<<FOURH / 256, 256>>>(bh);
    lstm_mma<<<dim3(HDIM / 32, BATCH / 256), 512, SMEM_SZ>>>(c);
    heads_kernel<<<BATCH / 32, 256>>>(Wa, ba, Wv, bv, out);
}

// round 6
// speedup vs baseline: 2.7722x; 1.2245x over previous
#include <cuda_runtime.h>
#include <cuda_fp16.h>
#include <math.h>
#include <cstdint>

#define BATCH 4096
#define SDIM  512
#define ADIM  64
#define HDIM  2048
#define KDIM  577
#define KP    576           // s(512) + a(64); reward column handled rank-1 in epilogue
#define NCH   9
#define FOURH 8192

// ---------------- scratch (static device globals) ----------------
__device__ __half g_x[BATCH * KP];      // fp16 packed [s|a]
__device__ __half g_w[FOURH * KP];      // gate-interleaved rows n' = j*4 + g, K-major
__device__ float g_vb[FOURH];
__device__ float g_vbp[8 * FOURH];
__device__ float g_hn[BATCH * HDIM];

__device__ __forceinline__ uint32_t smem_u32(const void* p) {
    uint32_t a;
    asm("{ .reg .u64 t; cvta.to.shared.u64 t, %1; cvt.u32.u64 %0, t; }" : "=r"(a) : "l"(p));
    return a;
}
#define SWZ128(off) ((off) ^ (((off) >> 3) & 0x70))

__device__ __forceinline__ void cpa16(uint32_t smem, const void* g) {
    asm volatile("cp.async.cg.shared.global [%0], [%1], 16;" :: "r"(smem), "l"(g));
}
#define CPA_COMMIT()  asm volatile("cp.async.commit_group;" ::: "memory")
#define CPA_WAIT(n)   asm volatile("cp.async.wait_group %0;" :: "n"(n) : "memory")

__device__ __forceinline__ void ldmx4(uint32_t* r, uint32_t addr) {
    asm volatile("ldmatrix.sync.aligned.m8n8.x4.shared.b16 {%0,%1,%2,%3}, [%4];"
                 : "=r"(r[0]), "=r"(r[1]), "=r"(r[2]), "=r"(r[3]) : "r"(addr));
}
__device__ __forceinline__ void ldmx2(uint32_t* r, uint32_t addr) {
    asm volatile("ldmatrix.sync.aligned.m8n8.x2.shared.b16 {%0,%1}, [%2];"
                 : "=r"(r[0]), "=r"(r[1]) : "r"(addr));
}
__device__ __forceinline__ void mma16816(float* c, const uint32_t* a, const uint32_t* b) {
    asm volatile(
        "mma.sync.aligned.m16n8k16.row.col.f32.f16.f16.f32 "
        "{%0,%1,%2,%3}, {%4,%5,%6,%7}, {%8,%9}, {%0,%1,%2,%3};"
        : "+f"(c[0]), "+f"(c[1]), "+f"(c[2]), "+f"(c[3])
        : "r"(a[0]), "r"(a[1]), "r"(a[2]), "r"(a[3]), "r"(b[0]), "r"(b[1]));
}

// ---------------------------------------------------------------------------
// 1) convX: pack [s|a] -> fp16 [BATCH x 576] (exactly, no padding)
// ---------------------------------------------------------------------------
__global__ void convX(const float* __restrict__ s, const float* __restrict__ a) {
    int idx = blockIdx.x * 256 + threadIdx.x;
    if (idx >= BATCH * KP) return;
    int b = idx / KP;
    int k = idx - b * KP;
    float v = (k < SDIM) ? s[b * SDIM + k] : a[b * ADIM + (k - SDIM)];
    g_x[idx] = __float2half_rn(v);
}

// ---------------------------------------------------------------------------
// 2) convW: Wx rows 0..575 -> K-major fp16, gate-interleaved n' = (n&2047)*4 + (n>>11)
// ---------------------------------------------------------------------------
__global__ void convW(const float* __restrict__ Wx) {
    __shared__ float t[64][33];
    int n0 = blockIdx.x * 32;
    int k0 = blockIdx.y * 64;
    int tx = threadIdx.x, ty = threadIdx.y;       // (32, 8)
#pragma unroll
    for (int i = 0; i < 8; i++) {
        int kl = ty * 8 + i;
        t[kl][tx] = Wx[(size_t)(k0 + kl) * FOURH + n0 + tx];
    }
    __syncthreads();
    int tid = ty * 32 + tx;
    int nl  = tid >> 3;
    int ch  = tid & 7;
    int n   = n0 + nl;
    size_t np = (size_t)(n & 2047) * 4 + (n >> 11);
    uint4 vh;
    __half* ph = (__half*)&vh;
#pragma unroll
    for (int u = 0; u < 8; u++)
        ph[u] = __float2half_rn(t[ch * 8 + u][nl]);
    *(uint4*)&g_w[np * KP + k0 + ch * 8] = vh;
}

// ---------------------------------------------------------------------------
// 3+4) vb = bh + h @ Wh (fp32 exact)
// ---------------------------------------------------------------------------
__global__ void vb_partial(const float* __restrict__ h, const float* __restrict__ Wh) {
    int j  = blockIdx.x * 256 + threadIdx.x;
    int k0 = blockIdx.y * 256;
    float acc = 0.0f;
#pragma unroll 8
    for (int k = 0; k < 256; k++)
        acc += h[k0 + k] * Wh[(size_t)(k0 + k) * FOURH + j];
    g_vbp[blockIdx.y * FOURH + j] = acc;
}
__global__ void vb_reduce(const float* __restrict__ bh) {
    int j = blockIdx.x * 256 + threadIdx.x;
    float acc = bh[j];
#pragma unroll
    for (int kc = 0; kc < 8; kc++) acc += g_vbp[kc * FOURH + j];
    g_vb[j] = acc;
}

// ---------------------------------------------------------------------------
// 5) HMMA GEMM + LSTM gate epilogue.
//    CTA: 256 rows x 128 cols (32 hidden x 4 gates), 512 threads, 16 warps 4x4.
//    Single fp16 term; reward rank-1 term + vb added exactly in fp32 epilogue.
// ---------------------------------------------------------------------------
#define ST_A   0
#define ST_B   32768
#define ST_STRIDE 49152
#define PIPE_SZ (2 * ST_STRIDE)
#define EPI_SZ  (256 * 33 * 4)
#define SMEM_SZ (EPI_SZ > PIPE_SZ ? EPI_SZ : PIPE_SZ)

__device__ __forceinline__ void load_stage(uint32_t sb, int stage, int kg,
                                           int row0, int j0, int tid) {
    uint32_t base = sb + stage * ST_STRIDE;
    // A: 256 rows x 64 halfs = 2048 x 16B
#pragma unroll
    for (int i = 0; i < 4; i++) {
        int slot = tid + i * 512;
        int r = slot >> 3, ch = slot & 7;
        uint32_t sw = SWZ128((uint32_t)(r * 128 + ch * 16));
        cpa16(base + ST_A + sw, g_x + (size_t)(row0 + r) * KP + kg + ch * 8);
    }
    // B: 128 rows x 64 halfs = 1024 x 16B
#pragma unroll
    for (int i = 0; i < 2; i++) {
        int slot = tid + i * 512;
        int r = slot >> 3, ch = slot & 7;
        uint32_t sw = SWZ128((uint32_t)(r * 128 + ch * 16));
        cpa16(base + ST_B + sw, g_w + (size_t)(j0 * 4 + r) * KP + kg + ch * 8);
    }
}

__global__ __launch_bounds__(512, 1) void lstm_mma(const float* __restrict__ cvec,
                                                   const float* __restrict__ rp,
                                                   const float* __restrict__ w576) {
    extern __shared__ char smem[];
    uint32_t sb = smem_u32(smem);
    int tid  = threadIdx.x;
    int lane = tid & 31, w = tid >> 5;
    int wm = w & 3, wn = w >> 2;          // 4 x 4 warp grid
    int row0 = blockIdx.y * 256;
    int j0   = blockIdx.x * 32;

    int lr = lane & 7, ls = lane >> 3;
    uint32_t a_row = wm * 64 + lr + (ls & 1) * 8;   // + mt*16
    uint32_t a_chs = (uint32_t)(ls >> 1);           // + kb
    uint32_t b_row = wn * 32 + lr;                  // + nt*8
    uint32_t b_chs = (uint32_t)(ls & 1);            // + kb

    float acc[4][4][4];
#pragma unroll
    for (int mt = 0; mt < 4; mt++)
#pragma unroll
        for (int nt = 0; nt < 4; nt++)
#pragma unroll
            for (int i = 0; i < 4; i++) acc[mt][nt][i] = 0.0f;

    load_stage(sb, 0, 0, row0, j0, tid);
    CPA_COMMIT();

    for (int t = 0; t < NCH; t++) {
        int cur = t & 1;
        if (t + 1 < NCH) {
            load_stage(sb, cur ^ 1, (t + 1) * 64, row0, j0, tid);
            CPA_COMMIT();
            CPA_WAIT(1);
        } else {
            CPA_WAIT(0);
        }
        __syncthreads();

        uint32_t sa = sb + cur * ST_STRIDE;
#pragma unroll
        for (int kb = 0; kb < 8; kb += 2) {          // 4 k16 steps
            uint32_t bb[4][2];
#pragma unroll
            for (int nt = 0; nt < 4; nt++) {
                uint32_t off = SWZ128((b_row + nt * 8) * 128 + (kb + b_chs) * 16);
                ldmx2(bb[nt], sa + ST_B + off);
            }
#pragma unroll
            for (int mt = 0; mt < 4; mt++) {
                uint32_t aa[4];
                uint32_t off = SWZ128((a_row + mt * 16) * 128 + (kb + a_chs) * 16);
                ldmx4(aa, sa + ST_A + off);
#pragma unroll
                for (int nt = 0; nt < 4; nt++)
                    mma16816(acc[mt][nt], aa, bb[nt]);
            }
        }
        __syncthreads();
    }

    // ---- epilogue: + vb + r*w576 (exact fp32), gate math ----
    int q = lane & 3;
    int gp = q & 1;            // 0: lane holds (zi,zf); 1: (zg,zo)
    int jsel = q >> 1;
    float* hsm = (float*)smem; // [256][33] overlay

#pragma unroll
    for (int nt = 0; nt < 4; nt++) {
        int j = j0 + wn * 8 + nt * 2 + jsel;
        float vbi = __ldg(&g_vb[j]);
        float vbf = __ldg(&g_vb[HDIM + j]);
        float vbg = __ldg(&g_vb[2 * HDIM + j]);
        float vbo = __ldg(&g_vb[3 * HDIM + j]);
        float w5i = __ldg(&w576[j]);
        float w5f = __ldg(&w576[HDIM + j]);
        float w5g = __ldg(&w576[2 * HDIM + j]);
        float w5o = __ldg(&w576[3 * HDIM + j]);
        float cj  = __ldg(&cvec[j]);
#pragma unroll
        for (int mt = 0; mt < 4; mt++) {
            int rw = wm * 64 + mt * 16 + (lane >> 2);
            float r0 = __ldg(&rp[row0 + rw]);
            float r1 = __ldg(&rp[row0 + rw + 8]);

            float v0 = acc[mt][nt][0], v1 = acc[mt][nt][1];
            float v2 = acc[mt][nt][2], v3 = acc[mt][nt][3];
            float p0 = __shfl_xor_sync(0xFFFFFFFFu, v0, 1);
            float p1 = __shfl_xor_sync(0xFFFFFFFFu, v1, 1);
            float p2 = __shfl_xor_sync(0xFFFFFFFFu, v2, 1);
            float p3 = __shfl_xor_sync(0xFFFFFFFFu, v3, 1);
            float zi0 = gp ? p0 : v0, zf0 = gp ? p1 : v1;
            float zg0 = gp ? v0 : p0, zo0 = gp ? v1 : p1;
            float zi1 = gp ? p2 : v2, zf1 = gp ? p3 : v3;
            float zg1 = gp ? v2 : p2, zo1 = gp ? v3 : p3;

            zi0 += vbi + r0 * w5i; zf0 += vbf + r0 * w5f;
            zg0 += vbg + r0 * w5g; zo0 += vbo + r0 * w5o;
            zi1 += vbi + r1 * w5i; zf1 += vbf + r1 * w5f;
            zg1 += vbg + r1 * w5g; zo1 += vbo + r1 * w5o;

            float i0 = 1.0f / (1.0f + __expf(-zi0));
            float f0 = 1.0f / (1.0f + __expf(-zf0));
            float o0 = 1.0f / (1.0f + __expf(-zo0));
            float c0 = f0 * cj + i0 * tanhf(zg0);
            float h0 = o0 * tanhf(c0);
            float i1 = 1.0f / (1.0f + __expf(-zi1));
            float f1 = 1.0f / (1.0f + __expf(-zf1));
            float o1 = 1.0f / (1.0f + __expf(-zo1));
            float c1 = f1 * cj + i1 * tanhf(zg1);
            float h1 = o1 * tanhf(c1);

            if (gp == 0) {
                int jl = wn * 8 + nt * 2 + jsel;
                hsm[rw * 33 + jl]       = h0;
                hsm[(rw + 8) * 33 + jl] = h1;
            }
        }
    }
    __syncthreads();

#pragma unroll
    for (int i = 0; i < 16; i++) {
        int idx = tid + i * 512;
        int rw = idx >> 5, cl = idx & 31;
        g_hn[(size_t)(row0 + rw) * HDIM + j0 + cl] = hsm[rw * 33 + cl];
    }
}

// ---------------------------------------------------------------------------
// 6) heads: softmax(h @ Wa + ba), v = h @ Wv + bv
// ---------------------------------------------------------------------------
__global__ __launch_bounds__(256) void heads_kernel(const float* __restrict__ Wa,
                                                    const float* __restrict__ ba,
                                                    const float* __restrict__ Wv,
                                                    const float* __restrict__ bv,
                                                    float* __restrict__ out) {
    __shared__ float hs[32][64];
    __shared__ float was[64][64];
    __shared__ float wvs[64];

    int tid  = threadIdx.x;
    int r    = tid >> 3;
    int ag   = tid & 7;
    int row0 = blockIdx.x * 32;

    float acc[8];
#pragma unroll
    for (int a = 0; a < 8; a++) acc[a] = 0.0f;
    float vacc = 0.0f;

    for (int k0 = 0; k0 < HDIM; k0 += 64) {
#pragma unroll
        for (int i = 0; i < 2; i++) {
            int slot = tid + i * 256;
            int rr = slot >> 4, kk4 = (slot & 15) * 4;
            *(float4*)&hs[rr][kk4] =
                *(const float4*)&g_hn[(size_t)(row0 + rr) * HDIM + k0 + kk4];
        }
#pragma unroll
        for (int i = 0; i < 4; i++) {
            int slot = tid + i * 256;
            int kk = slot >> 4, a4 = (slot & 15) * 4;
            *(float4*)&was[kk][a4] = *(const float4*)&Wa[(size_t)(k0 + kk) * 64 + a4];
        }
        if (tid < 64) wvs[tid] = Wv[k0 + tid];
        __syncthreads();

#pragma unroll 8
        for (int kk = 0; kk < 64; kk++) {
            float h = hs[r][kk];
            vacc += h * wvs[kk];
#pragma unroll
            for (int a = 0; a < 8; a++)
                acc[a] += h * was[kk][ag * 8 + a];
        }
        __syncthreads();
    }

    float l[8];
    float m = -INFINITY;
#pragma unroll
    for (int a = 0; a < 8; a++) {
        l[a] = acc[a] + ba[ag * 8 + a];
        m = fmaxf(m, l[a]);
    }
#pragma unroll
    for (int off = 4; off > 0; off >>= 1)
        m = fmaxf(m, __shfl_xor_sync(0xFFFFFFFFu, m, off, 8));

    float sum = 0.0f;
#pragma unroll
    for (int a = 0; a < 8; a++) {
        l[a] = expf(l[a] - m);
        sum += l[a];
    }
#pragma unroll
    for (int off = 4; off > 0; off >>= 1)
        sum += __shfl_xor_sync(0xFFFFFFFFu, sum, off, 8);

    float inv = 1.0f / sum;
    int row = row0 + r;
#pragma unroll
    for (int a = 0; a < 8; a++)
        out[(size_t)row * 64 + ag * 8 + a] = l[a] * inv;
    if (ag == 0)
        out[(size_t)BATCH * 64 + row] = vacc + bv[0];
}

// ---------------------------------------------------------------------------
extern "C" void kernel_launch(void* const* d_in, const int* in_sizes, int n_in,
                              void* d_out, int out_size) {
    const float* s      = (const float*)d_in[0];
    const float* a_prev = (const float*)d_in[1];
    const float* r_prev = (const float*)d_in[2];
    const float* h      = (const float*)d_in[3];
    const float* c      = (const float*)d_in[4];
    const float* Wx     = (const float*)d_in[5];
    const float* Wh     = (const float*)d_in[6];
    const float* bh     = (const float*)d_in[7];
    const float* Wa     = (const float*)d_in[8];
    const float* ba     = (const float*)d_in[9];
    const float* Wv     = (const float*)d_in[10];
    const float* bv     = (const float*)d_in[11];
    float* out = (float*)d_out;

    static bool attr_set = false;
    if (!attr_set) {
        cudaFuncSetAttribute(lstm_mma, cudaFuncAttributeMaxDynamicSharedMemorySize, SMEM_SZ);
        attr_set = true;
    }

    convX<<<(BATCH * KP + 255) / 256, 256>>>(s, a_prev);
    convW<<<dim3(FOURH / 32, KP / 64), dim3(32, 8)>>>(Wx);
    vb_partial<<<dim3(FOURH / 256, 8), 256>>>(h, Wh);
    vb_reduce<<<FOURH / 256, 256>>>(bh);
    lstm_mma<<<dim3(HDIM / 32, BATCH / 256), 512, SMEM_SZ>>>(
        c, r_prev, Wx + (size_t)(KDIM - 1) * FOURH);
    heads_kernel<<<BATCH / 32, 256>>>(Wa, ba, Wv, bv, out);
}

// round 7
// speedup vs baseline: 2.8557x; 1.0301x over previous
#include <cuda_runtime.h>
#include <cuda_fp16.h>
#include <math.h>
#include <cstdint>

#define BATCH 4096
#define SDIM  512
#define ADIM  64
#define HDIM  2048
#define KDIM  577
#define KP    576           // s(512) + a(64); reward column folded rank-1 in epilogue
#define NCH   9
#define FOURH 8192

// ---------------- scratch (static device globals) ----------------
__device__ __half g_x[BATCH * KP];      // fp16 packed [s|a]
__device__ __half g_w[FOURH * KP];      // gate-interleaved rows n' = j*4 + g, K-major
__device__ float g_vb[FOURH];
__device__ float g_vbp[8 * FOURH];
__device__ float g_hn[BATCH * HDIM];

__device__ __forceinline__ uint32_t smem_u32(const void* p) {
    uint32_t a;
    asm("{ .reg .u64 t; cvta.to.shared.u64 t, %1; cvt.u32.u64 %0, t; }" : "=r"(a) : "l"(p));
    return a;
}
#define SWZ128(off) ((off) ^ (((off) >> 3) & 0x70))

__device__ __forceinline__ void cpa16(uint32_t smem, const void* g) {
    asm volatile("cp.async.cg.shared.global [%0], [%1], 16;" :: "r"(smem), "l"(g));
}
#define CPA_COMMIT()  asm volatile("cp.async.commit_group;" ::: "memory")
#define CPA_WAIT(n)   asm volatile("cp.async.wait_group %0;" :: "n"(n) : "memory")

__device__ __forceinline__ void ldmx4(uint32_t* r, uint32_t addr) {
    asm volatile("ldmatrix.sync.aligned.m8n8.x4.shared.b16 {%0,%1,%2,%3}, [%4];"
                 : "=r"(r[0]), "=r"(r[1]), "=r"(r[2]), "=r"(r[3]) : "r"(addr));
}
__device__ __forceinline__ void ldmx2(uint32_t* r, uint32_t addr) {
    asm volatile("ldmatrix.sync.aligned.m8n8.x2.shared.b16 {%0,%1}, [%2];"
                 : "=r"(r[0]), "=r"(r[1]) : "r"(addr));
}
__device__ __forceinline__ void mma16816(float* c, const uint32_t* a, const uint32_t* b) {
    asm volatile(
        "mma.sync.aligned.m16n8k16.row.col.f32.f16.f16.f32 "
        "{%0,%1,%2,%3}, {%4,%5,%6,%7}, {%8,%9}, {%0,%1,%2,%3};"
        : "+f"(c[0]), "+f"(c[1]), "+f"(c[2]), "+f"(c[3])
        : "r"(a[0]), "r"(a[1]), "r"(a[2]), "r"(a[3]), "r"(b[0]), "r"(b[1]));
}

// ---------------------------------------------------------------------------
// 1) convX: pack [s|a] -> fp16 [BATCH x 576]
// ---------------------------------------------------------------------------
__global__ void convX(const float* __restrict__ s, const float* __restrict__ a) {
    int idx = blockIdx.x * 256 + threadIdx.x;
    if (idx >= BATCH * KP) return;
    int b = idx / KP;
    int k = idx - b * KP;
    float v = (k < SDIM) ? s[b * SDIM + k] : a[b * ADIM + (k - SDIM)];
    g_x[idx] = __float2half_rn(v);
}

// ---------------------------------------------------------------------------
// 2) convW: Wx rows 0..575 -> K-major fp16, gate-interleaved n' = (n&2047)*4 + (n>>11)
// ---------------------------------------------------------------------------
__global__ void convW(const float* __restrict__ Wx) {
    __shared__ float t[64][33];
    int n0 = blockIdx.x * 32;
    int k0 = blockIdx.y * 64;
    int tx = threadIdx.x, ty = threadIdx.y;       // (32, 8)
#pragma unroll
    for (int i = 0; i < 8; i++) {
        int kl = ty * 8 + i;
        t[kl][tx] = Wx[(size_t)(k0 + kl) * FOURH + n0 + tx];
    }
    __syncthreads();
    int tid = ty * 32 + tx;
    int nl  = tid >> 3;
    int ch  = tid & 7;
    int n   = n0 + nl;
    size_t np = (size_t)(n & 2047) * 4 + (n >> 11);
    uint4 vh;
    __half* ph = (__half*)&vh;
#pragma unroll
    for (int u = 0; u < 8; u++)
        ph[u] = __float2half_rn(t[ch * 8 + u][nl]);
    *(uint4*)&g_w[np * KP + k0 + ch * 8] = vh;
}

// ---------------------------------------------------------------------------
// 3+4) vb = bh + h @ Wh (fp32 exact)
// ---------------------------------------------------------------------------
__global__ void vb_partial(const float* __restrict__ h, const float* __restrict__ Wh) {
    int j  = blockIdx.x * 256 + threadIdx.x;
    int k0 = blockIdx.y * 256;
    float acc = 0.0f;
#pragma unroll 8
    for (int k = 0; k < 256; k++)
        acc += h[k0 + k] * Wh[(size_t)(k0 + k) * FOURH + j];
    g_vbp[blockIdx.y * FOURH + j] = acc;
}
__global__ void vb_reduce(const float* __restrict__ bh) {
    int j = blockIdx.x * 256 + threadIdx.x;
    float acc = bh[j];
#pragma unroll
    for (int kc = 0; kc < 8; kc++) acc += g_vbp[kc * FOURH + j];
    g_vb[j] = acc;
}

// ---------------------------------------------------------------------------
// 5) HMMA GEMM + LSTM gate epilogue.
//    CTA: 128 rows x 128 cols (32 hidden x 4 gates), 256 threads, 8 warps 2x4.
//    3-stage cp.async ring, ONE __syncthreads per chunk, 2 CTAs/SM.
// ---------------------------------------------------------------------------
#define ST_A   0
#define ST_B   16384
#define ST_STRIDE 32768
#define PIPE_SZ (3 * ST_STRIDE)
#define EPI_SZ  (128 * 33 * 4)
#define SMEM_SZ (EPI_SZ > PIPE_SZ ? EPI_SZ : PIPE_SZ)

__device__ __forceinline__ void load_stage(uint32_t sb, int stage, int kg,
                                           int row0, int j0, int tid) {
    uint32_t base = sb + stage * ST_STRIDE;
    // A: 128 rows x 64 halfs = 1024 x 16B
#pragma unroll
    for (int i = 0; i < 4; i++) {
        int slot = tid + i * 256;
        int r = slot >> 3, ch = slot & 7;
        uint32_t sw = SWZ128((uint32_t)(r * 128 + ch * 16));
        cpa16(base + ST_A + sw, g_x + (size_t)(row0 + r) * KP + kg + ch * 8);
    }
    // B: 128 rows x 64 halfs = 1024 x 16B
#pragma unroll
    for (int i = 0; i < 4; i++) {
        int slot = tid + i * 256;
        int r = slot >> 3, ch = slot & 7;
        uint32_t sw = SWZ128((uint32_t)(r * 128 + ch * 16));
        cpa16(base + ST_B + sw, g_w + (size_t)(j0 * 4 + r) * KP + kg + ch * 8);
    }
}

__global__ __launch_bounds__(256, 2) void lstm_mma(const float* __restrict__ cvec,
                                                   const float* __restrict__ rp,
                                                   const float* __restrict__ w576) {
    extern __shared__ char smem[];
    uint32_t sb = smem_u32(smem);
    int tid  = threadIdx.x;
    int lane = tid & 31, w = tid >> 5;
    int wm = w & 1, wn = w >> 1;          // 2 x 4 warp grid
    int row0 = blockIdx.y * 128;
    int j0   = blockIdx.x * 32;

    int lr = lane & 7, ls = lane >> 3;
    uint32_t a_row = wm * 64 + lr + (ls & 1) * 8;   // + mt*16
    uint32_t a_chs = (uint32_t)(ls >> 1);           // + kb
    uint32_t b_row = wn * 32 + lr;                  // + nt*8
    uint32_t b_chs = (uint32_t)(ls & 1);            // + kb

    float acc[4][4][4];
#pragma unroll
    for (int mt = 0; mt < 4; mt++)
#pragma unroll
        for (int nt = 0; nt < 4; nt++)
#pragma unroll
            for (int i = 0; i < 4; i++) acc[mt][nt][i] = 0.0f;

    load_stage(sb, 0, 0, row0, j0, tid);
    CPA_COMMIT();
    load_stage(sb, 1, 64, row0, j0, tid);
    CPA_COMMIT();

    for (int t = 0; t < NCH; t++) {
        if (t == NCH - 1) { CPA_WAIT(0); } else { CPA_WAIT(1); }
        __syncthreads();   // chunk t ready; all warps done computing chunk t-1

        if (t + 2 < NCH) {
            load_stage(sb, (t + 2) % 3, (t + 2) * 64, row0, j0, tid);
            CPA_COMMIT();
        }

        uint32_t sa = sb + (t % 3) * ST_STRIDE;
#pragma unroll
        for (int kb = 0; kb < 8; kb += 2) {          // 4 k16 steps
            uint32_t bb[4][2];
#pragma unroll
            for (int nt = 0; nt < 4; nt++) {
                uint32_t off = SWZ128((b_row + nt * 8) * 128 + (kb + b_chs) * 16);
                ldmx2(bb[nt], sa + ST_B + off);
            }
#pragma unroll
            for (int mt = 0; mt < 4; mt++) {
                uint32_t aa[4];
                uint32_t off = SWZ128((a_row + mt * 16) * 128 + (kb + a_chs) * 16);
                ldmx4(aa, sa + ST_A + off);
#pragma unroll
                for (int nt = 0; nt < 4; nt++)
                    mma16816(acc[mt][nt], aa, bb[nt]);
            }
        }
    }
    __syncthreads();   // mainloop done before smem reuse

    // ---- epilogue: + vb + r*w576 (exact fp32), gate math ----
    int q = lane & 3;
    int gp = q & 1;            // 0: lane holds (zi,zf); 1: (zg,zo)
    int jsel = q >> 1;
    float* hsm = (float*)smem; // [128][33] overlay

#pragma unroll
    for (int nt = 0; nt < 4; nt++) {
        int j = j0 + wn * 8 + nt * 2 + jsel;
        float vbi = __ldg(&g_vb[j]);
        float vbf = __ldg(&g_vb[HDIM + j]);
        float vbg = __ldg(&g_vb[2 * HDIM + j]);
        float vbo = __ldg(&g_vb[3 * HDIM + j]);
        float w5i = __ldg(&w576[j]);
        float w5f = __ldg(&w576[HDIM + j]);
        float w5g = __ldg(&w576[2 * HDIM + j]);
        float w5o = __ldg(&w576[3 * HDIM + j]);
        float cj  = __ldg(&cvec[j]);
#pragma unroll
        for (int mt = 0; mt < 4; mt++) {
            int rw = wm * 64 + mt * 16 + (lane >> 2);
            float r0 = __ldg(&rp[row0 + rw]);
            float r1 = __ldg(&rp[row0 + rw + 8]);

            float v0 = acc[mt][nt][0], v1 = acc[mt][nt][1];
            float v2 = acc[mt][nt][2], v3 = acc[mt][nt][3];
            float p0 = __shfl_xor_sync(0xFFFFFFFFu, v0, 1);
            float p1 = __shfl_xor_sync(0xFFFFFFFFu, v1, 1);
            float p2 = __shfl_xor_sync(0xFFFFFFFFu, v2, 1);
            float p3 = __shfl_xor_sync(0xFFFFFFFFu, v3, 1);
            float zi0 = gp ? p0 : v0, zf0 = gp ? p1 : v1;
            float zg0 = gp ? v0 : p0, zo0 = gp ? v1 : p1;
            float zi1 = gp ? p2 : v2, zf1 = gp ? p3 : v3;
            float zg1 = gp ? v2 : p2, zo1 = gp ? v3 : p3;

            zi0 += vbi + r0 * w5i; zf0 += vbf + r0 * w5f;
            zg0 += vbg + r0 * w5g; zo0 += vbo + r0 * w5o;
            zi1 += vbi + r1 * w5i; zf1 += vbf + r1 * w5f;
            zg1 += vbg + r1 * w5g; zo1 += vbo + r1 * w5o;

            float i0 = 1.0f / (1.0f + __expf(-zi0));
            float f0 = 1.0f / (1.0f + __expf(-zf0));
            float o0 = 1.0f / (1.0f + __expf(-zo0));
            float c0 = f0 * cj + i0 * tanhf(zg0);
            float h0 = o0 * tanhf(c0);
            float i1 = 1.0f / (1.0f + __expf(-zi1));
            float f1 = 1.0f / (1.0f + __expf(-zf1));
            float o1 = 1.0f / (1.0f + __expf(-zo1));
            float c1 = f1 * cj + i1 * tanhf(zg1);
            float h1 = o1 * tanhf(c1);

            if (gp == 0) {
                int jl = wn * 8 + nt * 2 + jsel;
                hsm[rw * 33 + jl]       = h0;
                hsm[(rw + 8) * 33 + jl] = h1;
            }
        }
    }
    __syncthreads();

#pragma unroll
    for (int i = 0; i < 16; i++) {
        int idx = tid + i * 256;
        int rw = idx >> 5, cl = idx & 31;
        g_hn[(size_t)(row0 + rw) * HDIM + j0 + cl] = hsm[rw * 33 + cl];
    }
}

// ---------------------------------------------------------------------------
// 6) heads: softmax(h @ Wa + ba), v = h @ Wv + bv
// ---------------------------------------------------------------------------
__global__ __launch_bounds__(256) void heads_kernel(const float* __restrict__ Wa,
                                                    const float* __restrict__ ba,
                                                    const float* __restrict__ Wv,
                                                    const float* __restrict__ bv,
                                                    float* __restrict__ out) {
    __shared__ float hs[32][64];
    __shared__ float was[64][64];
    __shared__ float wvs[64];

    int tid  = threadIdx.x;
    int r    = tid >> 3;
    int ag   = tid & 7;
    int row0 = blockIdx.x * 32;

    float acc[8];
#pragma unroll
    for (int a = 0; a < 8; a++) acc[a] = 0.0f;
    float vacc = 0.0f;

    for (int k0 = 0; k0 < HDIM; k0 += 64) {
#pragma unroll
        for (int i = 0; i < 2; i++) {
            int slot = tid + i * 256;
            int rr = slot >> 4, kk4 = (slot & 15) * 4;
            *(float4*)&hs[rr][kk4] =
                *(const float4*)&g_hn[(size_t)(row0 + rr) * HDIM + k0 + kk4];
        }
#pragma unroll
        for (int i = 0; i < 4; i++) {
            int slot = tid + i * 256;
            int kk = slot >> 4, a4 = (slot & 15) * 4;
            *(float4*)&was[kk][a4] = *(const float4*)&Wa[(size_t)(k0 + kk) * 64 + a4];
        }
        if (tid < 64) wvs[tid] = Wv[k0 + tid];
        __syncthreads();

#pragma unroll 8
        for (int kk = 0; kk < 64; kk++) {
            float h = hs[r][kk];
            vacc += h * wvs[kk];
#pragma unroll
            for (int a = 0; a < 8; a++)
                acc[a] += h * was[kk][ag * 8 + a];
        }
        __syncthreads();
    }

    float l[8];
    float m = -INFINITY;
#pragma unroll
    for (int a = 0; a < 8; a++) {
        l[a] = acc[a] + ba[ag * 8 + a];
        m = fmaxf(m, l[a]);
    }
#pragma unroll
    for (int off = 4; off > 0; off >>= 1)
        m = fmaxf(m, __shfl_xor_sync(0xFFFFFFFFu, m, off, 8));

    float sum = 0.0f;
#pragma unroll
    for (int a = 0; a < 8; a++) {
        l[a] = expf(l[a] - m);
        sum += l[a];
    }
#pragma unroll
    for (int off = 4; off > 0; off >>= 1)
        sum += __shfl_xor_sync(0xFFFFFFFFu, sum, off, 8);

    float inv = 1.0f / sum;
    int row = row0 + r;
#pragma unroll
    for (int a = 0; a < 8; a++)
        out[(size_t)row * 64 + ag * 8 + a] = l[a] * inv;
    if (ag == 0)
        out[(size_t)BATCH * 64 + row] = vacc + bv[0];
}

// ---------------------------------------------------------------------------
extern "C" void kernel_launch(void* const* d_in, const int* in_sizes, int n_in,
                              void* d_out, int out_size) {
    const float* s      = (const float*)d_in[0];
    const float* a_prev = (const float*)d_in[1];
    const float* r_prev = (const float*)d_in[2];
    const float* h      = (const float*)d_in[3];
    const float* c      = (const float*)d_in[4];
    const float* Wx     = (const float*)d_in[5];
    const float* Wh     = (const float*)d_in[6];
    const float* bh     = (const float*)d_in[7];
    const float* Wa     = (const float*)d_in[8];
    const float* ba     = (const float*)d_in[9];
    const float* Wv     = (const float*)d_in[10];
    const float* bv     = (const float*)d_in[11];
    float* out = (float*)d_out;

    static bool attr_set = false;
    if (!attr_set) {
        cudaFuncSetAttribute(lstm_mma, cudaFuncAttributeMaxDynamicSharedMemorySize, SMEM_SZ);
        attr_set = true;
    }

    convX<<<(BATCH * KP + 255) / 256, 256>>>(s, a_prev);
    convW<<<dim3(FOURH / 32, KP / 64), dim3(32, 8)>>>(Wx);
    vb_partial<<<dim3(FOURH / 256, 8), 256>>>(h, Wh);
    vb_reduce<<<FOURH / 256, 256>>>(bh);
    lstm_mma<<<dim3(HDIM / 32, BATCH / 128), 256, SMEM_SZ>>>(
        c, r_prev, Wx + (size_t)(KDIM - 1) * FOURH);
    heads_kernel<<<BATCH / 32, 256>>>(Wa, ba, Wv, bv, out);
}

// round 8
// speedup vs baseline: 2.9480x; 1.0323x over previous
#include <cuda_runtime.h>
#include <cuda_fp16.h>
#include <math.h>
#include <cstdint>

#define BATCH 4096
#define SDIM  512
#define ADIM  64
#define HDIM  2048
#define KDIM  577
#define KP    576           // s(512) + a(64); reward column folded rank-1 in epilogue
#define NCH   9
#define FOURH 8192

// ---------------- scratch (static device globals) ----------------
__device__ __half g_x[BATCH * KP];      // fp16 packed [s|a]
__device__ __half g_w[FOURH * KP];      // gate-interleaved rows n' = j*4 + g, K-major
__device__ float g_vbp[8 * FOURH];      // k-split partials of h @ Wh
__device__ float g_hn[BATCH * HDIM];

__device__ __forceinline__ uint32_t smem_u32(const void* p) {
    uint32_t a;
    asm("{ .reg .u64 t; cvta.to.shared.u64 t, %1; cvt.u32.u64 %0, t; }" : "=r"(a) : "l"(p));
    return a;
}
#define SWZ128(off) ((off) ^ (((off) >> 3) & 0x70))

__device__ __forceinline__ void cpa16(uint32_t smem, const void* g) {
    asm volatile("cp.async.cg.shared.global [%0], [%1], 16;" :: "r"(smem), "l"(g));
}
#define CPA_COMMIT()  asm volatile("cp.async.commit_group;" ::: "memory")
#define CPA_WAIT(n)   asm volatile("cp.async.wait_group %0;" :: "n"(n) : "memory")

__device__ __forceinline__ void ldmx4(uint32_t* r, uint32_t addr) {
    asm volatile("ldmatrix.sync.aligned.m8n8.x4.shared.b16 {%0,%1,%2,%3}, [%4];"
                 : "=r"(r[0]), "=r"(r[1]), "=r"(r[2]), "=r"(r[3]) : "r"(addr));
}
__device__ __forceinline__ void ldmx2(uint32_t* r, uint32_t addr) {
    asm volatile("ldmatrix.sync.aligned.m8n8.x2.shared.b16 {%0,%1}, [%2];"
                 : "=r"(r[0]), "=r"(r[1]) : "r"(addr));
}
__device__ __forceinline__ void mma16816(float* c, const uint32_t* a, const uint32_t* b) {
    asm volatile(
        "mma.sync.aligned.m16n8k16.row.col.f32.f16.f16.f32 "
        "{%0,%1,%2,%3}, {%4,%5,%6,%7}, {%8,%9}, {%0,%1,%2,%3};"
        : "+f"(c[0]), "+f"(c[1]), "+f"(c[2]), "+f"(c[3])
        : "r"(a[0]), "r"(a[1]), "r"(a[2]), "r"(a[3]), "r"(b[0]), "r"(b[1]));
}

// ---------------------------------------------------------------------------
// 1) convX: pack [s|a] -> fp16 [BATCH x 576]
// ---------------------------------------------------------------------------
__global__ void convX(const float* __restrict__ s, const float* __restrict__ a) {
    int idx = blockIdx.x * 256 + threadIdx.x;
    if (idx >= BATCH * KP) return;
    int b = idx / KP;
    int k = idx - b * KP;
    float v = (k < SDIM) ? s[b * SDIM + k] : a[b * ADIM + (k - SDIM)];
    g_x[idx] = __float2half_rn(v);
}

// ---------------------------------------------------------------------------
// 2) convW: Wx rows 0..575 -> K-major fp16, gate-interleaved n' = (n&2047)*4 + (n>>11)
// ---------------------------------------------------------------------------
__global__ void convW(const float* __restrict__ Wx) {
    __shared__ float t[64][33];
    int n0 = blockIdx.x * 32;
    int k0 = blockIdx.y * 64;
    int tx = threadIdx.x, ty = threadIdx.y;       // (32, 8)
#pragma unroll
    for (int i = 0; i < 8; i++) {
        int kl = ty * 8 + i;
        t[kl][tx] = Wx[(size_t)(k0 + kl) * FOURH + n0 + tx];
    }
    __syncthreads();
    int tid = ty * 32 + tx;
    int nl  = tid >> 3;
    int ch  = tid & 7;
    int n   = n0 + nl;
    size_t np = (size_t)(n & 2047) * 4 + (n >> 11);
    uint4 vh;
    __half* ph = (__half*)&vh;
#pragma unroll
    for (int u = 0; u < 8; u++)
        ph[u] = __float2half_rn(t[ch * 8 + u][nl]);
    *(uint4*)&g_w[np * KP + k0 + ch * 8] = vh;
}

// ---------------------------------------------------------------------------
// 3) vb partials: vbp[kc][j] = sum_{k in chunk kc} h[k] * Wh[k][j]
// ---------------------------------------------------------------------------
__global__ void vb_partial(const float* __restrict__ h, const float* __restrict__ Wh) {
    int j  = blockIdx.x * 256 + threadIdx.x;
    int k0 = blockIdx.y * 256;
    float acc = 0.0f;
#pragma unroll 8
    for (int k = 0; k < 256; k++)
        acc += h[k0 + k] * Wh[(size_t)(k0 + k) * FOURH + j];
    g_vbp[blockIdx.y * FOURH + j] = acc;
}

// ---------------------------------------------------------------------------
// 4) HMMA GEMM + LSTM gate epilogue. vb reduce fused into prologue.
//    CTA: 128 rows x 128 cols (32 hidden x 4 gates), 256 threads, 8 warps 2x4.
//    3-stage cp.async ring, one __syncthreads per chunk, 2 CTAs/SM.
// ---------------------------------------------------------------------------
#define ST_A   0
#define ST_B   16384
#define ST_STRIDE 32768
#define SVB_OFF  (3 * ST_STRIDE)
#define SMEM_SZ  (3 * ST_STRIDE + 512)

__device__ __forceinline__ void load_stage(uint32_t sb, int stage, int kg,
                                           int row0, int j0, int tid) {
    uint32_t base = sb + stage * ST_STRIDE;
#pragma unroll
    for (int i = 0; i < 4; i++) {
        int slot = tid + i * 256;
        int r = slot >> 3, ch = slot & 7;
        uint32_t sw = SWZ128((uint32_t)(r * 128 + ch * 16));
        cpa16(base + ST_A + sw, g_x + (size_t)(row0 + r) * KP + kg + ch * 8);
    }
#pragma unroll
    for (int i = 0; i < 4; i++) {
        int slot = tid + i * 256;
        int r = slot >> 3, ch = slot & 7;
        uint32_t sw = SWZ128((uint32_t)(r * 128 + ch * 16));
        cpa16(base + ST_B + sw, g_w + (size_t)(j0 * 4 + r) * KP + kg + ch * 8);
    }
}

__global__ __launch_bounds__(256, 2) void lstm_mma(const float* __restrict__ cvec,
                                                   const float* __restrict__ rp,
                                                   const float* __restrict__ w576,
                                                   const float* __restrict__ bh) {
    extern __shared__ char smem[];
    uint32_t sb = smem_u32(smem);
    int tid  = threadIdx.x;
    int lane = tid & 31, w = tid >> 5;
    int wm = w & 1, wn = w >> 1;          // 2 x 4 warp grid
    int row0 = blockIdx.y * 128;
    int j0   = blockIdx.x * 32;

    int lr = lane & 7, ls = lane >> 3;
    uint32_t a_row = wm * 64 + lr + (ls & 1) * 8;   // + mt*16
    uint32_t a_chs = (uint32_t)(ls >> 1);           // + kb
    uint32_t b_row = wn * 32 + lr;                  // + nt*8
    uint32_t b_chs = (uint32_t)(ls & 1);            // + kb

    float acc[4][4][4];
#pragma unroll
    for (int mt = 0; mt < 4; mt++)
#pragma unroll
        for (int nt = 0; nt < 4; nt++)
#pragma unroll
            for (int i = 0; i < 4; i++) acc[mt][nt][i] = 0.0f;

    load_stage(sb, 0, 0, row0, j0, tid);
    CPA_COMMIT();
    load_stage(sb, 1, 64, row0, j0, tid);
    CPA_COMMIT();

    // fused vb reduce: svb[g*32+jl] = bh + sum_kc vbp  (overlaps cp.async)
    float* svb = (float*)(smem + SVB_OFF);
    if (tid < 128) {
        int j = (tid >> 5) * HDIM + j0 + (tid & 31);
        float acc_vb = __ldg(&bh[j]);
#pragma unroll
        for (int kc = 0; kc < 8; kc++) acc_vb += g_vbp[kc * FOURH + j];
        svb[tid] = acc_vb;
    }

    for (int t = 0; t < NCH; t++) {
        if (t == NCH - 1) { CPA_WAIT(0); } else { CPA_WAIT(1); }
        __syncthreads();   // chunk t ready; all warps done with chunk t-1

        if (t + 2 < NCH) {
            load_stage(sb, (t + 2) % 3, (t + 2) * 64, row0, j0, tid);
            CPA_COMMIT();
        }

        uint32_t sa = sb + (t % 3) * ST_STRIDE;
#pragma unroll
        for (int kb = 0; kb < 8; kb += 2) {          // 4 k16 steps
            uint32_t bb[4][2];
#pragma unroll
            for (int nt = 0; nt < 4; nt++) {
                uint32_t off = SWZ128((b_row + nt * 8) * 128 + (kb + b_chs) * 16);
                ldmx2(bb[nt], sa + ST_B + off);
            }
#pragma unroll
            for (int mt = 0; mt < 4; mt++) {
                uint32_t aa[4];
                uint32_t off = SWZ128((a_row + mt * 16) * 128 + (kb + a_chs) * 16);
                ldmx4(aa, sa + ST_A + off);
#pragma unroll
                for (int nt = 0; nt < 4; nt++)
                    mma16816(acc[mt][nt], aa, bb[nt]);
            }
        }
    }
    __syncthreads();   // mainloop done before smem reuse (svb stays intact)

    // ---- epilogue: + vb + r*w576 (exact fp32), gate math ----
    int q = lane & 3;
    int gp = q & 1;            // 0: lane holds (zi,zf); 1: (zg,zo)
    int jsel = q >> 1;
    float* hsm = (float*)smem; // [128][33] overlay (pipe area only)

    float r0v[4], r1v[4];
#pragma unroll
    for (int mt = 0; mt < 4; mt++) {
        int rw = wm * 64 + mt * 16 + (lane >> 2);
        r0v[mt] = __ldg(&rp[row0 + rw]);
        r1v[mt] = __ldg(&rp[row0 + rw + 8]);
    }

#pragma unroll
    for (int nt = 0; nt < 4; nt++) {
        int jl = wn * 8 + nt * 2 + jsel;
        int j  = j0 + jl;
        float vbi = svb[jl];
        float vbf = svb[32 + jl];
        float vbg = svb[64 + jl];
        float vbo = svb[96 + jl];
        float w5i = __ldg(&w576[j]);
        float w5f = __ldg(&w576[HDIM + j]);
        float w5g = __ldg(&w576[2 * HDIM + j]);
        float w5o = __ldg(&w576[3 * HDIM + j]);
        float cj  = __ldg(&cvec[j]);
#pragma unroll
        for (int mt = 0; mt < 4; mt++) {
            float r0 = r0v[mt], r1 = r1v[mt];
            float v0 = acc[mt][nt][0], v1 = acc[mt][nt][1];
            float v2 = acc[mt][nt][2], v3 = acc[mt][nt][3];
            float p0 = __shfl_xor_sync(0xFFFFFFFFu, v0, 1);
            float p1 = __shfl_xor_sync(0xFFFFFFFFu, v1, 1);
            float p2 = __shfl_xor_sync(0xFFFFFFFFu, v2, 1);
            float p3 = __shfl_xor_sync(0xFFFFFFFFu, v3, 1);
            float zi0 = gp ? p0 : v0, zf0 = gp ? p1 : v1;
            float zg0 = gp ? v0 : p0, zo0 = gp ? v1 : p1;
            float zi1 = gp ? p2 : v2, zf1 = gp ? p3 : v3;
            float zg1 = gp ? v2 : p2, zo1 = gp ? v3 : p3;

            zi0 += vbi + r0 * w5i; zf0 += vbf + r0 * w5f;
            zg0 += vbg + r0 * w5g; zo0 += vbo + r0 * w5o;
            zi1 += vbi + r1 * w5i; zf1 += vbf + r1 * w5f;
            zg1 += vbg + r1 * w5g; zo1 += vbo + r1 * w5o;

            float i0 = 1.0f / (1.0f + __expf(-zi0));
            float f0 = 1.0f / (1.0f + __expf(-zf0));
            float o0 = 1.0f / (1.0f + __expf(-zo0));
            float c0 = f0 * cj + i0 * tanhf(zg0);
            float h0 = o0 * tanhf(c0);
            float i1 = 1.0f / (1.0f + __expf(-zi1));
            float f1 = 1.0f / (1.0f + __expf(-zf1));
            float o1 = 1.0f / (1.0f + __expf(-zo1));
            float c1 = f1 * cj + i1 * tanhf(zg1);
            float h1 = o1 * tanhf(c1);

            if (gp == 0) {
                int rw = wm * 64 + mt * 16 + (lane >> 2);
                hsm[rw * 33 + jl]       = h0;
                hsm[(rw + 8) * 33 + jl] = h1;
            }
        }
    }
    __syncthreads();

#pragma unroll
    for (int i = 0; i < 16; i++) {
        int idx = tid + i * 256;
        int rw = idx >> 5, cl = idx & 31;
        g_hn[(size_t)(row0 + rw) * HDIM + j0 + cl] = hsm[rw * 33 + cl];
    }
}

// ---------------------------------------------------------------------------
// 5) heads: softmax(h @ Wa + ba), v = h @ Wv + bv. Split-K: 512 threads,
//    thread (r, half, ag) covers k-half of 8 actions of row r; shfl combine.
// ---------------------------------------------------------------------------
__global__ __launch_bounds__(512) void heads_kernel(const float* __restrict__ Wa,
                                                    const float* __restrict__ ba,
                                                    const float* __restrict__ Wv,
                                                    const float* __restrict__ bv,
                                                    float* __restrict__ out) {
    __shared__ float hs[32][64];
    __shared__ float was[64][64];
    __shared__ float wvs[64];

    int tid  = threadIdx.x;
    int r    = tid >> 4;          // 0..31
    int half = (tid >> 3) & 1;    // k-half
    int ag   = tid & 7;           // action group
    int row0 = blockIdx.x * 32;

    float acc[8];
#pragma unroll
    for (int a = 0; a < 8; a++) acc[a] = 0.0f;
    float vacc = 0.0f;

    for (int k0 = 0; k0 < HDIM; k0 += 64) {
        // hs: 32x64 = 512 float4, 1 per thread
        {
            int rr = tid >> 4, kk4 = (tid & 15) * 4;
            *(float4*)&hs[rr][kk4] =
                *(const float4*)&g_hn[(size_t)(row0 + rr) * HDIM + k0 + kk4];
        }
        // was: 64x64 = 1024 float4, 2 per thread
#pragma unroll
        for (int i = 0; i < 2; i++) {
            int slot = tid + i * 512;
            int kk = slot >> 4, a4 = (slot & 15) * 4;
            *(float4*)&was[kk][a4] = *(const float4*)&Wa[(size_t)(k0 + kk) * 64 + a4];
        }
        if (tid < 64) wvs[tid] = Wv[k0 + tid];
        __syncthreads();

        int kb = half * 32;
#pragma unroll 8
        for (int kkl = 0; kkl < 32; kkl++) {
            int kk = kb + kkl;
            float h = hs[r][kk];
            vacc += h * wvs[kk];
#pragma unroll
            for (int a = 0; a < 8; a++)
                acc[a] += h * was[kk][ag * 8 + a];
        }
        __syncthreads();
    }

    // combine k-halves (partner = lane ^ 8)
#pragma unroll
    for (int a = 0; a < 8; a++)
        acc[a] += __shfl_xor_sync(0xFFFFFFFFu, acc[a], 8);
    vacc += __shfl_xor_sync(0xFFFFFFFFu, vacc, 8);

    float l[8];
    float m = -INFINITY;
#pragma unroll
    for (int a = 0; a < 8; a++) {
        l[a] = acc[a] + ba[ag * 8 + a];
        m = fmaxf(m, l[a]);
    }
#pragma unroll
    for (int off = 4; off > 0; off >>= 1)
        m = fmaxf(m, __shfl_xor_sync(0xFFFFFFFFu, m, off, 8));

    float sum = 0.0f;
#pragma unroll
    for (int a = 0; a < 8; a++) {
        l[a] = expf(l[a] - m);
        sum += l[a];
    }
#pragma unroll
    for (int off = 4; off > 0; off >>= 1)
        sum += __shfl_xor_sync(0xFFFFFFFFu, sum, off, 8);

    float inv = 1.0f / sum;
    int row = row0 + r;
    if (half == 0) {
#pragma unroll
        for (int a = 0; a < 8; a++)
            out[(size_t)row * 64 + ag * 8 + a] = l[a] * inv;
        if (ag == 0)
            out[(size_t)BATCH * 64 + row] = vacc + bv[0];
    }
}

// ---------------------------------------------------------------------------
extern "C" void kernel_launch(void* const* d_in, const int* in_sizes, int n_in,
                              void* d_out, int out_size) {
    const float* s      = (const float*)d_in[0];
    const float* a_prev = (const float*)d_in[1];
    const float* r_prev = (const float*)d_in[2];
    const float* h      = (const float*)d_in[3];
    const float* c      = (const float*)d_in[4];
    const float* Wx     = (const float*)d_in[5];
    const float* Wh     = (const float*)d_in[6];
    const float* bh     = (const float*)d_in[7];
    const float* Wa     = (const float*)d_in[8];
    const float* ba     = (const float*)d_in[9];
    const float* Wv     = (const float*)d_in[10];
    const float* bv     = (const float*)d_in[11];
    float* out = (float*)d_out;

    static bool attr_set = false;
    if (!attr_set) {
        cudaFuncSetAttribute(lstm_mma, cudaFuncAttributeMaxDynamicSharedMemorySize, SMEM_SZ);
        attr_set = true;
    }

    convX<<<(BATCH * KP + 255) / 256, 256>>>(s, a_prev);
    convW<<<dim3(FOURH / 32, KP / 64), dim3(32, 8)>>>(Wx);
    vb_partial<<<dim3(FOURH / 256, 8), 256>>>(h, Wh);
    lstm_mma<<<dim3(HDIM / 32, BATCH / 128), 256, SMEM_SZ>>>(
        c, r_prev, Wx + (size_t)(KDIM - 1) * FOURH, bh);
    heads_kernel<<<BATCH / 32, 512>>>(Wa, ba, Wv, bv, out);
}

// round 9
// speedup vs baseline: 4.9236x; 1.6702x over previous
#include <cuda_runtime.h>
#include <cuda_fp16.h>
#include <math.h>
#include <cstdint>

#define BATCH 4096
#define SDIM  512
#define ADIM  64
#define HDIM  2048
#define KDIM  577
#define KP    576           // s(512) + a(64); reward column folded rank-1 in epilogue
#define NCH   9
#define FOURH 8192

// ---------------- scratch (static device globals) ----------------
__device__ __half g_x[BATCH * KP];      // fp16 packed [s|a]
__device__ __half g_w[FOURH * KP];      // gate-interleaved rows n' = j*4 + g, K-major
__device__ __half g_wa[64 * HDIM];      // Wa transposed [n][k] K-major fp16
__device__ float g_vbp[8 * FOURH];      // k-split partials of h @ Wh
__device__ __half g_hf[BATCH * HDIM];   // h_new in fp16

__device__ __forceinline__ uint32_t smem_u32(const void* p) {
    uint32_t a;
    asm("{ .reg .u64 t; cvta.to.shared.u64 t, %1; cvt.u32.u64 %0, t; }" : "=r"(a) : "l"(p));
    return a;
}
#define SWZ128(off) ((off) ^ (((off) >> 3) & 0x70))

__device__ __forceinline__ void cpa16(uint32_t smem, const void* g) {
    asm volatile("cp.async.cg.shared.global [%0], [%1], 16;" :: "r"(smem), "l"(g));
}
#define CPA_COMMIT()  asm volatile("cp.async.commit_group;" ::: "memory")
#define CPA_WAIT(n)   asm volatile("cp.async.wait_group %0;" :: "n"(n) : "memory")

__device__ __forceinline__ void ldmx4(uint32_t* r, uint32_t addr) {
    asm volatile("ldmatrix.sync.aligned.m8n8.x4.shared.b16 {%0,%1,%2,%3}, [%4];"
                 : "=r"(r[0]), "=r"(r[1]), "=r"(r[2]), "=r"(r[3]) : "r"(addr));
}
__device__ __forceinline__ void ldmx2(uint32_t* r, uint32_t addr) {
    asm volatile("ldmatrix.sync.aligned.m8n8.x2.shared.b16 {%0,%1}, [%2];"
                 : "=r"(r[0]), "=r"(r[1]) : "r"(addr));
}
__device__ __forceinline__ void mma16816(float* c, const uint32_t* a, const uint32_t* b) {
    asm volatile(
        "mma.sync.aligned.m16n8k16.row.col.f32.f16.f16.f32 "
        "{%0,%1,%2,%3}, {%4,%5,%6,%7}, {%8,%9}, {%0,%1,%2,%3};"
        : "+f"(c[0]), "+f"(c[1]), "+f"(c[2]), "+f"(c[3])
        : "r"(a[0]), "r"(a[1]), "r"(a[2]), "r"(a[3]), "r"(b[0]), "r"(b[1]));
}

// ---------------------------------------------------------------------------
// 1) convX: pack [s|a] -> fp16 [BATCH x 576]
// ---------------------------------------------------------------------------
__global__ void convX(const float* __restrict__ s, const float* __restrict__ a) {
    int idx = blockIdx.x * 256 + threadIdx.x;
    if (idx >= BATCH * KP) return;
    int b = idx / KP;
    int k = idx - b * KP;
    float v = (k < SDIM) ? s[b * SDIM + k] : a[b * ADIM + (k - SDIM)];
    g_x[idx] = __float2half_rn(v);
}

// ---------------------------------------------------------------------------
// 2) convW: Wx rows 0..575 -> K-major fp16, gate-interleaved n' = (n&2047)*4 + (n>>11)
// ---------------------------------------------------------------------------
__global__ void convW(const float* __restrict__ Wx) {
    __shared__ float t[64][33];
    int n0 = blockIdx.x * 32;
    int k0 = blockIdx.y * 64;
    int tx = threadIdx.x, ty = threadIdx.y;       // (32, 8)
#pragma unroll
    for (int i = 0; i < 8; i++) {
        int kl = ty * 8 + i;
        t[kl][tx] = Wx[(size_t)(k0 + kl) * FOURH + n0 + tx];
    }
    __syncthreads();
    int tid = ty * 32 + tx;
    int nl  = tid >> 3;
    int ch  = tid & 7;
    int n   = n0 + nl;
    size_t np = (size_t)(n & 2047) * 4 + (n >> 11);
    uint4 vh;
    __half* ph = (__half*)&vh;
#pragma unroll
    for (int u = 0; u < 8; u++)
        ph[u] = __float2half_rn(t[ch * 8 + u][nl]);
    *(uint4*)&g_w[np * KP + k0 + ch * 8] = vh;
}

// ---------------------------------------------------------------------------
// 3) convA: Wa [2048 x 64] -> g_wa [64 x 2048] K-major fp16
// ---------------------------------------------------------------------------
__global__ void convA(const float* __restrict__ Wa) {
    __shared__ float t[64][65];
    int k0 = blockIdx.x * 64;
    int tid = threadIdx.x;       // 256
#pragma unroll
    for (int i = 0; i < 16; i++) {
        int e = tid + i * 256;
        int kl = e >> 6, n = e & 63;
        t[kl][n] = Wa[(size_t)(k0 + kl) * 64 + n];
    }
    __syncthreads();
    int n = tid >> 2, kq = (tid & 3) * 16;
    uint4 v[2];
    __half* ph = (__half*)v;
#pragma unroll
    for (int u = 0; u < 16; u++)
        ph[u] = __float2half_rn(t[kq + u][n]);
    *(uint4*)&g_wa[(size_t)n * HDIM + k0 + kq]     = v[0];
    *(uint4*)&g_wa[(size_t)n * HDIM + k0 + kq + 8] = v[1];
}

// ---------------------------------------------------------------------------
// 4) vb partials: vbp[kc][j] = sum_{k in chunk kc} h[k] * Wh[k][j]
// ---------------------------------------------------------------------------
__global__ void vb_partial(const float* __restrict__ h, const float* __restrict__ Wh) {
    int j  = blockIdx.x * 256 + threadIdx.x;
    int k0 = blockIdx.y * 256;
    float acc = 0.0f;
#pragma unroll 8
    for (int k = 0; k < 256; k++)
        acc += h[k0 + k] * Wh[(size_t)(k0 + k) * FOURH + j];
    g_vbp[blockIdx.y * FOURH + j] = acc;
}

// ---------------------------------------------------------------------------
// 5) HMMA GEMM + LSTM gate epilogue, h stored fp16.
//    CTA: 128 rows x 128 cols (32 hidden x 4 gates), 256 threads, 8 warps 2x4.
//    3-stage cp.async ring; swizzle addresses precomputed (1 reg per operand).
// ---------------------------------------------------------------------------
#define ST_A   0
#define ST_B   16384
#define ST_STRIDE 32768
#define SVB_OFF  (3 * ST_STRIDE)
#define SMEM_SZ  (3 * ST_STRIDE + 512)

__global__ __launch_bounds__(256, 2) void lstm_mma(const float* __restrict__ cvec,
                                                   const float* __restrict__ rp,
                                                   const float* __restrict__ w576,
                                                   const float* __restrict__ bh) {
    extern __shared__ char smem[];
    uint32_t sb = smem_u32(smem);
    int tid  = threadIdx.x;
    int lane = tid & 31, w = tid >> 5;
    int wm = w & 1, wn = w >> 1;          // 2 x 4 warp grid
    int row0 = blockIdx.y * 128;
    int j0   = blockIdx.x * 32;

    int lr = lane & 7, ls = lane >> 3;
    uint32_t a_row = wm * 64 + lr + (ls & 1) * 8;   // + mt*16
    uint32_t a_chs = (uint32_t)(ls >> 1);
    uint32_t b_row = wn * 32 + lr;                  // + nt*8
    uint32_t b_chs = (uint32_t)(ls & 1);

    // precomputed swizzled bases: addr = sa + ((p0 + tile_off) ^ (kb<<4))
    uint32_t pa0 = ST_A + (((a_row * 128) | ((a_row * 16) & 0x70)) ^ (a_chs << 4));
    uint32_t pb0 = ST_B + (((b_row * 128) | ((b_row * 16) & 0x70)) ^ (b_chs << 4));

    // cp.async smem offsets: slot i -> sw0 + i*4096 (A and B share pattern)
    uint32_t sw0 = SWZ128((uint32_t)((tid >> 3) * 128 + (tid & 7) * 16));
    const __half* px = g_x + (size_t)(row0 + (tid >> 3)) * KP + (tid & 7) * 8;
    const __half* pw = g_w + (size_t)(j0 * 4 + (tid >> 3)) * KP + (tid & 7) * 8;

    float acc[4][4][4];
#pragma unroll
    for (int mt = 0; mt < 4; mt++)
#pragma unroll
        for (int nt = 0; nt < 4; nt++)
#pragma unroll
            for (int i = 0; i < 4; i++) acc[mt][nt][i] = 0.0f;

#pragma unroll
    for (int st = 0; st < 2; st++) {      // prologue: chunks 0,1
        uint32_t base = sb + st * ST_STRIDE;
#pragma unroll
        for (int i = 0; i < 4; i++) {
            cpa16(base + ST_A + sw0 + i * 4096, px + (size_t)i * 32 * KP + st * 64);
            cpa16(base + ST_B + sw0 + i * 4096, pw + (size_t)i * 32 * KP + st * 64);
        }
        CPA_COMMIT();
    }

    // fused vb reduce (overlaps prologue cp.async)
    float* svb = (float*)(smem + SVB_OFF);
    if (tid < 128) {
        int j = (tid >> 5) * HDIM + j0 + (tid & 31);
        float acc_vb = __ldg(&bh[j]);
#pragma unroll
        for (int kc = 0; kc < 8; kc++) acc_vb += g_vbp[kc * FOURH + j];
        svb[tid] = acc_vb;
    }

    for (int t = 0; t < NCH; t++) {
        if (t == NCH - 1) { CPA_WAIT(0); } else { CPA_WAIT(1); }
        __syncthreads();

        if (t + 2 < NCH) {
            uint32_t base = sb + ((t + 2) % 3) * ST_STRIDE;
            int kg = (t + 2) * 64;
#pragma unroll
            for (int i = 0; i < 4; i++) {
                cpa16(base + ST_A + sw0 + i * 4096, px + (size_t)i * 32 * KP + kg);
                cpa16(base + ST_B + sw0 + i * 4096, pw + (size_t)i * 32 * KP + kg);
            }
            CPA_COMMIT();
        }

        uint32_t sa = sb + (t % 3) * ST_STRIDE;
#pragma unroll
        for (int kb = 0; kb < 8; kb += 2) {          // 4 k16 steps
            uint32_t koff = (uint32_t)(kb << 4);
            uint32_t bb[4][2];
#pragma unroll
            for (int nt = 0; nt < 4; nt++)
                ldmx2(bb[nt], sa + ((pb0 + nt * 1024) ^ koff));
#pragma unroll
            for (int mt = 0; mt < 4; mt++) {
                uint32_t aa[4];
                ldmx4(aa, sa + ((pa0 + mt * 2048) ^ koff));
#pragma unroll
                for (int nt = 0; nt < 4; nt++)
                    mma16816(acc[mt][nt], aa, bb[nt]);
            }
        }
    }
    __syncthreads();

    // ---- epilogue: + vb + r*w576 (exact fp32), gate math, fp16 store ----
    int q = lane & 3;
    int gp = q & 1;
    int jsel = q >> 1;
    float* hsm = (float*)smem; // [128][33] overlay

    float r0v[4], r1v[4];
#pragma unroll
    for (int mt = 0; mt < 4; mt++) {
        int rw = wm * 64 + mt * 16 + (lane >> 2);
        r0v[mt] = __ldg(&rp[row0 + rw]);
        r1v[mt] = __ldg(&rp[row0 + rw + 8]);
    }

#pragma unroll
    for (int nt = 0; nt < 4; nt++) {
        int jl = wn * 8 + nt * 2 + jsel;
        int j  = j0 + jl;
        float vbi = svb[jl];
        float vbf = svb[32 + jl];
        float vbg = svb[64 + jl];
        float vbo = svb[96 + jl];
        float w5i = __ldg(&w576[j]);
        float w5f = __ldg(&w576[HDIM + j]);
        float w5g = __ldg(&w576[2 * HDIM + j]);
        float w5o = __ldg(&w576[3 * HDIM + j]);
        float cj  = __ldg(&cvec[j]);
#pragma unroll
        for (int mt = 0; mt < 4; mt++) {
            float r0 = r0v[mt], r1 = r1v[mt];
            float v0 = acc[mt][nt][0], v1 = acc[mt][nt][1];
            float v2 = acc[mt][nt][2], v3 = acc[mt][nt][3];
            float p0 = __shfl_xor_sync(0xFFFFFFFFu, v0, 1);
            float p1 = __shfl_xor_sync(0xFFFFFFFFu, v1, 1);
            float p2 = __shfl_xor_sync(0xFFFFFFFFu, v2, 1);
            float p3 = __shfl_xor_sync(0xFFFFFFFFu, v3, 1);
            float zi0 = gp ? p0 : v0, zf0 = gp ? p1 : v1;
            float zg0 = gp ? v0 : p0, zo0 = gp ? v1 : p1;
            float zi1 = gp ? p2 : v2, zf1 = gp ? p3 : v3;
            float zg1 = gp ? v2 : p2, zo1 = gp ? v3 : p3;

            zi0 += vbi + r0 * w5i; zf0 += vbf + r0 * w5f;
            zg0 += vbg + r0 * w5g; zo0 += vbo + r0 * w5o;
            zi1 += vbi + r1 * w5i; zf1 += vbf + r1 * w5f;
            zg1 += vbg + r1 * w5g; zo1 += vbo + r1 * w5o;

            float i0 = 1.0f / (1.0f + __expf(-zi0));
            float f0 = 1.0f / (1.0f + __expf(-zf0));
            float o0 = 1.0f / (1.0f + __expf(-zo0));
            float c0 = f0 * cj + i0 * tanhf(zg0);
            float h0 = o0 * tanhf(c0);
            float i1 = 1.0f / (1.0f + __expf(-zi1));
            float f1 = 1.0f / (1.0f + __expf(-zf1));
            float o1 = 1.0f / (1.0f + __expf(-zo1));
            float c1 = f1 * cj + i1 * tanhf(zg1);
            float h1 = o1 * tanhf(c1);

            if (gp == 0) {
                int rw = wm * 64 + mt * 16 + (lane >> 2);
                hsm[rw * 33 + jl]       = h0;
                hsm[(rw + 8) * 33 + jl] = h1;
            }
        }
    }
    __syncthreads();

    // fp16 store of the [128 x 32] h tile
#pragma unroll
    for (int i = 0; i < 8; i++) {
        int slot = tid + i * 256;           // 2048 half2 slots
        int rw = slot >> 4, c2 = (slot & 15) * 2;
        __half2 hv = __floats2half2_rn(hsm[rw * 33 + c2], hsm[rw * 33 + c2 + 1]);
        *(__half2*)(g_hf + (size_t)(row0 + rw) * HDIM + j0 + c2) = hv;
    }
}

// ---------------------------------------------------------------------------
// 6) heads via HMMA: logits = h @ Wa; softmax from smem; value SIMT over fp16 h.
//    CTA: 32 rows x 64 actions, 256 threads, 8 warps (2m x 4n), K = 2048.
// ---------------------------------------------------------------------------
#define H_STA 0
#define H_STB 4096
#define H_STRIDE 12288
#define H_NCH 32
#define H_SMEM (3 * H_STRIDE + 8192)
#define H_WV_OFF (3 * H_STRIDE)

__global__ __launch_bounds__(256, 2) void heads_mma(const float* __restrict__ Wv,
                                                    const float* __restrict__ ba,
                                                    const float* __restrict__ bv,
                                                    float* __restrict__ out) {
    extern __shared__ char smem[];
    uint32_t sb = smem_u32(smem);
    int tid  = threadIdx.x;
    int lane = tid & 31, w = tid >> 5;
    int wm = w & 1, wn = w >> 1;          // 2m x 4n
    int row0 = blockIdx.x * 32;

    int lr = lane & 7, ls = lane >> 3;
    uint32_t a_row = wm * 16 + lr + (ls & 1) * 8;
    uint32_t a_chs = (uint32_t)(ls >> 1);
    uint32_t b_row = wn * 16 + lr;        // + nt*8
    uint32_t b_chs = (uint32_t)(ls & 1);

    uint32_t pa0 = H_STA + (((a_row * 128) | ((a_row * 16) & 0x70)) ^ (a_chs << 4));
    uint32_t pb0 = H_STB + (((b_row * 128) | ((b_row * 16) & 0x70)) ^ (b_chs << 4));

    uint32_t sw0 = SWZ128((uint32_t)((tid >> 3) * 128 + (tid & 7) * 16));
    const __half* ph = g_hf + (size_t)(row0 + (tid >> 3)) * HDIM + (tid & 7) * 8;
    const __half* pa = g_wa + (size_t)(tid >> 3) * HDIM + (tid & 7) * 8;

    float acc[2][4];
#pragma unroll
    for (int nt = 0; nt < 2; nt++)
#pragma unroll
        for (int i = 0; i < 4; i++) acc[nt][i] = 0.0f;

#pragma unroll
    for (int st = 0; st < 2; st++) {
        uint32_t base = sb + st * H_STRIDE;
        cpa16(base + H_STA + sw0, ph + st * 64);
#pragma unroll
        for (int i = 0; i < 2; i++)
            cpa16(base + H_STB + sw0 + i * 4096, pa + (size_t)i * 32 * HDIM + st * 64);
        CPA_COMMIT();
    }

    for (int t = 0; t < H_NCH; t++) {
        if (t == H_NCH - 1) { CPA_WAIT(0); } else { CPA_WAIT(1); }
        __syncthreads();

        if (t + 2 < H_NCH) {
            uint32_t base = sb + ((t + 2) % 3) * H_STRIDE;
            int kg = (t + 2) * 64;
            cpa16(base + H_STA + sw0, ph + kg);
#pragma unroll
            for (int i = 0; i < 2; i++)
                cpa16(base + H_STB + sw0 + i * 4096, pa + (size_t)i * 32 * HDIM + kg);
            CPA_COMMIT();
        }

        uint32_t sa = sb + (t % 3) * H_STRIDE;
#pragma unroll
        for (int kb = 0; kb < 8; kb += 2) {
            uint32_t koff = (uint32_t)(kb << 4);
            uint32_t aa[4];
            ldmx4(aa, sa + (pa0 ^ koff));
#pragma unroll
            for (int nt = 0; nt < 2; nt++) {
                uint32_t bb[2];
                ldmx2(bb, sa + ((pb0 + nt * 1024) ^ koff));
                mma16816(acc[nt], aa, bb);
            }
        }
    }
    __syncthreads();

    // stage logits [32][65] + load Wv to smem
    float* lsm = (float*)smem;
    float* wvs = (float*)(smem + H_WV_OFF);
    {
        int r = wm * 16 + (lane >> 2);
#pragma unroll
        for (int nt = 0; nt < 2; nt++) {
            int c = wn * 16 + nt * 8 + (lane & 3) * 2;
            lsm[r * 65 + c]           = acc[nt][0];
            lsm[r * 65 + c + 1]       = acc[nt][1];
            lsm[(r + 8) * 65 + c]     = acc[nt][2];
            lsm[(r + 8) * 65 + c + 1] = acc[nt][3];
        }
    }
#pragma unroll
    for (int i = 0; i < 2; i++) {
        int e = tid + i * 256;
        *(float4*)&wvs[e * 4] = *(const float4*)&Wv[e * 4];
    }
    __syncthreads();

    // softmax (8 lanes per row) + value
    int rowt = tid >> 3, ag = tid & 7;
    float l[8];
    float m = -INFINITY;
#pragma unroll
    for (int a = 0; a < 8; a++) {
        l[a] = lsm[rowt * 65 + ag * 8 + a] + __ldg(&ba[ag * 8 + a]);
        m = fmaxf(m, l[a]);
    }
#pragma unroll
    for (int off = 4; off > 0; off >>= 1)
        m = fmaxf(m, __shfl_xor_sync(0xFFFFFFFFu, m, off, 8));
    float sum = 0.0f;
#pragma unroll
    for (int a = 0; a < 8; a++) {
        l[a] = expf(l[a] - m);
        sum += l[a];
    }
#pragma unroll
    for (int off = 4; off > 0; off >>= 1)
        sum += __shfl_xor_sync(0xFFFFFFFFu, sum, off, 8);
    float inv = 1.0f / sum;
    int row = row0 + rowt;
#pragma unroll
    for (int a = 0; a < 8; a++)
        out[(size_t)row * 64 + ag * 8 + a] = l[a] * inv;

    // value: each lane covers 256 of K = 2048
    float vacc = 0.0f;
    const __half* hrow = g_hf + (size_t)row * HDIM + ag * 256;
#pragma unroll 4
    for (int u = 0; u < 32; u++) {
        uint4 hv = *(const uint4*)(hrow + u * 8);
        __half2* h2 = (__half2*)&hv;
        int kb = ag * 256 + u * 8;
#pragma unroll
        for (int p = 0; p < 4; p++) {
            float2 f = __half22float2(h2[p]);
            vacc += f.x * wvs[kb + p * 2];
            vacc += f.y * wvs[kb + p * 2 + 1];
        }
    }
#pragma unroll
    for (int off = 4; off > 0; off >>= 1)
        vacc += __shfl_xor_sync(0xFFFFFFFFu, vacc, off, 8);
    if (ag == 0)
        out[(size_t)BATCH * 64 + row] = vacc + __ldg(&bv[0]);
}

// ---------------------------------------------------------------------------
extern "C" void kernel_launch(void* const* d_in, const int* in_sizes, int n_in,
                              void* d_out, int out_size) {
    const float* s      = (const float*)d_in[0];
    const float* a_prev = (const float*)d_in[1];
    const float* r_prev = (const float*)d_in[2];
    const float* h      = (const float*)d_in[3];
    const float* c      = (const float*)d_in[4];
    const float* Wx     = (const float*)d_in[5];
    const float* Wh     = (const float*)d_in[6];
    const float* bh     = (const float*)d_in[7];
    const float* Wa     = (const float*)d_in[8];
    const float* ba     = (const float*)d_in[9];
    const float* Wv     = (const float*)d_in[10];
    const float* bv     = (const float*)d_in[11];
    float* out = (float*)d_out;

    static bool attr_set = false;
    if (!attr_set) {
        cudaFuncSetAttribute(lstm_mma, cudaFuncAttributeMaxDynamicSharedMemorySize, SMEM_SZ);
        cudaFuncSetAttribute(heads_mma, cudaFuncAttributeMaxDynamicSharedMemorySize, H_SMEM);
        attr_set = true;
    }

    convX<<<(BATCH * KP + 255) / 256, 256>>>(s, a_prev);
    convW<<<dim3(FOURH / 32, KP / 64), dim3(32, 8)>>>(Wx);
    convA<<<HDIM / 64, 256>>>(Wa);
    vb_partial<<<dim3(FOURH / 256, 8), 256>>>(h, Wh);
    lstm_mma<<<dim3(HDIM / 32, BATCH / 128), 256, SMEM_SZ>>>(
        c, r_prev, Wx + (size_t)(KDIM - 1) * FOURH, bh);
    heads_mma<<<BATCH / 32, 256, H_SMEM>>>(Wv, ba, bv, out);
}

// round 10
// speedup vs baseline: 5.1641x; 1.0488x over previous
#include <cuda_runtime.h>
#include <cuda_fp16.h>
#include <math.h>
#include <cstdint>

#define BATCH 4096
#define SDIM  512
#define ADIM  64
#define HDIM  2048
#define KDIM  577
#define KP    576           // s(512) + a(64); reward column folded rank-1 in epilogue
#define NCH   9
#define FOURH 8192
#define VB_CH 32            // k-chunks for vb_partial

// ---------------- scratch (static device globals) ----------------
__device__ __half g_x[BATCH * KP];      // fp16 packed [s|a]
__device__ __half g_w[FOURH * KP];      // gate-interleaved rows n' = j*4 + g, K-major
__device__ __half g_wa[64 * HDIM];      // Wa transposed [n][k] K-major fp16
__device__ float g_vbp[VB_CH * FOURH];  // k-split partials of h @ Wh
__device__ __half g_hf[BATCH * HDIM];   // h_new in fp16

__device__ __forceinline__ uint32_t smem_u32(const void* p) {
    uint32_t a;
    asm("{ .reg .u64 t; cvta.to.shared.u64 t, %1; cvt.u32.u64 %0, t; }" : "=r"(a) : "l"(p));
    return a;
}
#define SWZ128(off) ((off) ^ (((off) >> 3) & 0x70))

__device__ __forceinline__ void cpa16(uint32_t smem, const void* g) {
    asm volatile("cp.async.cg.shared.global [%0], [%1], 16;" :: "r"(smem), "l"(g));
}
#define CPA_COMMIT()  asm volatile("cp.async.commit_group;" ::: "memory")
#define CPA_WAIT(n)   asm volatile("cp.async.wait_group %0;" :: "n"(n) : "memory")

__device__ __forceinline__ void ldmx4(uint32_t* r, uint32_t addr) {
    asm volatile("ldmatrix.sync.aligned.m8n8.x4.shared.b16 {%0,%1,%2,%3}, [%4];"
                 : "=r"(r[0]), "=r"(r[1]), "=r"(r[2]), "=r"(r[3]) : "r"(addr));
}
__device__ __forceinline__ void ldmx2(uint32_t* r, uint32_t addr) {
    asm volatile("ldmatrix.sync.aligned.m8n8.x2.shared.b16 {%0,%1}, [%2];"
                 : "=r"(r[0]), "=r"(r[1]) : "r"(addr));
}
__device__ __forceinline__ void mma16816(float* c, const uint32_t* a, const uint32_t* b) {
    asm volatile(
        "mma.sync.aligned.m16n8k16.row.col.f32.f16.f16.f32 "
        "{%0,%1,%2,%3}, {%4,%5,%6,%7}, {%8,%9}, {%0,%1,%2,%3};"
        : "+f"(c[0]), "+f"(c[1]), "+f"(c[2]), "+f"(c[3])
        : "r"(a[0]), "r"(a[1]), "r"(a[2]), "r"(a[3]), "r"(b[0]), "r"(b[1]));
}

// ---------------------------------------------------------------------------
// convX: pack [s|a] -> fp16 [BATCH x 576]
// ---------------------------------------------------------------------------
__global__ void convX(const float* __restrict__ s, const float* __restrict__ a) {
    int idx = blockIdx.x * 256 + threadIdx.x;
    if (idx >= BATCH * KP) return;
    int b = idx / KP;
    int k = idx - b * KP;
    float v = (k < SDIM) ? s[b * SDIM + k] : a[b * ADIM + (k - SDIM)];
    g_x[idx] = __float2half_rn(v);
}

// ---------------------------------------------------------------------------
// convW: Wx rows 0..575 -> K-major fp16, gate-interleaved n' = (n&2047)*4 + (n>>11)
// ---------------------------------------------------------------------------
__global__ void convW(const float* __restrict__ Wx) {
    __shared__ float t[64][33];
    int n0 = blockIdx.x * 32;
    int k0 = blockIdx.y * 64;
    int tx = threadIdx.x, ty = threadIdx.y;       // (32, 8)
#pragma unroll
    for (int i = 0; i < 8; i++) {
        int kl = ty * 8 + i;
        t[kl][tx] = Wx[(size_t)(k0 + kl) * FOURH + n0 + tx];
    }
    __syncthreads();
    int tid = ty * 32 + tx;
    int nl  = tid >> 3;
    int ch  = tid & 7;
    int n   = n0 + nl;
    size_t np = (size_t)(n & 2047) * 4 + (n >> 11);
    uint4 vh;
    __half* ph = (__half*)&vh;
#pragma unroll
    for (int u = 0; u < 8; u++)
        ph[u] = __float2half_rn(t[ch * 8 + u][nl]);
    *(uint4*)&g_w[np * KP + k0 + ch * 8] = vh;
}

// ---------------------------------------------------------------------------
// convA: Wa [2048 x 64] -> g_wa [64 x 2048] K-major fp16
// ---------------------------------------------------------------------------
__global__ void convA(const float* __restrict__ Wa) {
    __shared__ float t[64][65];
    int k0 = blockIdx.x * 64;
    int tid = threadIdx.x;       // 256
#pragma unroll
    for (int i = 0; i < 16; i++) {
        int e = tid + i * 256;
        int kl = e >> 6, n = e & 63;
        t[kl][n] = Wa[(size_t)(k0 + kl) * 64 + n];
    }
    __syncthreads();
    int n = tid >> 2, kq = (tid & 3) * 16;
    uint4 v[2];
    __half* ph = (__half*)v;
#pragma unroll
    for (int u = 0; u < 16; u++)
        ph[u] = __float2half_rn(t[kq + u][n]);
    *(uint4*)&g_wa[(size_t)n * HDIM + k0 + kq]     = v[0];
    *(uint4*)&g_wa[(size_t)n * HDIM + k0 + kq + 8] = v[1];
}

// ---------------------------------------------------------------------------
// vb_partial: vbp[kc][j] = sum_{k in 64-chunk kc} h[k] * Wh[k][j]
// grid (32, 32), block 256 — 1024 blocks to saturate HBM.
// ---------------------------------------------------------------------------
__global__ void vb_partial(const float* __restrict__ h, const float* __restrict__ Wh) {
    int j  = blockIdx.x * 256 + threadIdx.x;
    int k0 = blockIdx.y * 64;
    float acc = 0.0f;
#pragma unroll 16
    for (int k = 0; k < 64; k++)
        acc += h[k0 + k] * __ldg(&Wh[(size_t)(k0 + k) * FOURH + j]);
    g_vbp[blockIdx.y * FOURH + j] = acc;
}

// ---------------------------------------------------------------------------
// lstm_mma: HMMA GEMM + LSTM gate epilogue, h stored fp16. (profiled slot #4)
// ---------------------------------------------------------------------------
#define ST_A   0
#define ST_B   16384
#define ST_STRIDE 32768
#define SVB_OFF  (3 * ST_STRIDE)
#define SMEM_SZ  (3 * ST_STRIDE + 512)

__global__ __launch_bounds__(256, 2) void lstm_mma(const float* __restrict__ cvec,
                                                   const float* __restrict__ rp,
                                                   const float* __restrict__ w576,
                                                   const float* __restrict__ bh) {
    extern __shared__ char smem[];
    uint32_t sb = smem_u32(smem);
    int tid  = threadIdx.x;
    int lane = tid & 31, w = tid >> 5;
    int wm = w & 1, wn = w >> 1;          // 2 x 4 warp grid
    int row0 = blockIdx.y * 128;
    int j0   = blockIdx.x * 32;

    int lr = lane & 7, ls = lane >> 3;
    uint32_t a_row = wm * 64 + lr + (ls & 1) * 8;   // + mt*16
    uint32_t a_chs = (uint32_t)(ls >> 1);
    uint32_t b_row = wn * 32 + lr;                  // + nt*8
    uint32_t b_chs = (uint32_t)(ls & 1);

    uint32_t pa0 = ST_A + (((a_row * 128) | ((a_row * 16) & 0x70)) ^ (a_chs << 4));
    uint32_t pb0 = ST_B + (((b_row * 128) | ((b_row * 16) & 0x70)) ^ (b_chs << 4));

    uint32_t sw0 = SWZ128((uint32_t)((tid >> 3) * 128 + (tid & 7) * 16));
    const __half* px = g_x + (size_t)(row0 + (tid >> 3)) * KP + (tid & 7) * 8;
    const __half* pw = g_w + (size_t)(j0 * 4 + (tid >> 3)) * KP + (tid & 7) * 8;

    float acc[4][4][4];
#pragma unroll
    for (int mt = 0; mt < 4; mt++)
#pragma unroll
        for (int nt = 0; nt < 4; nt++)
#pragma unroll
            for (int i = 0; i < 4; i++) acc[mt][nt][i] = 0.0f;

#pragma unroll
    for (int st = 0; st < 2; st++) {      // prologue: chunks 0,1
        uint32_t base = sb + st * ST_STRIDE;
#pragma unroll
        for (int i = 0; i < 4; i++) {
            cpa16(base + ST_A + sw0 + i * 4096, px + (size_t)i * 32 * KP + st * 64);
            cpa16(base + ST_B + sw0 + i * 4096, pw + (size_t)i * 32 * KP + st * 64);
        }
        CPA_COMMIT();
    }

    // fused vb reduce (overlaps prologue cp.async)
    float* svb = (float*)(smem + SVB_OFF);
    if (tid < 128) {
        int j = (tid >> 5) * HDIM + j0 + (tid & 31);
        float acc_vb = __ldg(&bh[j]);
#pragma unroll
        for (int kc = 0; kc < VB_CH; kc++) acc_vb += g_vbp[kc * FOURH + j];
        svb[tid] = acc_vb;
    }

    for (int t = 0; t < NCH; t++) {
        if (t == NCH - 1) { CPA_WAIT(0); } else { CPA_WAIT(1); }
        __syncthreads();

        if (t + 2 < NCH) {
            uint32_t base = sb + ((t + 2) % 3) * ST_STRIDE;
            int kg = (t + 2) * 64;
#pragma unroll
            for (int i = 0; i < 4; i++) {
                cpa16(base + ST_A + sw0 + i * 4096, px + (size_t)i * 32 * KP + kg);
                cpa16(base + ST_B + sw0 + i * 4096, pw + (size_t)i * 32 * KP + kg);
            }
            CPA_COMMIT();
        }

        uint32_t sa = sb + (t % 3) * ST_STRIDE;
#pragma unroll
        for (int kb = 0; kb < 8; kb += 2) {          // 4 k16 steps
            uint32_t koff = (uint32_t)(kb << 4);
            uint32_t bb[4][2];
#pragma unroll
            for (int nt = 0; nt < 4; nt++)
                ldmx2(bb[nt], sa + ((pb0 + nt * 1024) ^ koff));
#pragma unroll
            for (int mt = 0; mt < 4; mt++) {
                uint32_t aa[4];
                ldmx4(aa, sa + ((pa0 + mt * 2048) ^ koff));
#pragma unroll
                for (int nt = 0; nt < 4; nt++)
                    mma16816(acc[mt][nt], aa, bb[nt]);
            }
        }
    }
    __syncthreads();

    // ---- epilogue: + vb + r*w576 (exact fp32), gate math, fp16 store ----
    int q = lane & 3;
    int gp = q & 1;
    int jsel = q >> 1;
    float* hsm = (float*)smem;

    float r0v[4], r1v[4];
#pragma unroll
    for (int mt = 0; mt < 4; mt++) {
        int rw = wm * 64 + mt * 16 + (lane >> 2);
        r0v[mt] = __ldg(&rp[row0 + rw]);
        r1v[mt] = __ldg(&rp[row0 + rw + 8]);
    }

#pragma unroll
    for (int nt = 0; nt < 4; nt++) {
        int jl = wn * 8 + nt * 2 + jsel;
        int j  = j0 + jl;
        float vbi = svb[jl];
        float vbf = svb[32 + jl];
        float vbg = svb[64 + jl];
        float vbo = svb[96 + jl];
        float w5i = __ldg(&w576[j]);
        float w5f = __ldg(&w576[HDIM + j]);
        float w5g = __ldg(&w576[2 * HDIM + j]);
        float w5o = __ldg(&w576[3 * HDIM + j]);
        float cj  = __ldg(&cvec[j]);
#pragma unroll
        for (int mt = 0; mt < 4; mt++) {
            float r0 = r0v[mt], r1 = r1v[mt];
            float v0 = acc[mt][nt][0], v1 = acc[mt][nt][1];
            float v2 = acc[mt][nt][2], v3 = acc[mt][nt][3];
            float p0 = __shfl_xor_sync(0xFFFFFFFFu, v0, 1);
            float p1 = __shfl_xor_sync(0xFFFFFFFFu, v1, 1);
            float p2 = __shfl_xor_sync(0xFFFFFFFFu, v2, 1);
            float p3 = __shfl_xor_sync(0xFFFFFFFFu, v3, 1);
            float zi0 = gp ? p0 : v0, zf0 = gp ? p1 : v1;
            float zg0 = gp ? v0 : p0, zo0 = gp ? v1 : p1;
            float zi1 = gp ? p2 : v2, zf1 = gp ? p3 : v3;
            float zg1 = gp ? v2 : p2, zo1 = gp ? v3 : p3;

            zi0 += vbi + r0 * w5i; zf0 += vbf + r0 * w5f;
            zg0 += vbg + r0 * w5g; zo0 += vbo + r0 * w5o;
            zi1 += vbi + r1 * w5i; zf1 += vbf + r1 * w5f;
            zg1 += vbg + r1 * w5g; zo1 += vbo + r1 * w5o;

            float i0 = 1.0f / (1.0f + __expf(-zi0));
            float f0 = 1.0f / (1.0f + __expf(-zf0));
            float o0 = 1.0f / (1.0f + __expf(-zo0));
            float c0 = f0 * cj + i0 * tanhf(zg0);
            float h0 = o0 * tanhf(c0);
            float i1 = 1.0f / (1.0f + __expf(-zi1));
            float f1 = 1.0f / (1.0f + __expf(-zf1));
            float o1 = 1.0f / (1.0f + __expf(-zo1));
            float c1 = f1 * cj + i1 * tanhf(zg1);
            float h1 = o1 * tanhf(c1);

            if (gp == 0) {
                int rw = wm * 64 + mt * 16 + (lane >> 2);
                hsm[rw * 33 + jl]       = h0;
                hsm[(rw + 8) * 33 + jl] = h1;
            }
        }
    }
    __syncthreads();

#pragma unroll
    for (int i = 0; i < 8; i++) {
        int slot = tid + i * 256;
        int rw = slot >> 4, c2 = (slot & 15) * 2;
        __half2 hv = __floats2half2_rn(hsm[rw * 33 + c2], hsm[rw * 33 + c2 + 1]);
        *(__half2*)(g_hf + (size_t)(row0 + rw) * HDIM + j0 + c2) = hv;
    }
}

// ---------------------------------------------------------------------------
// heads_mma: logits = h @ Wa via HMMA; softmax; value SIMT over fp16 h.
// ---------------------------------------------------------------------------
#define H_STA 0
#define H_STB 4096
#define H_STRIDE 12288
#define H_NCH 32
#define H_SMEM (3 * H_STRIDE + 8192)
#define H_WV_OFF (3 * H_STRIDE)

__global__ __launch_bounds__(256, 2) void heads_mma(const float* __restrict__ Wv,
                                                    const float* __restrict__ ba,
                                                    const float* __restrict__ bv,
                                                    float* __restrict__ out) {
    extern __shared__ char smem[];
    uint32_t sb = smem_u32(smem);
    int tid  = threadIdx.x;
    int lane = tid & 31, w = tid >> 5;
    int wm = w & 1, wn = w >> 1;
    int row0 = blockIdx.x * 32;

    int lr = lane & 7, ls = lane >> 3;
    uint32_t a_row = wm * 16 + lr + (ls & 1) * 8;
    uint32_t a_chs = (uint32_t)(ls >> 1);
    uint32_t b_row = wn * 16 + lr;
    uint32_t b_chs = (uint32_t)(ls & 1);

    uint32_t pa0 = H_STA + (((a_row * 128) | ((a_row * 16) & 0x70)) ^ (a_chs << 4));
    uint32_t pb0 = H_STB + (((b_row * 128) | ((b_row * 16) & 0x70)) ^ (b_chs << 4));

    uint32_t sw0 = SWZ128((uint32_t)((tid >> 3) * 128 + (tid & 7) * 16));
    const __half* ph = g_hf + (size_t)(row0 + (tid >> 3)) * HDIM + (tid & 7) * 8;
    const __half* pa = g_wa + (size_t)(tid >> 3) * HDIM + (tid & 7) * 8;

    float acc[2][4];
#pragma unroll
    for (int nt = 0; nt < 2; nt++)
#pragma unroll
        for (int i = 0; i < 4; i++) acc[nt][i] = 0.0f;

#pragma unroll
    for (int st = 0; st < 2; st++) {
        uint32_t base = sb + st * H_STRIDE;
        cpa16(base + H_STA + sw0, ph + st * 64);
#pragma unroll
        for (int i = 0; i < 2; i++)
            cpa16(base + H_STB + sw0 + i * 4096, pa + (size_t)i * 32 * HDIM + st * 64);
        CPA_COMMIT();
    }

    for (int t = 0; t < H_NCH; t++) {
        if (t == H_NCH - 1) { CPA_WAIT(0); } else { CPA_WAIT(1); }
        __syncthreads();

        if (t + 2 < H_NCH) {
            uint32_t base = sb + ((t + 2) % 3) * H_STRIDE;
            int kg = (t + 2) * 64;
            cpa16(base + H_STA + sw0, ph + kg);
#pragma unroll
            for (int i = 0; i < 2; i++)
                cpa16(base + H_STB + sw0 + i * 4096, pa + (size_t)i * 32 * HDIM + kg);
            CPA_COMMIT();
        }

        uint32_t sa = sb + (t % 3) * H_STRIDE;
#pragma unroll
        for (int kb = 0; kb < 8; kb += 2) {
            uint32_t koff = (uint32_t)(kb << 4);
            uint32_t aa[4];
            ldmx4(aa, sa + (pa0 ^ koff));
#pragma unroll
            for (int nt = 0; nt < 2; nt++) {
                uint32_t bb[2];
                ldmx2(bb, sa + ((pb0 + nt * 1024) ^ koff));
                mma16816(acc[nt], aa, bb);
            }
        }
    }
    __syncthreads();

    float* lsm = (float*)smem;
    float* wvs = (float*)(smem + H_WV_OFF);
    {
        int r = wm * 16 + (lane >> 2);
#pragma unroll
        for (int nt = 0; nt < 2; nt++) {
            int c = wn * 16 + nt * 8 + (lane & 3) * 2;
            lsm[r * 65 + c]           = acc[nt][0];
            lsm[r * 65 + c + 1]       = acc[nt][1];
            lsm[(r + 8) * 65 + c]     = acc[nt][2];
            lsm[(r + 8) * 65 + c + 1] = acc[nt][3];
        }
    }
#pragma unroll
    for (int i = 0; i < 2; i++) {
        int e = tid + i * 256;
        *(float4*)&wvs[e * 4] = *(const float4*)&Wv[e * 4];
    }
    __syncthreads();

    int rowt = tid >> 3, ag = tid & 7;
    float l[8];
    float m = -INFINITY;
#pragma unroll
    for (int a = 0; a < 8; a++) {
        l[a] = lsm[rowt * 65 + ag * 8 + a] + __ldg(&ba[ag * 8 + a]);
        m = fmaxf(m, l[a]);
    }
#pragma unroll
    for (int off = 4; off > 0; off >>= 1)
        m = fmaxf(m, __shfl_xor_sync(0xFFFFFFFFu, m, off, 8));
    float sum = 0.0f;
#pragma unroll
    for (int a = 0; a < 8; a++) {
        l[a] = expf(l[a] - m);
        sum += l[a];
    }
#pragma unroll
    for (int off = 4; off > 0; off >>= 1)
        sum += __shfl_xor_sync(0xFFFFFFFFu, sum, off, 8);
    float inv = 1.0f / sum;
    int row = row0 + rowt;
#pragma unroll
    for (int a = 0; a < 8; a++)
        out[(size_t)row * 64 + ag * 8 + a] = l[a] * inv;

    float vacc = 0.0f;
    const __half* hrow = g_hf + (size_t)row * HDIM + ag * 256;
#pragma unroll 4
    for (int u = 0; u < 32; u++) {
        uint4 hv = *(const uint4*)(hrow + u * 8);
        __half2* h2 = (__half2*)&hv;
        int kb = ag * 256 + u * 8;
#pragma unroll
        for (int p = 0; p < 4; p++) {
            float2 f = __half22float2(h2[p]);
            vacc += f.x * wvs[kb + p * 2];
            vacc += f.y * wvs[kb + p * 2 + 1];
        }
    }
#pragma unroll
    for (int off = 4; off > 0; off >>= 1)
        vacc += __shfl_xor_sync(0xFFFFFFFFu, vacc, off, 8);
    if (ag == 0)
        out[(size_t)BATCH * 64 + row] = vacc + __ldg(&bv[0]);
}

// ---------------------------------------------------------------------------
extern "C" void kernel_launch(void* const* d_in, const int* in_sizes, int n_in,
                              void* d_out, int out_size) {
    const float* s      = (const float*)d_in[0];
    const float* a_prev = (const float*)d_in[1];
    const float* r_prev = (const float*)d_in[2];
    const float* h      = (const float*)d_in[3];
    const float* c      = (const float*)d_in[4];
    const float* Wx     = (const float*)d_in[5];
    const float* Wh     = (const float*)d_in[6];
    const float* bh     = (const float*)d_in[7];
    const float* Wa     = (const float*)d_in[8];
    const float* ba     = (const float*)d_in[9];
    const float* Wv     = (const float*)d_in[10];
    const float* bv     = (const float*)d_in[11];
    float* out = (float*)d_out;

    static bool attr_set = false;
    if (!attr_set) {
        cudaFuncSetAttribute(lstm_mma, cudaFuncAttributeMaxDynamicSharedMemorySize, SMEM_SZ);
        cudaFuncSetAttribute(heads_mma, cudaFuncAttributeMaxDynamicSharedMemorySize, H_SMEM);
        attr_set = true;
    }

    // order chosen so lstm_mma sits in the ncu-profiled 4th slot
    convX<<<(BATCH * KP + 255) / 256, 256>>>(s, a_prev);
    convW<<<dim3(FOURH / 32, KP / 64), dim3(32, 8)>>>(Wx);
    vb_partial<<<dim3(FOURH / 256, VB_CH), 256>>>(h, Wh);
    lstm_mma<<<dim3(HDIM / 32, BATCH / 128), 256, SMEM_SZ>>>(
        c, r_prev, Wx + (size_t)(KDIM - 1) * FOURH, bh);
    convA<<<HDIM / 64, 256>>>(Wa);
    heads_mma<<<BATCH / 32, 256, H_SMEM>>>(Wv, ba, bv, out);
}

// round 11
// speedup vs baseline: 6.0815x; 1.1777x over previous
#include <cuda_runtime.h>
#include <cuda_fp16.h>
#include <math.h>
#include <cstdint>

#define BATCH 4096
#define SDIM  512
#define ADIM  64
#define HDIM  2048
#define KDIM  577
#define KP    576           // s(512) + a(64); reward column folded rank-1 in epilogue
#define NCH   9
#define FOURH 8192
#define VB_CH 32

// ---------------- scratch (static device globals) ----------------
__device__ __half g_x[BATCH * KP];      // fp16 packed [s|a]
__device__ __half g_w[FOURH * KP];      // gate-interleaved rows n' = j*4 + g, K-major
__device__ __half g_wa[64 * HDIM];      // Wa transposed [n][k] K-major fp16
__device__ float g_vbp[VB_CH * FOURH];  // k-split partials of h @ Wh
__device__ __half g_hf[BATCH * HDIM];   // h_new in fp16

__device__ __forceinline__ uint32_t smem_u32(const void* p) {
    uint32_t a;
    asm("{ .reg .u64 t; cvta.to.shared.u64 t, %1; cvt.u32.u64 %0, t; }" : "=r"(a) : "l"(p));
    return a;
}
#define SWZ128(off) ((off) ^ (((off) >> 3) & 0x70))

__device__ __forceinline__ void cpa16(uint32_t smem, const void* g) {
    asm volatile("cp.async.cg.shared.global [%0], [%1], 16;" :: "r"(smem), "l"(g));
}
#define CPA_COMMIT()  asm volatile("cp.async.commit_group;" ::: "memory")
#define CPA_WAIT(n)   asm volatile("cp.async.wait_group %0;" :: "n"(n) : "memory")

__device__ __forceinline__ void ldmx4(uint32_t* r, uint32_t addr) {
    asm volatile("ldmatrix.sync.aligned.m8n8.x4.shared.b16 {%0,%1,%2,%3}, [%4];"
                 : "=r"(r[0]), "=r"(r[1]), "=r"(r[2]), "=r"(r[3]) : "r"(addr));
}
__device__ __forceinline__ void ldmx2(uint32_t* r, uint32_t addr) {
    asm volatile("ldmatrix.sync.aligned.m8n8.x2.shared.b16 {%0,%1}, [%2];"
                 : "=r"(r[0]), "=r"(r[1]) : "r"(addr));
}
__device__ __forceinline__ void mma16816(float* c, const uint32_t* a, const uint32_t* b) {
    asm volatile(
        "mma.sync.aligned.m16n8k16.row.col.f32.f16.f16.f32 "
        "{%0,%1,%2,%3}, {%4,%5,%6,%7}, {%8,%9}, {%0,%1,%2,%3};"
        : "+f"(c[0]), "+f"(c[1]), "+f"(c[2]), "+f"(c[3])
        : "r"(a[0]), "r"(a[1]), "r"(a[2]), "r"(a[3]), "r"(b[0]), "r"(b[1]));
}

// fast gate math: err ~1e-6, saturates correctly (exp->inf => tanh->1, exp->0 => -1)
__device__ __forceinline__ float fsig(float x) {
    return __fdividef(1.0f, 1.0f + __expf(-x));
}
__device__ __forceinline__ float ftanh(float x) {
    return 1.0f - __fdividef(2.0f, __expf(2.0f * x) + 1.0f);
}

// ---------------------------------------------------------------------------
// convX: pack [s|a] -> fp16 [BATCH x 576]
// ---------------------------------------------------------------------------
__global__ void convX(const float* __restrict__ s, const float* __restrict__ a) {
    int idx = blockIdx.x * 256 + threadIdx.x;
    if (idx >= BATCH * KP) return;
    int b = idx / KP;
    int k = idx - b * KP;
    float v = (k < SDIM) ? s[b * SDIM + k] : a[b * ADIM + (k - SDIM)];
    g_x[idx] = __float2half_rn(v);
}

// ---------------------------------------------------------------------------
// convW: Wx rows 0..575 -> K-major fp16, gate-interleaved n' = (n&2047)*4 + (n>>11)
// ---------------------------------------------------------------------------
__global__ void convW(const float* __restrict__ Wx) {
    __shared__ float t[64][33];
    int n0 = blockIdx.x * 32;
    int k0 = blockIdx.y * 64;
    int tx = threadIdx.x, ty = threadIdx.y;       // (32, 8)
#pragma unroll
    for (int i = 0; i < 8; i++) {
        int kl = ty * 8 + i;
        t[kl][tx] = Wx[(size_t)(k0 + kl) * FOURH + n0 + tx];
    }
    __syncthreads();
    int tid = ty * 32 + tx;
    int nl  = tid >> 3;
    int ch  = tid & 7;
    int n   = n0 + nl;
    size_t np = (size_t)(n & 2047) * 4 + (n >> 11);
    uint4 vh;
    __half* ph = (__half*)&vh;
#pragma unroll
    for (int u = 0; u < 8; u++)
        ph[u] = __float2half_rn(t[ch * 8 + u][nl]);
    *(uint4*)&g_w[np * KP + k0 + ch * 8] = vh;
}

// ---------------------------------------------------------------------------
// convA: Wa [2048 x 64] -> g_wa [64 x 2048] K-major fp16
// ---------------------------------------------------------------------------
__global__ void convA(const float* __restrict__ Wa) {
    __shared__ float t[64][65];
    int k0 = blockIdx.x * 64;
    int tid = threadIdx.x;       // 256
#pragma unroll
    for (int i = 0; i < 16; i++) {
        int e = tid + i * 256;
        int kl = e >> 6, n = e & 63;
        t[kl][n] = Wa[(size_t)(k0 + kl) * 64 + n];
    }
    __syncthreads();
    int n = tid >> 2, kq = (tid & 3) * 16;
    uint4 v[2];
    __half* ph = (__half*)v;
#pragma unroll
    for (int u = 0; u < 16; u++)
        ph[u] = __float2half_rn(t[kq + u][n]);
    *(uint4*)&g_wa[(size_t)n * HDIM + k0 + kq]     = v[0];
    *(uint4*)&g_wa[(size_t)n * HDIM + k0 + kq + 8] = v[1];
}

// ---------------------------------------------------------------------------
// vb_partial: vbp[kc][j] = sum_{k in 64-chunk kc} h[k] * Wh[k][j]
// ---------------------------------------------------------------------------
__global__ void vb_partial(const float* __restrict__ h, const float* __restrict__ Wh) {
    int j  = blockIdx.x * 256 + threadIdx.x;
    int k0 = blockIdx.y * 64;
    float acc = 0.0f;
#pragma unroll 16
    for (int k = 0; k < 64; k++)
        acc += h[k0 + k] * __ldg(&Wh[(size_t)(k0 + k) * FOURH + j]);
    g_vbp[blockIdx.y * FOURH + j] = acc;
}

// ---------------------------------------------------------------------------
// lstm_mma: HMMA GEMM + LSTM gate epilogue. (profiled slot #4)
// ---------------------------------------------------------------------------
#define ST_A   0
#define ST_B   16384
#define ST_STRIDE 32768
#define SVB_OFF  (3 * ST_STRIDE)
#define SMEM_SZ  (3 * ST_STRIDE + 512)

__global__ __launch_bounds__(256, 2) void lstm_mma(const float* __restrict__ cvec,
                                                   const float* __restrict__ rp,
                                                   const float* __restrict__ w576,
                                                   const float* __restrict__ bh) {
    extern __shared__ char smem[];
    uint32_t sb = smem_u32(smem);
    int tid  = threadIdx.x;
    int lane = tid & 31, w = tid >> 5;
    int wm = w & 1, wn = w >> 1;          // 2 x 4 warp grid
    int row0 = blockIdx.y * 128;
    int j0   = blockIdx.x * 32;

    int lr = lane & 7, ls = lane >> 3;
    uint32_t a_row = wm * 64 + lr + (ls & 1) * 8;   // + mt*16
    uint32_t a_chs = (uint32_t)(ls >> 1);           // col 16B-slot within kstep
    uint32_t b_row = wn * 32 + lr;                  // + nt*8

    // swizzled bases (sa folded per chunk); XOR with kstep offsets is exact:
    // low 7 bits of stage base are 0, XOR footprint is bits 4-6.
    uint32_t pa0 = ST_A + (((a_row * 128) | ((a_row * 16) & 0x70)) ^ (a_chs << 4));
    uint32_t pb0 = ST_B + (((b_row * 128) | ((b_row * 16) & 0x70)) ^ ((uint32_t)ls << 4));

    uint32_t sw0 = SWZ128((uint32_t)((tid >> 3) * 128 + (tid & 7) * 16));
    const __half* px = g_x + (size_t)(row0 + (tid >> 3)) * KP + (tid & 7) * 8;
    const __half* pw = g_w + (size_t)(j0 * 4 + (tid >> 3)) * KP + (tid & 7) * 8;

    float acc[4][4][4];
#pragma unroll
    for (int mt = 0; mt < 4; mt++)
#pragma unroll
        for (int nt = 0; nt < 4; nt++)
#pragma unroll
            for (int i = 0; i < 4; i++) acc[mt][nt][i] = 0.0f;

#pragma unroll
    for (int st = 0; st < 2; st++) {      // prologue: chunks 0,1
        uint32_t base = sb + st * ST_STRIDE;
#pragma unroll
        for (int i = 0; i < 4; i++) {
            cpa16(base + ST_A + sw0 + i * 4096, px + (size_t)i * 32 * KP + st * 64);
            cpa16(base + ST_B + sw0 + i * 4096, pw + (size_t)i * 32 * KP + st * 64);
        }
        CPA_COMMIT();
    }

    // fused vb reduce (overlaps prologue cp.async)
    float* svb = (float*)(smem + SVB_OFF);
    if (tid < 128) {
        int j = (tid >> 5) * HDIM + j0 + (tid & 31);
        float acc_vb = __ldg(&bh[j]);
#pragma unroll
        for (int kc = 0; kc < VB_CH; kc++) acc_vb += g_vbp[kc * FOURH + j];
        svb[tid] = acc_vb;
    }

    for (int t = 0; t < NCH; t++) {
        if (t == NCH - 1) { CPA_WAIT(0); } else { CPA_WAIT(1); }
        __syncthreads();

        if (t + 2 < NCH) {
            uint32_t base = sb + ((t + 2) % 3) * ST_STRIDE;
            int kg = (t + 2) * 64;
#pragma unroll
            for (int i = 0; i < 4; i++) {
                cpa16(base + ST_A + sw0 + i * 4096, px + (size_t)i * 32 * KP + kg);
                cpa16(base + ST_B + sw0 + i * 4096, pw + (size_t)i * 32 * KP + kg);
            }
            CPA_COMMIT();
        }

        uint32_t sa = sb + (t % 3) * ST_STRIDE;
        uint32_t aA[4], aB[4];
#pragma unroll
        for (int mt = 0; mt < 4; mt++) aA[mt] = sa + pa0 + mt * 2048;
#pragma unroll
        for (int nt = 0; nt < 4; nt++) aB[nt] = sa + pb0 + nt * 1024;

#pragma unroll
        for (int half = 0; half < 2; half++) {       // 2 ksteps per half
            uint32_t hoff = (uint32_t)(half << 6);   // 0 or 64
            uint32_t bb[4][4];                       // [nt][2 ksteps x 2 regs]
#pragma unroll
            for (int nt = 0; nt < 4; nt++)
                ldmx4(bb[nt], aB[nt] ^ hoff);
#pragma unroll
            for (int ks = 0; ks < 2; ks++) {
                uint32_t koff = hoff + (uint32_t)(ks << 5);
#pragma unroll
                for (int mt = 0; mt < 4; mt++) {
                    uint32_t aa[4];
                    ldmx4(aa, aA[mt] ^ koff);
#pragma unroll
                    for (int nt = 0; nt < 4; nt++)
                        mma16816(acc[mt][nt], aa, &bb[nt][ks * 2]);
                }
            }
        }
    }
    __syncthreads();

    // ---- epilogue: + vb + r*w576 (exact fp32), fast gate math, fp16 store ----
    int q = lane & 3;
    int gp = q & 1;
    int jsel = q >> 1;
    float* hsm = (float*)smem;

    float r0v[4], r1v[4];
#pragma unroll
    for (int mt = 0; mt < 4; mt++) {
        int rw = wm * 64 + mt * 16 + (lane >> 2);
        r0v[mt] = __ldg(&rp[row0 + rw]);
        r1v[mt] = __ldg(&rp[row0 + rw + 8]);
    }

#pragma unroll
    for (int nt = 0; nt < 4; nt++) {
        int jl = wn * 8 + nt * 2 + jsel;
        int j  = j0 + jl;
        float vbi = svb[jl];
        float vbf = svb[32 + jl];
        float vbg = svb[64 + jl];
        float vbo = svb[96 + jl];
        float w5i = __ldg(&w576[j]);
        float w5f = __ldg(&w576[HDIM + j]);
        float w5g = __ldg(&w576[2 * HDIM + j]);
        float w5o = __ldg(&w576[3 * HDIM + j]);
        float cj  = __ldg(&cvec[j]);
#pragma unroll
        for (int mt = 0; mt < 4; mt++) {
            float r0 = r0v[mt], r1 = r1v[mt];
            float v0 = acc[mt][nt][0], v1 = acc[mt][nt][1];
            float v2 = acc[mt][nt][2], v3 = acc[mt][nt][3];
            float p0 = __shfl_xor_sync(0xFFFFFFFFu, v0, 1);
            float p1 = __shfl_xor_sync(0xFFFFFFFFu, v1, 1);
            float p2 = __shfl_xor_sync(0xFFFFFFFFu, v2, 1);
            float p3 = __shfl_xor_sync(0xFFFFFFFFu, v3, 1);
            float zi0 = gp ? p0 : v0, zf0 = gp ? p1 : v1;
            float zg0 = gp ? v0 : p0, zo0 = gp ? v1 : p1;
            float zi1 = gp ? p2 : v2, zf1 = gp ? p3 : v3;
            float zg1 = gp ? v2 : p2, zo1 = gp ? v3 : p3;

            zi0 += vbi + r0 * w5i; zf0 += vbf + r0 * w5f;
            zg0 += vbg + r0 * w5g; zo0 += vbo + r0 * w5o;
            zi1 += vbi + r1 * w5i; zf1 += vbf + r1 * w5f;
            zg1 += vbg + r1 * w5g; zo1 += vbo + r1 * w5o;

            float c0 = fsig(zf0) * cj + fsig(zi0) * ftanh(zg0);
            float h0 = fsig(zo0) * ftanh(c0);
            float c1 = fsig(zf1) * cj + fsig(zi1) * ftanh(zg1);
            float h1 = fsig(zo1) * ftanh(c1);

            if (gp == 0) {
                int rw = wm * 64 + mt * 16 + (lane >> 2);
                hsm[rw * 33 + jl]       = h0;
                hsm[(rw + 8) * 33 + jl] = h1;
            }
        }
    }
    __syncthreads();

#pragma unroll
    for (int i = 0; i < 8; i++) {
        int slot = tid + i * 256;
        int rw = slot >> 4, c2 = (slot & 15) * 2;
        __half2 hv = __floats2half2_rn(hsm[rw * 33 + c2], hsm[rw * 33 + c2 + 1]);
        *(__half2*)(g_hf + (size_t)(row0 + rw) * HDIM + j0 + c2) = hv;
    }
}

// ---------------------------------------------------------------------------
// heads_mma: logits = h @ Wa via HMMA; softmax; value SIMT over fp16 h.
// ---------------------------------------------------------------------------
#define H_STA 0
#define H_STB 4096
#define H_STRIDE 12288
#define H_NCH 32
#define H_SMEM (3 * H_STRIDE + 8192)
#define H_WV_OFF (3 * H_STRIDE)

__global__ __launch_bounds__(256, 2) void heads_mma(const float* __restrict__ Wv,
                                                    const float* __restrict__ ba,
                                                    const float* __restrict__ bv,
                                                    float* __restrict__ out) {
    extern __shared__ char smem[];
    uint32_t sb = smem_u32(smem);
    int tid  = threadIdx.x;
    int lane = tid & 31, w = tid >> 5;
    int wm = w & 1, wn = w >> 1;
    int row0 = blockIdx.x * 32;

    int lr = lane & 7, ls = lane >> 3;
    uint32_t a_row = wm * 16 + lr + (ls & 1) * 8;
    uint32_t a_chs = (uint32_t)(ls >> 1);
    uint32_t b_row = wn * 16 + lr;
    uint32_t b_chs = (uint32_t)(ls & 1);

    uint32_t pa0 = H_STA + (((a_row * 128) | ((a_row * 16) & 0x70)) ^ (a_chs << 4));
    uint32_t pb0 = H_STB + (((b_row * 128) | ((b_row * 16) & 0x70)) ^ (b_chs << 4));

    uint32_t sw0 = SWZ128((uint32_t)((tid >> 3) * 128 + (tid & 7) * 16));
    const __half* ph = g_hf + (size_t)(row0 + (tid >> 3)) * HDIM + (tid & 7) * 8;
    const __half* pa = g_wa + (size_t)(tid >> 3) * HDIM + (tid & 7) * 8;

    float acc[2][4];
#pragma unroll
    for (int nt = 0; nt < 2; nt++)
#pragma unroll
        for (int i = 0; i < 4; i++) acc[nt][i] = 0.0f;

#pragma unroll
    for (int st = 0; st < 2; st++) {
        uint32_t base = sb + st * H_STRIDE;
        cpa16(base + H_STA + sw0, ph + st * 64);
#pragma unroll
        for (int i = 0; i < 2; i++)
            cpa16(base + H_STB + sw0 + i * 4096, pa + (size_t)i * 32 * HDIM + st * 64);
        CPA_COMMIT();
    }

    for (int t = 0; t < H_NCH; t++) {
        if (t == H_NCH - 1) { CPA_WAIT(0); } else { CPA_WAIT(1); }
        __syncthreads();

        if (t + 2 < H_NCH) {
            uint32_t base = sb + ((t + 2) % 3) * H_STRIDE;
            int kg = (t + 2) * 64;
            cpa16(base + H_STA + sw0, ph + kg);
#pragma unroll
            for (int i = 0; i < 2; i++)
                cpa16(base + H_STB + sw0 + i * 4096, pa + (size_t)i * 32 * HDIM + kg);
            CPA_COMMIT();
        }

        uint32_t sa = sb + (t % 3) * H_STRIDE;
#pragma unroll
        for (int kb = 0; kb < 8; kb += 2) {
            uint32_t koff = (uint32_t)(kb << 4);
            uint32_t aa[4];
            ldmx4(aa, sa + (pa0 ^ koff));
#pragma unroll
            for (int nt = 0; nt < 2; nt++) {
                uint32_t bb[2];
                ldmx2(bb, sa + ((pb0 + nt * 1024) ^ koff));
                mma16816(acc[nt], aa, bb);
            }
        }
    }
    __syncthreads();

    float* lsm = (float*)smem;
    float* wvs = (float*)(smem + H_WV_OFF);
    {
        int r = wm * 16 + (lane >> 2);
#pragma unroll
        for (int nt = 0; nt < 2; nt++) {
            int c = wn * 16 + nt * 8 + (lane & 3) * 2;
            lsm[r * 65 + c]           = acc[nt][0];
            lsm[r * 65 + c + 1]       = acc[nt][1];
            lsm[(r + 8) * 65 + c]     = acc[nt][2];
            lsm[(r + 8) * 65 + c + 1] = acc[nt][3];
        }
    }
#pragma unroll
    for (int i = 0; i < 2; i++) {
        int e = tid + i * 256;
        *(float4*)&wvs[e * 4] = *(const float4*)&Wv[e * 4];
    }
    __syncthreads();

    int rowt = tid >> 3, ag = tid & 7;
    float l[8];
    float m = -INFINITY;
#pragma unroll
    for (int a = 0; a < 8; a++) {
        l[a] = lsm[rowt * 65 + ag * 8 + a] + __ldg(&ba[ag * 8 + a]);
        m = fmaxf(m, l[a]);
    }
#pragma unroll
    for (int off = 4; off > 0; off >>= 1)
        m = fmaxf(m, __shfl_xor_sync(0xFFFFFFFFu, m, off, 8));
    float sum = 0.0f;
#pragma unroll
    for (int a = 0; a < 8; a++) {
        l[a] = __expf(l[a] - m);
        sum += l[a];
    }
#pragma unroll
    for (int off = 4; off > 0; off >>= 1)
        sum += __shfl_xor_sync(0xFFFFFFFFu, sum, off, 8);
    float inv = __fdividef(1.0f, sum);
    int row = row0 + rowt;
#pragma unroll
    for (int a = 0; a < 8; a++)
        out[(size_t)row * 64 + ag * 8 + a] = l[a] * inv;

    float vacc = 0.0f;
    const __half* hrow = g_hf + (size_t)row * HDIM + ag * 256;
#pragma unroll 4
    for (int u = 0; u < 32; u++) {
        uint4 hv = *(const uint4*)(hrow + u * 8);
        __half2* h2 = (__half2*)&hv;
        int kb = ag * 256 + u * 8;
#pragma unroll
        for (int p = 0; p < 4; p++) {
            float2 f = __half22float2(h2[p]);
            vacc += f.x * wvs[kb + p * 2];
            vacc += f.y * wvs[kb + p * 2 + 1];
        }
    }
#pragma unroll
    for (int off = 4; off > 0; off >>= 1)
        vacc += __shfl_xor_sync(0xFFFFFFFFu, vacc, off, 8);
    if (ag == 0)
        out[(size_t)BATCH * 64 + row] = vacc + __ldg(&bv[0]);
}

// ---------------------------------------------------------------------------
extern "C" void kernel_launch(void* const* d_in, const int* in_sizes, int n_in,
                              void* d_out, int out_size) {
    const float* s      = (const float*)d_in[0];
    const float* a_prev = (const float*)d_in[1];
    const float* r_prev = (const float*)d_in[2];
    const float* h      = (const float*)d_in[3];
    const float* c      = (const float*)d_in[4];
    const float* Wx     = (const float*)d_in[5];
    const float* Wh     = (const float*)d_in[6];
    const float* bh     = (const float*)d_in[7];
    const float* Wa     = (const float*)d_in[8];
    const float* ba     = (const float*)d_in[9];
    const float* Wv     = (const float*)d_in[10];
    const float* bv     = (const float*)d_in[11];
    float* out = (float*)d_out;

    static bool attr_set = false;
    if (!attr_set) {
        cudaFuncSetAttribute(lstm_mma, cudaFuncAttributeMaxDynamicSharedMemorySize, SMEM_SZ);
        cudaFuncSetAttribute(heads_mma, cudaFuncAttributeMaxDynamicSharedMemorySize, H_SMEM);
        attr_set = true;
    }

    // order keeps lstm_mma in the ncu-profiled 4th slot
    convX<<<(BATCH * KP + 255) / 256, 256>>>(s, a_prev);
    convW<<<dim3(FOURH / 32, KP / 64), dim3(32, 8)>>>(Wx);
    vb_partial<<<dim3(FOURH / 256, VB_CH), 256>>>(h, Wh);
    lstm_mma<<<dim3(HDIM / 32, BATCH / 128), 256, SMEM_SZ>>>(
        c, r_prev, Wx + (size_t)(KDIM - 1) * FOURH, bh);
    convA<<<HDIM / 64, 256>>>(Wa);
    heads_mma<<<BATCH / 32, 256, H_SMEM>>>(Wv, ba, bv, out);
}

// round 12
// speedup vs baseline: 6.8762x; 1.1307x over previous
#include <cuda_runtime.h>
#include <cuda_fp16.h>
#include <math.h>
#include <cstdint>

#define BATCH 4096
#define SDIM  512
#define ADIM  64
#define HDIM  2048
#define KDIM  577
#define KP    576           // s(512) + a(64); reward column folded rank-1 in epilogue
#define NCH   9
#define FOURH 8192
#define VB_CH 32

// ---------------- scratch (static device globals) ----------------
__device__ __half g_x[BATCH * KP];      // fp16 packed [s|a]
__device__ __half g_w[FOURH * KP];      // gate-interleaved rows n' = j*4 + g, K-major
__device__ __half g_wa[64 * HDIM];      // Wa transposed [n][k] K-major fp16
__device__ float g_vbp[VB_CH * FOURH];  // k-split partials of h @ Wh
__device__ __half g_hf[BATCH * HDIM];   // h_new in fp16

__device__ __forceinline__ uint32_t smem_u32(const void* p) {
    uint32_t a;
    asm("{ .reg .u64 t; cvta.to.shared.u64 t, %1; cvt.u32.u64 %0, t; }" : "=r"(a) : "l"(p));
    return a;
}
#define SWZ128(off) ((off) ^ (((off) >> 3) & 0x70))

__device__ __forceinline__ void cpa16(uint32_t smem, const void* g) {
    asm volatile("cp.async.cg.shared.global [%0], [%1], 16;" :: "r"(smem), "l"(g));
}
#define CPA_COMMIT()  asm volatile("cp.async.commit_group;" ::: "memory")
#define CPA_WAIT(n)   asm volatile("cp.async.wait_group %0;" :: "n"(n) : "memory")

__device__ __forceinline__ void ldmx4(uint32_t* r, uint32_t addr) {
    asm volatile("ldmatrix.sync.aligned.m8n8.x4.shared.b16 {%0,%1,%2,%3}, [%4];"
                 : "=r"(r[0]), "=r"(r[1]), "=r"(r[2]), "=r"(r[3]) : "r"(addr));
}
__device__ __forceinline__ void ldmx2(uint32_t* r, uint32_t addr) {
    asm volatile("ldmatrix.sync.aligned.m8n8.x2.shared.b16 {%0,%1}, [%2];"
                 : "=r"(r[0]), "=r"(r[1]) : "r"(addr));
}
__device__ __forceinline__ void mma16816(float* c, const uint32_t* a, const uint32_t* b) {
    asm volatile(
        "mma.sync.aligned.m16n8k16.row.col.f32.f16.f16.f32 "
        "{%0,%1,%2,%3}, {%4,%5,%6,%7}, {%8,%9}, {%0,%1,%2,%3};"
        : "+f"(c[0]), "+f"(c[1]), "+f"(c[2]), "+f"(c[3])
        : "r"(a[0]), "r"(a[1]), "r"(a[2]), "r"(a[3]), "r"(b[0]), "r"(b[1]));
}

// fast gate math
__device__ __forceinline__ float fsig(float x) {
    return __fdividef(1.0f, 1.0f + __expf(-x));
}
__device__ __forceinline__ float ftanh(float x) {
    return 1.0f - __fdividef(2.0f, __expf(2.0f * x) + 1.0f);
}

// ---------------------------------------------------------------------------
// prep: fused vb_partial + convW + convA + convX (block-range dispatch)
//   [0, 1024)      vb_partial   (32 j-blocks x 32 k-chunks)
//   [1024, 3328)   convW        (256 n-blocks x 9 k-blocks)
//   [3328, 3360)   convA        (32 k-blocks)
//   [3360, 4512)   convX        (1152 blocks, 8 halfs/thread)
// ---------------------------------------------------------------------------
#define PREP_BLOCKS 4512

__global__ __launch_bounds__(256) void prep(const float* __restrict__ s,
                                            const float* __restrict__ a,
                                            const float* __restrict__ h,
                                            const float* __restrict__ Wh,
                                            const float* __restrict__ Wx,
                                            const float* __restrict__ Wa) {
    __shared__ float t[64][65];      // convA needs [64][65]; convW uses [64][33] slice
    int bid = blockIdx.x;
    int tid = threadIdx.x;

    if (bid < 1024) {
        // ---- vb_partial ----
        int j  = (bid & 31) * 256 + tid;
        int k0 = (bid >> 5) * 64;
        float acc = 0.0f;
#pragma unroll 16
        for (int k = 0; k < 64; k++)
            acc += h[k0 + k] * __ldg(&Wh[(size_t)(k0 + k) * FOURH + j]);
        g_vbp[(bid >> 5) * FOURH + j] = acc;
    } else if (bid < 3328) {
        // ---- convW: Wx -> K-major fp16, gate-interleaved ----
        int b  = bid - 1024;
        int n0 = (b & 255) * 32;
        int k0 = (b >> 8) * 64;
        int tx = tid & 31, ty = tid >> 5;
#pragma unroll
        for (int i = 0; i < 8; i++) {
            int kl = ty * 8 + i;
            t[kl][tx] = Wx[(size_t)(k0 + kl) * FOURH + n0 + tx];
        }
        __syncthreads();
        int nl = tid >> 3;
        int ch = tid & 7;
        int n  = n0 + nl;
        size_t np = (size_t)(n & 2047) * 4 + (n >> 11);
        uint4 vh;
        __half* ph = (__half*)&vh;
#pragma unroll
        for (int u = 0; u < 8; u++)
            ph[u] = __float2half_rn(t[ch * 8 + u][nl]);
        *(uint4*)&g_w[np * KP + k0 + ch * 8] = vh;
    } else if (bid < 3360) {
        // ---- convA: Wa [2048 x 64] -> g_wa [64 x 2048] K-major fp16 ----
        int k0 = (bid - 3328) * 64;
#pragma unroll
        for (int i = 0; i < 16; i++) {
            int e = tid + i * 256;
            int kl = e >> 6, n = e & 63;
            t[kl][n] = Wa[(size_t)(k0 + kl) * 64 + n];
        }
        __syncthreads();
        int n = tid >> 2, kq = (tid & 3) * 16;
        uint4 v[2];
        __half* ph = (__half*)v;
#pragma unroll
        for (int u = 0; u < 16; u++)
            ph[u] = __float2half_rn(t[kq + u][n]);
        *(uint4*)&g_wa[(size_t)n * HDIM + k0 + kq]     = v[0];
        *(uint4*)&g_wa[(size_t)n * HDIM + k0 + kq + 8] = v[1];
    } else {
        // ---- convX: pack [s|a] -> fp16, 8 halfs per thread ----
        int gid = (bid - 3360) * 256 + tid;       // 0 .. 294911
        int b = gid / 72, kc = gid - b * 72;
        int k0 = kc * 8;
        float4 f0, f1;
        if (k0 < SDIM) {
            f0 = *(const float4*)&s[(size_t)b * SDIM + k0];
            f1 = *(const float4*)&s[(size_t)b * SDIM + k0 + 4];
        } else {
            f0 = *(const float4*)&a[(size_t)b * ADIM + (k0 - SDIM)];
            f1 = *(const float4*)&a[(size_t)b * ADIM + (k0 - SDIM) + 4];
        }
        uint4 o;
        __half* ph = (__half*)&o;
        ph[0] = __float2half_rn(f0.x); ph[1] = __float2half_rn(f0.y);
        ph[2] = __float2half_rn(f0.z); ph[3] = __float2half_rn(f0.w);
        ph[4] = __float2half_rn(f1.x); ph[5] = __float2half_rn(f1.y);
        ph[6] = __float2half_rn(f1.z); ph[7] = __float2half_rn(f1.w);
        *(uint4*)&g_x[(size_t)b * KP + k0] = o;
    }
}

// ---------------------------------------------------------------------------
// lstm_mma: HMMA GEMM + LSTM gate epilogue (work-split between lane pairs).
// ---------------------------------------------------------------------------
#define ST_A   0
#define ST_B   16384
#define ST_STRIDE 32768
#define SVB_OFF  (3 * ST_STRIDE)
#define SMEM_SZ  (3 * ST_STRIDE + 512)

__global__ __launch_bounds__(256, 2) void lstm_mma(const float* __restrict__ cvec,
                                                   const float* __restrict__ rp,
                                                   const float* __restrict__ w576,
                                                   const float* __restrict__ bh) {
    extern __shared__ char smem[];
    uint32_t sb = smem_u32(smem);
    int tid  = threadIdx.x;
    int lane = tid & 31, w = tid >> 5;
    int wm = w & 1, wn = w >> 1;          // 2 x 4 warp grid
    int row0 = blockIdx.y * 128;
    int j0   = blockIdx.x * 32;

    int lr = lane & 7, ls = lane >> 3;
    uint32_t a_row = wm * 64 + lr + (ls & 1) * 8;   // + mt*16
    uint32_t a_chs = (uint32_t)(ls >> 1);
    uint32_t b_row = wn * 32 + lr;                  // + nt*8

    uint32_t pa0 = ST_A + (((a_row * 128) | ((a_row * 16) & 0x70)) ^ (a_chs << 4));
    uint32_t pb0 = ST_B + (((b_row * 128) | ((b_row * 16) & 0x70)) ^ ((uint32_t)ls << 4));

    uint32_t sw0 = SWZ128((uint32_t)((tid >> 3) * 128 + (tid & 7) * 16));
    const __half* px = g_x + (size_t)(row0 + (tid >> 3)) * KP + (tid & 7) * 8;
    const __half* pw = g_w + (size_t)(j0 * 4 + (tid >> 3)) * KP + (tid & 7) * 8;

    float acc[4][4][4];
#pragma unroll
    for (int mt = 0; mt < 4; mt++)
#pragma unroll
        for (int nt = 0; nt < 4; nt++)
#pragma unroll
            for (int i = 0; i < 4; i++) acc[mt][nt][i] = 0.0f;

#pragma unroll
    for (int st = 0; st < 2; st++) {      // prologue: chunks 0,1
        uint32_t base = sb + st * ST_STRIDE;
#pragma unroll
        for (int i = 0; i < 4; i++) {
            cpa16(base + ST_A + sw0 + i * 4096, px + (size_t)i * 32 * KP + st * 64);
            cpa16(base + ST_B + sw0 + i * 4096, pw + (size_t)i * 32 * KP + st * 64);
        }
        CPA_COMMIT();
    }

    // fused vb reduce (overlaps prologue cp.async)
    float* svb = (float*)(smem + SVB_OFF);
    if (tid < 128) {
        int j = (tid >> 5) * HDIM + j0 + (tid & 31);
        float acc_vb = __ldg(&bh[j]);
#pragma unroll
        for (int kc = 0; kc < VB_CH; kc++) acc_vb += g_vbp[kc * FOURH + j];
        svb[tid] = acc_vb;
    }

    for (int t = 0; t < NCH; t++) {
        if (t == NCH - 1) { CPA_WAIT(0); } else { CPA_WAIT(1); }
        __syncthreads();

        if (t + 2 < NCH) {
            uint32_t base = sb + ((t + 2) % 3) * ST_STRIDE;
            int kg = (t + 2) * 64;
#pragma unroll
            for (int i = 0; i < 4; i++) {
                cpa16(base + ST_A + sw0 + i * 4096, px + (size_t)i * 32 * KP + kg);
                cpa16(base + ST_B + sw0 + i * 4096, pw + (size_t)i * 32 * KP + kg);
            }
            CPA_COMMIT();
        }

        uint32_t sa = sb + (t % 3) * ST_STRIDE;
        uint32_t aA[4], aB[4];
#pragma unroll
        for (int mt = 0; mt < 4; mt++) aA[mt] = sa + pa0 + mt * 2048;
#pragma unroll
        for (int nt = 0; nt < 4; nt++) aB[nt] = sa + pb0 + nt * 1024;

#pragma unroll
        for (int half = 0; half < 2; half++) {
            uint32_t hoff = (uint32_t)(half << 6);
            uint32_t bb[4][4];
#pragma unroll
            for (int nt = 0; nt < 4; nt++)
                ldmx4(bb[nt], aB[nt] ^ hoff);
#pragma unroll
            for (int ks = 0; ks < 2; ks++) {
                uint32_t koff = hoff + (uint32_t)(ks << 5);
#pragma unroll
                for (int mt = 0; mt < 4; mt++) {
                    uint32_t aa[4];
                    ldmx4(aa, aA[mt] ^ koff);
#pragma unroll
                    for (int nt = 0; nt < 4; nt++)
                        mma16816(acc[mt][nt], aa, &bb[nt][ks * 2]);
                }
            }
        }
    }
    __syncthreads();

    // ---- epilogue: work-split — gp==0 computes row rw, gp==1 row rw+8 ----
    int q = lane & 3;
    int gp = q & 1;            // 0: lane holds (zi,zf); 1: (zg,zo)
    int jsel = q >> 1;
    float* hsm = (float*)smem;

    float rv[4];
#pragma unroll
    for (int mt = 0; mt < 4; mt++) {
        int rw = wm * 64 + mt * 16 + (lane >> 2) + (gp ? 8 : 0);
        rv[mt] = __ldg(&rp[row0 + rw]);
    }

#pragma unroll
    for (int nt = 0; nt < 4; nt++) {
        int jl = wn * 8 + nt * 2 + jsel;
        int j  = j0 + jl;
        float vbi = svb[jl];
        float vbf = svb[32 + jl];
        float vbg = svb[64 + jl];
        float vbo = svb[96 + jl];
        float w5i = __ldg(&w576[j]);
        float w5f = __ldg(&w576[HDIM + j]);
        float w5g = __ldg(&w576[2 * HDIM + j]);
        float w5o = __ldg(&w576[3 * HDIM + j]);
        float cj  = __ldg(&cvec[j]);
#pragma unroll
        for (int mt = 0; mt < 4; mt++) {
            float v0 = acc[mt][nt][0], v1 = acc[mt][nt][1];
            float v2 = acc[mt][nt][2], v3 = acc[mt][nt][3];
            float p0 = __shfl_xor_sync(0xFFFFFFFFu, v0, 1);
            float p1 = __shfl_xor_sync(0xFFFFFFFFu, v1, 1);
            float p2 = __shfl_xor_sync(0xFFFFFFFFu, v2, 1);
            float p3 = __shfl_xor_sync(0xFFFFFFFFu, v3, 1);
            // gp==0: own (zi0,zf0,zi1,zf1), partner has (zg,zo) -> compute row rw
            // gp==1: own (zg0,zo0,zg1,zo1), partner has (zi,zf) -> compute row rw+8
            float zi = gp ? p2 : v0;
            float zf = gp ? p3 : v1;
            float zg = gp ? v2 : p0;
            float zo = gp ? v3 : p1;

            float r = rv[mt];
            zi += vbi + r * w5i;
            zf += vbf + r * w5f;
            zg += vbg + r * w5g;
            zo += vbo + r * w5o;

            float cn = fsig(zf) * cj + fsig(zi) * ftanh(zg);
            float hv = fsig(zo) * ftanh(cn);

            int rw = wm * 64 + mt * 16 + (lane >> 2) + (gp ? 8 : 0);
            hsm[rw * 33 + jl] = hv;
        }
    }
    __syncthreads();

#pragma unroll
    for (int i = 0; i < 8; i++) {
        int slot = tid + i * 256;
        int rw = slot >> 4, c2 = (slot & 15) * 2;
        __half2 hv = __floats2half2_rn(hsm[rw * 33 + c2], hsm[rw * 33 + c2 + 1]);
        *(__half2*)(g_hf + (size_t)(row0 + rw) * HDIM + j0 + c2) = hv;
    }
}

// ---------------------------------------------------------------------------
// heads_mma: logits = h @ Wa via HMMA; softmax; value SIMT over fp16 h.
// ---------------------------------------------------------------------------
#define H_STA 0
#define H_STB 4096
#define H_STRIDE 12288
#define H_NCH 32
#define H_SMEM (3 * H_STRIDE + 8192)
#define H_WV_OFF (3 * H_STRIDE)

__global__ __launch_bounds__(256, 2) void heads_mma(const float* __restrict__ Wv,
                                                    const float* __restrict__ ba,
                                                    const float* __restrict__ bv,
                                                    float* __restrict__ out) {
    extern __shared__ char smem[];
    uint32_t sb = smem_u32(smem);
    int tid  = threadIdx.x;
    int lane = tid & 31, w = tid >> 5;
    int wm = w & 1, wn = w >> 1;
    int row0 = blockIdx.x * 32;

    int lr = lane & 7, ls = lane >> 3;
    uint32_t a_row = wm * 16 + lr + (ls & 1) * 8;
    uint32_t a_chs = (uint32_t)(ls >> 1);
    uint32_t b_row = wn * 16 + lr;
    uint32_t b_chs = (uint32_t)(ls & 1);

    uint32_t pa0 = H_STA + (((a_row * 128) | ((a_row * 16) & 0x70)) ^ (a_chs << 4));
    uint32_t pb0 = H_STB + (((b_row * 128) | ((b_row * 16) & 0x70)) ^ (b_chs << 4));

    uint32_t sw0 = SWZ128((uint32_t)((tid >> 3) * 128 + (tid & 7) * 16));
    const __half* ph = g_hf + (size_t)(row0 + (tid >> 3)) * HDIM + (tid & 7) * 8;
    const __half* pa = g_wa + (size_t)(tid >> 3) * HDIM + (tid & 7) * 8;

    float acc[2][4];
#pragma unroll
    for (int nt = 0; nt < 2; nt++)
#pragma unroll
        for (int i = 0; i < 4; i++) acc[nt][i] = 0.0f;

#pragma unroll
    for (int st = 0; st < 2; st++) {
        uint32_t base = sb + st * H_STRIDE;
        cpa16(base + H_STA + sw0, ph + st * 64);
#pragma unroll
        for (int i = 0; i < 2; i++)
            cpa16(base + H_STB + sw0 + i * 4096, pa + (size_t)i * 32 * HDIM + st * 64);
        CPA_COMMIT();
    }

    for (int t = 0; t < H_NCH; t++) {
        if (t == H_NCH - 1) { CPA_WAIT(0); } else { CPA_WAIT(1); }
        __syncthreads();

        if (t + 2 < H_NCH) {
            uint32_t base = sb + ((t + 2) % 3) * H_STRIDE;
            int kg = (t + 2) * 64;
            cpa16(base + H_STA + sw0, ph + kg);
#pragma unroll
            for (int i = 0; i < 2; i++)
                cpa16(base + H_STB + sw0 + i * 4096, pa + (size_t)i * 32 * HDIM + kg);
            CPA_COMMIT();
        }

        uint32_t sa = sb + (t % 3) * H_STRIDE;
#pragma unroll
        for (int kb = 0; kb < 8; kb += 2) {
            uint32_t koff = (uint32_t)(kb << 4);
            uint32_t aa[4];
            ldmx4(aa, sa + (pa0 ^ koff));
#pragma unroll
            for (int nt = 0; nt < 2; nt++) {
                uint32_t bb[2];
                ldmx2(bb, sa + ((pb0 + nt * 1024) ^ koff));
                mma16816(acc[nt], aa, bb);
            }
        }
    }
    __syncthreads();

    float* lsm = (float*)smem;
    float* wvs = (float*)(smem + H_WV_OFF);
    {
        int r = wm * 16 + (lane >> 2);
#pragma unroll
        for (int nt = 0; nt < 2; nt++) {
            int c = wn * 16 + nt * 8 + (lane & 3) * 2;
            lsm[r * 65 + c]           = acc[nt][0];
            lsm[r * 65 + c + 1]       = acc[nt][1];
            lsm[(r + 8) * 65 + c]     = acc[nt][2];
            lsm[(r + 8) * 65 + c + 1] = acc[nt][3];
        }
    }
#pragma unroll
    for (int i = 0; i < 2; i++) {
        int e = tid + i * 256;
        *(float4*)&wvs[e * 4] = *(const float4*)&Wv[e * 4];
    }
    __syncthreads();

    int rowt = tid >> 3, ag = tid & 7;
    float l[8];
    float m = -INFINITY;
#pragma unroll
    for (int a = 0; a < 8; a++) {
        l[a] = lsm[rowt * 65 + ag * 8 + a] + __ldg(&ba[ag * 8 + a]);
        m = fmaxf(m, l[a]);
    }
#pragma unroll
    for (int off = 4; off > 0; off >>= 1)
        m = fmaxf(m, __shfl_xor_sync(0xFFFFFFFFu, m, off, 8));
    float sum = 0.0f;
#pragma unroll
    for (int a = 0; a < 8; a++) {
        l[a] = __expf(l[a] - m);
        sum += l[a];
    }
#pragma unroll
    for (int off = 4; off > 0; off >>= 1)
        sum += __shfl_xor_sync(0xFFFFFFFFu, sum, off, 8);
    float inv = __fdividef(1.0f, sum);
    int row = row0 + rowt;
#pragma unroll
    for (int a = 0; a < 8; a++)
        out[(size_t)row * 64 + ag * 8 + a] = l[a] * inv;

    float vacc = 0.0f;
    const __half* hrow = g_hf + (size_t)row * HDIM + ag * 256;
#pragma unroll 4
    for (int u = 0; u < 32; u++) {
        uint4 hv = *(const uint4*)(hrow + u * 8);
        __half2* h2 = (__half2*)&hv;
        int kb = ag * 256 + u * 8;
#pragma unroll
        for (int p = 0; p < 4; p++) {
            float2 f = __half22float2(h2[p]);
            vacc += f.x * wvs[kb + p * 2];
            vacc += f.y * wvs[kb + p * 2 + 1];
        }
    }
#pragma unroll
    for (int off = 4; off > 0; off >>= 1)
        vacc += __shfl_xor_sync(0xFFFFFFFFu, vacc, off, 8);
    if (ag == 0)
        out[(size_t)BATCH * 64 + row] = vacc + __ldg(&bv[0]);
}

// ---------------------------------------------------------------------------
extern "C" void kernel_launch(void* const* d_in, const int* in_sizes, int n_in,
                              void* d_out, int out_size) {
    const float* s      = (const float*)d_in[0];
    const float* a_prev = (const float*)d_in[1];
    const float* r_prev = (const float*)d_in[2];
    const float* h      = (const float*)d_in[3];
    const float* c      = (const float*)d_in[4];
    const float* Wx     = (const float*)d_in[5];
    const float* Wh     = (const float*)d_in[6];
    const float* bh     = (const float*)d_in[7];
    const float* Wa     = (const float*)d_in[8];
    const float* ba     = (const float*)d_in[9];
    const float* Wv     = (const float*)d_in[10];
    const float* bv     = (const float*)d_in[11];
    float* out = (float*)d_out;

    static bool attr_set = false;
    if (!attr_set) {
        cudaFuncSetAttribute(lstm_mma, cudaFuncAttributeMaxDynamicSharedMemorySize, SMEM_SZ);
        cudaFuncSetAttribute(heads_mma, cudaFuncAttributeMaxDynamicSharedMemorySize, H_SMEM);
        attr_set = true;
    }

    prep<<<PREP_BLOCKS, 256>>>(s, a_prev, h, Wh, Wx, Wa);
    lstm_mma<<<dim3(HDIM / 32, BATCH / 128), 256, SMEM_SZ>>>(
        c, r_prev, Wx + (size_t)(KDIM - 1) * FOURH, bh);
    heads_mma<<<BATCH / 32, 256, H_SMEM>>>(Wv, ba, bv, out);
}